// round 8
// baseline (speedup 1.0000x reference)
#include <cuda_runtime.h>
#include <cuda_fp16.h>
#include <math.h>
#include <stdint.h>

// Problem constants
#define G 256
#define N0 256
#define HF 256            // hidden feature dim
#define MAXN (G*N0)       // 65536
#define MAXE (G*2048)     // 524288
#define EPG 2048          // edges per graph (fixed slot count, masked edges have ew=0)

// -------- scratch (device globals; no allocation allowed) --------
__device__ float g_h[MAXN*HF];        // 64 MB : h = x @ W
__device__ float g_agg[MAXN*HF];      // 64 MB : conv output
__device__ float g_x[(MAXN/2)*HF];    // 32 MB : pooled features
__device__ float g_dinv[MAXN];
__device__ float g_score[MAXN];
__device__ float g_spart[4*MAXN];     // per-fc-chunk score partials
__device__ int   g_newid[MAXN];
__device__ int   g_perm[MAXN/2];
__device__ int   g_esrc0[MAXE], g_edst0[MAXE];
__device__ float g_eew0[MAXE];
__device__ int   g_esrc1[MAXE], g_edst1[MAXE];
__device__ float g_eew1[MAXE];
__device__ int   g_rs[MAXN];
__device__ int   g_rc[MAXN];
__device__ int2  g_cpack[MAXE];       // CSR packed (src, norm-bits), deterministic order
__device__ float g_ro[G*512];
__device__ float g_h1[G*256];
__device__ float g_h2[G*128];
// X split buffers (fp16 hi/lo)
__device__ __half g_xhi[8388608];
__device__ __half g_xlo[8388608];
// W split buffers (fp16 hi/lo, [256 (N)] x [K] K-major), K<=256
__device__ __half g_whi[256*256];
__device__ __half g_wlo[256*256];

// ================= helpers =================
__device__ __forceinline__ uint32_t smem_u32(const void* p) {
    uint32_t a;
    asm("{ .reg .u64 t; cvta.to.shared.u64 t, %1; cvt.u32.u64 %0, t; }"
        : "=r"(a) : "l"(p));
    return a;
}
__device__ __forceinline__ void ldsm_x4(uint32_t* r, uint32_t addr) {
    asm volatile("ldmatrix.sync.aligned.m8n8.x4.shared.b16 {%0,%1,%2,%3}, [%4];"
        : "=r"(r[0]), "=r"(r[1]), "=r"(r[2]), "=r"(r[3]) : "r"(addr));
}
__device__ __forceinline__ void ldsm_x2(uint32_t* r, uint32_t addr) {
    asm volatile("ldmatrix.sync.aligned.m8n8.x2.shared.b16 {%0,%1}, [%2];"
        : "=r"(r[0]), "=r"(r[1]) : "r"(addr));
}
__device__ __forceinline__ void mma_f16(float* d, const uint32_t* a, const uint32_t* b) {
    asm volatile("mma.sync.aligned.m16n8k16.row.col.f32.f16.f16.f32 "
        "{%0,%1,%2,%3}, {%4,%5,%6,%7}, {%8,%9}, {%0,%1,%2,%3};"
        : "+f"(d[0]), "+f"(d[1]), "+f"(d[2]), "+f"(d[3])
        : "r"(a[0]), "r"(a[1]), "r"(a[2]), "r"(a[3]), "r"(b[0]), "r"(b[1]));
}

// ================= split pre-passes (fp16 2-way) =================
__global__ void xsplit_kernel(const float* __restrict__ X, int total,
                              __half* __restrict__ xhi, __half* __restrict__ xlo) {
    int i = blockIdx.x * 256 + threadIdx.x;
    if (i >= total) return;
    float v = X[i];
    __half h = __float2half_rn(v);
    __half l = __float2half_rn(v - __half2float(h));
    xhi[i] = h; xlo[i] = l;
}

__global__ void wsplit_kernel(const float* __restrict__ W, int K,
                              __half* __restrict__ whi, __half* __restrict__ wlo) {
    int idx = blockIdx.x * 256 + threadIdx.x;
    if (idx >= K * 256) return;
    int k = idx >> 8, n = idx & 255;
    float w = W[idx];
    __half h = __float2half_rn(w);
    __half l = __float2half_rn(w - __half2float(h));
    whi[n*K + k] = h; wlo[n*K + k] = l;
}

// ================= MMA GEMM: C[n,256] = X[n,K] @ W[K,256] =================
// near-fp32 via fp16 2-way split, 3 product segments (hh, hl, lh; ll dropped ~2^-22).
#define SEGB 6144
#define MMA_SMEM (4*SEGB)

__global__ __launch_bounds__(256) void gemm_mma_kernel(
        const __half* __restrict__ Xhi, const __half* __restrict__ Xlo,
        const __half* __restrict__ Whi, const __half* __restrict__ Wlo,
        float* __restrict__ C, int K) {
    extern __shared__ __align__(16) char smem[];
    char* smA = smem;                  // 2 segs
    char* smB = smem + 2*SEGB;         // 2 segs
    uint32_t sb = smem_u32(smem);
    int tid = threadIdx.x, w = tid >> 5, lane = tid & 31;
    int rowBase = blockIdx.x * 128, colBase = blockIdx.y * 128;
    int warpRow = (w >> 2) * 64, warpCol = (w & 3) * 32;

    float acc[4][4][4];
    #pragma unroll
    for (int i = 0; i < 4; i++)
        #pragma unroll
        for (int j = 0; j < 4; j++)
            #pragma unroll
            for (int d = 0; d < 4; d++) acc[i][j][d] = 0.f;

    int r  = tid >> 1;
    int hf = tid & 1;
    uint32_t stOff = (uint32_t)(r * 48 + hf * 16);

    int bl = lane & 15;
    uint32_t aFragBase = sb + (uint32_t)((warpRow + (lane & 15)) * 48 + (lane >> 4) * 16);
    uint32_t bFragBase = sb + 2*SEGB
                       + (uint32_t)((warpCol + (bl & 7)) * 48 + (bl >> 3) * 16);

    const int NC = K >> 4;
    for (int kb = 0; kb < NC; kb++) {
        {
            size_t goff = (size_t)(rowBase + r) * K + kb * 16 + hf * 8;
            *(uint4*)(smA        + stOff) = *(const uint4*)(Xhi + goff);
            *(uint4*)(smA + SEGB + stOff) = *(const uint4*)(Xlo + goff);
        }
        {
            size_t goff = (size_t)(colBase + r) * K + kb * 16 + hf * 8;
            *(uint4*)(smB        + stOff) = *(const uint4*)(Whi + goff);
            *(uint4*)(smB + SEGB + stOff) = *(const uint4*)(Wlo + goff);
        }
        __syncthreads();

        uint32_t bfr[2][4][2];
        #pragma unroll
        for (int s = 0; s < 2; s++)
            #pragma unroll
            for (int nt = 0; nt < 4; nt++)
                ldsm_x2(bfr[s][nt], bFragBase + s*SEGB + nt*(8*48));

        #pragma unroll
        for (int mt = 0; mt < 4; mt++) {
            uint32_t afr[2][4];
            #pragma unroll
            for (int s = 0; s < 2; s++)
                ldsm_x4(afr[s], aFragBase + s*SEGB + mt*(16*48));
            #pragma unroll
            for (int cb = 0; cb < 3; cb++) {        // hh, hl, lh
                int ai = (cb == 2) ? 1 : 0;
                int bi = (cb == 1) ? 1 : 0;
                #pragma unroll
                for (int nt = 0; nt < 4; nt++)
                    mma_f16(acc[mt][nt], afr[ai], bfr[bi][nt]);
            }
        }
        __syncthreads();
    }

    #pragma unroll
    for (int mt = 0; mt < 4; mt++) {
        int row = rowBase + warpRow + mt*16 + (lane >> 2);
        #pragma unroll
        for (int nt = 0; nt < 4; nt++) {
            int col = colBase + warpCol + nt*8 + (lane & 3)*2;
            *(float2*)&C[(size_t)row * 256 + col] =
                make_float2(acc[mt][nt][0], acc[mt][nt][1]);
            *(float2*)&C[(size_t)(row + 8) * 256 + col] =
                make_float2(acc[mt][nt][2], acc[mt][nt][3]);
        }
    }
}

// ---------------- per-graph CSR build, deterministic row order ----------------
// deg sums are exact integers (w in {0,1}) -> order-free; rows filled in edge order.
__global__ __launch_bounds__(256) void csr_build_kernel(
        const int* __restrict__ src, const int* __restrict__ dst,
        const float* __restrict__ ew, int npg,
        int* __restrict__ rs, int* __restrict__ rc,
        int2* __restrict__ cpack, float* __restrict__ dinv) {
    __shared__ float sdeg[256];
    __shared__ int   scnt[256];
    __shared__ int   sscan[256];
    __shared__ int   ssrc[EPG];
    __shared__ int   sdst[EPG];
    int g = blockIdx.x, t = threadIdx.x;
    int nbase = g * npg, ebase = g * EPG;

    if (t < npg) { sdeg[t] = 1.0f; scnt[t] = 0; }
    __syncthreads();
    for (int e = t; e < EPG; e += 256) {
        float w = ew ? ew[ebase + e] : 1.0f;
        int s = src[ebase + e] - nbase;
        int d = dst[ebase + e] - nbase;
        ssrc[e] = s;
        sdst[e] = (w != 0.f) ? d : -1;
        if (w != 0.f) {
            atomicAdd(&sdeg[d], w);    // integer-valued: exact, order-free
            atomicAdd(&scnt[d], 1);
        }
    }
    __syncthreads();
    int v = (t < npg) ? scnt[t] : 0;
    sscan[t] = v;
    __syncthreads();
    #pragma unroll
    for (int off = 1; off < 256; off <<= 1) {
        int add = (t >= off) ? sscan[t - off] : 0;
        __syncthreads();
        sscan[t] += add;
        __syncthreads();
    }
    int start = sscan[t] - v;
    if (t < npg) {
        rs[nbase + t] = start;
        rc[nbase + t] = v;
        dinv[nbase + t] = 1.0f / sdeg[t];
        // deterministic scatter: scan edges in order, pick my row's edges
        float rdt = rsqrtf(sdeg[t]);
        int pos = start, end = start + v;
        for (int e = 0; e < EPG && pos < end; e++) {
            if (sdst[e] == t) {
                int s = ssrc[e];
                float nm = rsqrtf(sdeg[s]) * rdt;   // valid edges have w == 1
                cpack[ebase + pos++] = make_int2(s, __float_as_int(nm));
            }
        }
    }
}

// ---------------- fused aggregation + self-loop + bias + relu + score partial --
// block = (fc in [0,4), graph g); stages h tile [npg][64] floats; 2 dsts per warp
__global__ __launch_bounds__(256) void agg_fused_kernel(
        const float* __restrict__ h, const float* __restrict__ dinv,
        const int* __restrict__ rs, const int* __restrict__ rc,
        const int2* __restrict__ cpack, const float* __restrict__ bias,
        const float* __restrict__ pw, float* __restrict__ out,
        float* __restrict__ spart, int npg) {
    extern __shared__ float ht[];   // npg * 64 floats
    int fc = blockIdx.x, g = blockIdx.y;
    int t = threadIdx.x;
    int nbase = g * npg, ebase = g * EPG;

    const float4* h4 = (const float4*)h;
    float4* ht4 = (float4*)ht;
    for (int i = t; i < npg * 16; i += 256) {
        int node = i >> 4, q = i & 15;
        ht4[i] = h4[(size_t)(nbase + node) * 64 + fc * 16 + q];
    }
    __syncthreads();

    int w = t >> 5, lane = t & 31;
    float b0  = __ldg(bias + fc*64 + lane*2);
    float b1  = __ldg(bias + fc*64 + lane*2 + 1);
    float pw0 = __ldg(pw + fc*64 + lane*2);
    float pw1 = __ldg(pw + fc*64 + lane*2 + 1);
    const float2* ht2 = (const float2*)ht;

    for (int d0 = w * 2; d0 < npg; d0 += 16) {
        int d1 = d0 + 1;
        float2 v0 = ht2[d0*32 + lane];
        float2 v1 = ht2[d1*32 + lane];
        float dv0 = dinv[nbase + d0], dv1 = dinv[nbase + d1];
        float a00 = v0.x * dv0 + b0, a01 = v0.y * dv0 + b1;
        float a10 = v1.x * dv1 + b0, a11 = v1.y * dv1 + b1;
        int c0 = rc[nbase + d0], c1 = rc[nbase + d1];
        const int2* cp0 = cpack + ebase + rs[nbase + d0];
        const int2* cp1 = cpack + ebase + rs[nbase + d1];
        int e0 = 0, e1 = 0;
        while (e0 + 2 <= c0 && e1 + 2 <= c1) {
            int2 pa = __ldg(cp0 + e0), pb = __ldg(cp0 + e0 + 1);
            int2 pc = __ldg(cp1 + e1), pd = __ldg(cp1 + e1 + 1);
            float2 xa = ht2[pa.x*32 + lane]; float na = __int_as_float(pa.y);
            float2 xb = ht2[pb.x*32 + lane]; float nb = __int_as_float(pb.y);
            float2 xc = ht2[pc.x*32 + lane]; float nc = __int_as_float(pc.y);
            float2 xd = ht2[pd.x*32 + lane]; float nd = __int_as_float(pd.y);
            a00 += na * xa.x; a01 += na * xa.y;
            a00 += nb * xb.x; a01 += nb * xb.y;
            a10 += nc * xc.x; a11 += nc * xc.y;
            a10 += nd * xd.x; a11 += nd * xd.y;
            e0 += 2; e1 += 2;
        }
        for (; e0 < c0; e0++) {
            int2 p = __ldg(cp0 + e0);
            float2 x = ht2[p.x*32 + lane]; float nm = __int_as_float(p.y);
            a00 += nm * x.x; a01 += nm * x.y;
        }
        for (; e1 < c1; e1++) {
            int2 p = __ldg(cp1 + e1);
            float2 x = ht2[p.x*32 + lane]; float nm = __int_as_float(p.y);
            a10 += nm * x.x; a11 += nm * x.y;
        }
        float2 o0 = make_float2(fmaxf(a00, 0.f), fmaxf(a01, 0.f));
        float2 o1 = make_float2(fmaxf(a10, 0.f), fmaxf(a11, 0.f));
        *(float2*)(out + (size_t)(nbase + d0) * 256 + fc*64 + lane*2) = o0;
        *(float2*)(out + (size_t)(nbase + d1) * 256 + fc*64 + lane*2) = o1;
        // score partials (deterministic shfl order)
        float sp0 = o0.x * pw0 + o0.y * pw1;
        float sp1 = o1.x * pw0 + o1.y * pw1;
        #pragma unroll
        for (int off = 16; off > 0; off >>= 1) {
            sp0 += __shfl_down_sync(0xFFFFFFFFu, sp0, off);
            sp1 += __shfl_down_sync(0xFFFFFFFFu, sp1, off);
        }
        if (lane == 0) {
            spart[fc * MAXN + nbase + d0] = sp0;
            spart[fc * MAXN + nbase + d1] = sp1;
        }
    }
}

// ---------------- pool: sum partials, tanh, ||w|| inline, rank-count top-k -----
__global__ void pool_kernel(const float* __restrict__ spart,
                            const float* __restrict__ pw,
                            float* __restrict__ score, int npg, int k,
                            int* __restrict__ newid, int* __restrict__ perm) {
    __shared__ float s[256];
    __shared__ float red[256];
    int g = blockIdx.x, t = threadIdx.x;
    float ss = 0.f;
    for (int i = t; i < 256; i += npg) { float v = pw[i]; ss += v * v; }
    red[t] = ss;
    __syncthreads();
    for (int st = npg >> 1; st > 0; st >>= 1) {
        if (t < st) red[t] += red[t + st];
        __syncthreads();
    }
    float winv = rsqrtf(red[0]);

    int node = g * npg + t;
    float acc = 0.f;
    #pragma unroll
    for (int c = 0; c < 4; c++) acc += spart[c * MAXN + node];
    float my = tanhf(acc * winv);
    score[node] = my;
    s[t] = my;
    __syncthreads();
    int rank = 0;
    for (int j = 0; j < npg; j++) {
        float v = s[j];
        rank += (v > my) || (v == my && j < t);
    }
    if (rank < k) {
        newid[node] = g * k + rank;
        perm[g * k + rank] = node;
    } else {
        newid[node] = -1;
    }
}

// ---------------- gather*score (+ optional fp16 split for next GEMM) -----------
__global__ void gather_split_kernel(const float* __restrict__ x,
                                    const float* __restrict__ score,
                                    const int* __restrict__ perm,
                                    float* __restrict__ nx,
                                    __half* __restrict__ xhi,
                                    __half* __restrict__ xlo, int nNew) {
    int i = blockIdx.x * blockDim.x + threadIdx.x;
    if (i >= nNew * HF) return;
    int nn = i >> 8, f = i & 255;
    int old = perm[nn];
    float v = x[(size_t)old * HF + f] * score[old];
    nx[i] = v;
    __half h = __float2half_rn(v);
    xhi[i] = h;
    xlo[i] = __float2half_rn(v - __half2float(h));
}

__global__ void gather_scale_kernel(const float* __restrict__ x,
                                    const float* __restrict__ score,
                                    const int* __restrict__ perm,
                                    float* __restrict__ nx, int nNew) {
    int i = blockIdx.x * blockDim.x + threadIdx.x;
    if (i >= nNew * HF) return;
    int nn = i >> 8, f = i & 255;
    int old = perm[nn];
    nx[i] = x[(size_t)old * HF + f] * score[old];
}

__global__ void remap_kernel(const int* __restrict__ src, const int* __restrict__ dst,
                             const float* __restrict__ ew, const int* __restrict__ newid,
                             int* __restrict__ nsrc, int* __restrict__ ndst,
                             float* __restrict__ new_ew, int E) {
    int e = blockIdx.x * blockDim.x + threadIdx.x;
    if (e >= E) return;
    int s = newid[src[e]], d = newid[dst[e]];
    float w = ew ? ew[e] : 1.0f;
    bool valid = (s >= 0) && (d >= 0);
    nsrc[e]   = valid ? s : 0;
    ndst[e]   = valid ? d : 0;
    new_ew[e] = valid ? w : 0.f;
}

// ---------------- readout: [max | mean] per graph ----------------
__global__ void readout_kernel(const float* __restrict__ x, int k,
                               float* __restrict__ ro, int accumulate) {
    int g = blockIdx.x, f = threadIdx.x;
    const float* base = x + (size_t)g * k * HF + f;
    float mx = -3.4e38f, sum = 0.f;
    for (int j = 0; j < k; j++) {
        float v = base[(size_t)j * HF];
        mx = fmaxf(mx, v);
        sum += v;
    }
    float mean = sum / (float)k;
    if (accumulate) {
        ro[g*512 + f]       += mx;
        ro[g*512 + 256 + f] += mean;
    } else {
        ro[g*512 + f]       = mx;
        ro[g*512 + 256 + f] = mean;
    }
}

// ---------------- MLP (multi-graph blocks to amortize weight reads) ------------
__global__ __launch_bounds__(256) void lin1_kernel(const float* __restrict__ in,
        const float* __restrict__ W, const float* __restrict__ b,
        float* __restrict__ out) {
    int gb = blockIdx.x * 8, c = threadIdx.x;
    __shared__ float rows[8 * 512];
    for (int i = c; i < 8 * 512; i += 256) rows[i] = in[gb * 512 + i];
    __syncthreads();
    float acc[8];
    float bc = b[c];
    #pragma unroll
    for (int gg = 0; gg < 8; gg++) acc[gg] = bc;
    for (int kk = 0; kk < 512; kk++) {
        float wv = W[kk * 256 + c];
        #pragma unroll
        for (int gg = 0; gg < 8; gg++) acc[gg] += rows[gg * 512 + kk] * wv;
    }
    #pragma unroll
    for (int gg = 0; gg < 8; gg++)
        out[(gb + gg) * 256 + c] = fmaxf(acc[gg], 0.f);
}
__global__ __launch_bounds__(128) void lin2_kernel(const float* __restrict__ in,
        const float* __restrict__ W, const float* __restrict__ b,
        float* __restrict__ out) {
    int gb = blockIdx.x * 16, c = threadIdx.x;
    __shared__ float rows[16 * 256];
    for (int i = c; i < 16 * 256; i += 128) rows[i] = in[gb * 256 + i];
    __syncthreads();
    float acc[16];
    float bc = b[c];
    #pragma unroll
    for (int gg = 0; gg < 16; gg++) acc[gg] = bc;
    for (int kk = 0; kk < 256; kk++) {
        float wv = W[kk * 128 + c];
        #pragma unroll
        for (int gg = 0; gg < 16; gg++) acc[gg] += rows[gg * 256 + kk] * wv;
    }
    #pragma unroll
    for (int gg = 0; gg < 16; gg++)
        out[(gb + gg) * 128 + c] = fmaxf(acc[gg], 0.f);
}
__global__ void lin3_lsm_kernel(const float* __restrict__ in, const float* __restrict__ W,
                                const float* __restrict__ b, float* __restrict__ out) {
    int g = blockIdx.x, lane = threadIdx.x;
    const float* row = in + g*128;
    float a0 = 0.f, a1 = 0.f;
    #pragma unroll
    for (int kk = lane; kk < 128; kk += 32) {
        float v = row[kk];
        a0 += v * W[kk*2 + 0];
        a1 += v * W[kk*2 + 1];
    }
    #pragma unroll
    for (int o = 16; o > 0; o >>= 1) {
        a0 += __shfl_down_sync(0xFFFFFFFFu, a0, o);
        a1 += __shfl_down_sync(0xFFFFFFFFu, a1, o);
    }
    if (lane == 0) {
        float l0 = a0 + b[0], l1 = a1 + b[1];
        float m = fmaxf(l0, l1);
        float lse = m + logf(expf(l0 - m) + expf(l1 - m));
        out[g*2 + 0] = l0 - lse;
        out[g*2 + 1] = l1 - lse;
    }
}

// ---------------- host driver ----------------
extern "C" void kernel_launch(void* const* d_in, const int* in_sizes, int n_in,
                              void* d_out, int out_size) {
    const float* d_x      = (const float*)d_in[0];
    const int*   d_ei     = (const int*)d_in[1];
    const float* gcn_w0   = (const float*)d_in[3];
    const float* gcn_b0   = (const float*)d_in[4];
    const float* gcn_w1   = (const float*)d_in[5];
    const float* gcn_b1   = (const float*)d_in[6];
    const float* gcn_w2   = (const float*)d_in[7];
    const float* gcn_b2   = (const float*)d_in[8];
    const float* pool_w0  = (const float*)d_in[9];
    const float* pool_w1  = (const float*)d_in[10];
    const float* pool_w2  = (const float*)d_in[11];
    const float* lin1_w   = (const float*)d_in[12];
    const float* lin1_b   = (const float*)d_in[13];
    const float* lin2_w   = (const float*)d_in[14];
    const float* lin2_b   = (const float*)d_in[15];
    const float* lin3_w   = (const float*)d_in[16];
    const float* lin3_b   = (const float*)d_in[17];
    float* out = (float*)d_out;

    const int E = in_sizes[1] / 2;
    const int* d_src = d_ei;
    const int* d_dst = d_ei + E;

    float *p_h, *p_agg, *p_x, *p_dinv, *p_score, *p_spart, *p_ro, *p_h1, *p_h2;
    int *p_newid, *p_perm, *p_es0, *p_ed0, *p_es1, *p_ed1, *p_rs, *p_rc;
    int2 *p_cpack;
    float *p_ew0, *p_ew1;
    __half *p_xhi, *p_xlo, *p_whi, *p_wlo;
    cudaGetSymbolAddress((void**)&p_h,    g_h);
    cudaGetSymbolAddress((void**)&p_agg,  g_agg);
    cudaGetSymbolAddress((void**)&p_x,    g_x);
    cudaGetSymbolAddress((void**)&p_dinv, g_dinv);
    cudaGetSymbolAddress((void**)&p_score,g_score);
    cudaGetSymbolAddress((void**)&p_spart,g_spart);
    cudaGetSymbolAddress((void**)&p_newid,g_newid);
    cudaGetSymbolAddress((void**)&p_perm, g_perm);
    cudaGetSymbolAddress((void**)&p_es0,  g_esrc0);
    cudaGetSymbolAddress((void**)&p_ed0,  g_edst0);
    cudaGetSymbolAddress((void**)&p_ew0,  g_eew0);
    cudaGetSymbolAddress((void**)&p_es1,  g_esrc1);
    cudaGetSymbolAddress((void**)&p_ed1,  g_edst1);
    cudaGetSymbolAddress((void**)&p_ew1,  g_eew1);
    cudaGetSymbolAddress((void**)&p_rs,   g_rs);
    cudaGetSymbolAddress((void**)&p_rc,   g_rc);
    cudaGetSymbolAddress((void**)&p_cpack,g_cpack);
    cudaGetSymbolAddress((void**)&p_ro,   g_ro);
    cudaGetSymbolAddress((void**)&p_h1,   g_h1);
    cudaGetSymbolAddress((void**)&p_h2,   g_h2);
    cudaGetSymbolAddress((void**)&p_xhi,  g_xhi);
    cudaGetSymbolAddress((void**)&p_xlo,  g_xlo);
    cudaGetSymbolAddress((void**)&p_whi,  g_whi);
    cudaGetSymbolAddress((void**)&p_wlo,  g_wlo);

    cudaFuncSetAttribute(agg_fused_kernel,
                         cudaFuncAttributeMaxDynamicSharedMemorySize, 65536);

    // ---------------- level 0 ----------------
    int n = MAXN;
    {
        int npg = 256;
        wsplit_kernel<<<128, 256>>>(gcn_w0, 128, p_whi, p_wlo);
        xsplit_kernel<<<(n * 128 + 255) / 256, 256>>>(d_x, n * 128, p_xhi, p_xlo);
        gemm_mma_kernel<<<dim3(n / 128, 2), 256, MMA_SMEM>>>(p_xhi, p_xlo, p_whi, p_wlo, p_h, 128);
        csr_build_kernel<<<G, 256>>>(d_src, d_dst, nullptr, npg, p_rs, p_rc, p_cpack, p_dinv);
        agg_fused_kernel<<<dim3(4, G), 256, npg*64*4>>>(p_h, p_dinv, p_rs, p_rc,
                                                        p_cpack, gcn_b0, pool_w0,
                                                        p_agg, p_spart, npg);
    }
    {
        int npg = 256, k = 128, nNew = G * k;
        pool_kernel<<<G, npg>>>(p_spart, pool_w0, p_score, npg, k, p_newid, p_perm);
        gather_split_kernel<<<(nNew * HF + 255) / 256, 256>>>(p_agg, p_score, p_perm,
                                                              p_x, p_xhi, p_xlo, nNew);
        remap_kernel<<<(E + 255) / 256, 256>>>(d_src, d_dst, nullptr, p_newid,
                                               p_es0, p_ed0, p_ew0, E);
        readout_kernel<<<G, 256>>>(p_x, k, p_ro, 0);
        n = nNew;                 // 32768
    }
    // ---------------- level 1 ----------------
    {
        int npg = 128;
        wsplit_kernel<<<256, 256>>>(gcn_w1, 256, p_whi, p_wlo);
        gemm_mma_kernel<<<dim3(n / 128, 2), 256, MMA_SMEM>>>(p_xhi, p_xlo, p_whi, p_wlo, p_h, 256);
        csr_build_kernel<<<G, 256>>>(p_es0, p_ed0, p_ew0, npg, p_rs, p_rc, p_cpack, p_dinv);
        agg_fused_kernel<<<dim3(4, G), 256, npg*64*4>>>(p_h, p_dinv, p_rs, p_rc,
                                                        p_cpack, gcn_b1, pool_w1,
                                                        p_agg, p_spart, npg);
    }
    {
        int npg = 128, k = 64, nNew = G * k;
        pool_kernel<<<G, npg>>>(p_spart, pool_w1, p_score, npg, k, p_newid, p_perm);
        gather_split_kernel<<<(nNew * HF + 255) / 256, 256>>>(p_agg, p_score, p_perm,
                                                              p_x, p_xhi, p_xlo, nNew);
        remap_kernel<<<(E + 255) / 256, 256>>>(p_es0, p_ed0, p_ew0, p_newid,
                                               p_es1, p_ed1, p_ew1, E);
        readout_kernel<<<G, 256>>>(p_x, k, p_ro, 1);
        n = nNew;                 // 16384
    }
    // ---------------- level 2 ----------------
    {
        int npg = 64;
        wsplit_kernel<<<256, 256>>>(gcn_w2, 256, p_whi, p_wlo);
        gemm_mma_kernel<<<dim3(n / 128, 2), 256, MMA_SMEM>>>(p_xhi, p_xlo, p_whi, p_wlo, p_h, 256);
        csr_build_kernel<<<G, 256>>>(p_es1, p_ed1, p_ew1, npg, p_rs, p_rc, p_cpack, p_dinv);
        agg_fused_kernel<<<dim3(4, G), 256, npg*64*4>>>(p_h, p_dinv, p_rs, p_rc,
                                                        p_cpack, gcn_b2, pool_w2,
                                                        p_agg, p_spart, npg);
    }
    {
        int npg = 64, k = 32;
        pool_kernel<<<G, npg>>>(p_spart, pool_w2, p_score, npg, k, p_newid, p_perm);
        gather_scale_kernel<<<(G * k * HF + 255) / 256, 256>>>(p_agg, p_score, p_perm, p_x, G * k);
        readout_kernel<<<G, 256>>>(p_x, k, p_ro, 1);
    }

    // ---------------- MLP head ----------------
    lin1_kernel<<<32, 256>>>(p_ro, lin1_w, lin1_b, p_h1);
    lin2_kernel<<<16, 128>>>(p_h1, lin2_w, lin2_b, p_h2);
    lin3_lsm_kernel<<<G, 32>>>(p_h2, lin3_w, lin3_b, out);
}

// round 9
// speedup vs baseline: 1.6000x; 1.6000x over previous
#include <cuda_runtime.h>
#include <cuda_fp16.h>
#include <math.h>
#include <stdint.h>

// Problem constants
#define G 256
#define N0 256
#define HF 256            // hidden feature dim
#define MAXN (G*N0)       // 65536
#define MAXE (G*2048)     // 524288
#define EPG 2048          // edges per graph (fixed slot count, masked edges have ew=0)

// -------- scratch (device globals; no allocation allowed) --------
__device__ float g_h[MAXN*HF];        // 64 MB : h = x @ W
__device__ float g_agg[MAXN*HF];      // 64 MB : conv output
__device__ float g_x[(MAXN/2)*HF];    // 32 MB : pooled features
__device__ float g_dinv[MAXN];
__device__ float g_score[MAXN];
__device__ float g_spart[4*MAXN];     // per-fc-chunk score partials
__device__ int   g_newid[MAXN];
__device__ int   g_perm[MAXN/2];
__device__ int   g_esrc0[MAXE], g_edst0[MAXE];
__device__ float g_eew0[MAXE];
__device__ int   g_esrc1[MAXE], g_edst1[MAXE];
__device__ float g_eew1[MAXE];
__device__ int   g_rs[MAXN];
__device__ int   g_rc[MAXN];
__device__ int2  g_cpack[MAXE];       // CSR packed (src, norm-bits)
__device__ float g_ro[G*512];
__device__ float g_h1[G*256];
__device__ float g_h2[G*128];
// X split buffers (fp16 hi/lo)
__device__ __half g_xhi[8388608];
__device__ __half g_xlo[8388608];
// W split buffers (fp16 hi/lo, [256 (N)] x [K] K-major), K<=256
__device__ __half g_whi[256*256];
__device__ __half g_wlo[256*256];

// ================= helpers =================
__device__ __forceinline__ uint32_t smem_u32(const void* p) {
    uint32_t a;
    asm("{ .reg .u64 t; cvta.to.shared.u64 t, %1; cvt.u32.u64 %0, t; }"
        : "=r"(a) : "l"(p));
    return a;
}
__device__ __forceinline__ void ldsm_x4(uint32_t* r, uint32_t addr) {
    asm volatile("ldmatrix.sync.aligned.m8n8.x4.shared.b16 {%0,%1,%2,%3}, [%4];"
        : "=r"(r[0]), "=r"(r[1]), "=r"(r[2]), "=r"(r[3]) : "r"(addr));
}
__device__ __forceinline__ void ldsm_x2(uint32_t* r, uint32_t addr) {
    asm volatile("ldmatrix.sync.aligned.m8n8.x2.shared.b16 {%0,%1}, [%2];"
        : "=r"(r[0]), "=r"(r[1]) : "r"(addr));
}
__device__ __forceinline__ void mma_f16(float* d, const uint32_t* a, const uint32_t* b) {
    asm volatile("mma.sync.aligned.m16n8k16.row.col.f32.f16.f16.f32 "
        "{%0,%1,%2,%3}, {%4,%5,%6,%7}, {%8,%9}, {%0,%1,%2,%3};"
        : "+f"(d[0]), "+f"(d[1]), "+f"(d[2]), "+f"(d[3])
        : "r"(a[0]), "r"(a[1]), "r"(a[2]), "r"(a[3]), "r"(b[0]), "r"(b[1]));
}

// ================= split pre-passes (fp16 2-way) =================
__global__ void xsplit_kernel(const float* __restrict__ X, int total,
                              __half* __restrict__ xhi, __half* __restrict__ xlo) {
    int i = blockIdx.x * 256 + threadIdx.x;
    if (i >= total) return;
    float v = X[i];
    __half h = __float2half_rn(v);
    __half l = __float2half_rn(v - __half2float(h));
    xhi[i] = h; xlo[i] = l;
}

__global__ void wsplit_kernel(const float* __restrict__ W, int K,
                              __half* __restrict__ whi, __half* __restrict__ wlo) {
    int idx = blockIdx.x * 256 + threadIdx.x;
    if (idx >= K * 256) return;
    int k = idx >> 8, n = idx & 255;
    float w = W[idx];
    __half h = __float2half_rn(w);
    __half l = __float2half_rn(w - __half2float(h));
    whi[n*K + k] = h; wlo[n*K + k] = l;
}

// ================= MMA GEMM: C[n,256] = X[n,K] @ W[K,256] =================
// near-fp32 via fp16 2-way split, 3 product segments (hh, hl, lh; ll dropped ~2^-22).
#define SEGB 6144
#define MMA_SMEM (4*SEGB)

__global__ __launch_bounds__(256) void gemm_mma_kernel(
        const __half* __restrict__ Xhi, const __half* __restrict__ Xlo,
        const __half* __restrict__ Whi, const __half* __restrict__ Wlo,
        float* __restrict__ C, int K) {
    extern __shared__ __align__(16) char smem[];
    char* smA = smem;                  // 2 segs
    char* smB = smem + 2*SEGB;         // 2 segs
    uint32_t sb = smem_u32(smem);
    int tid = threadIdx.x, w = tid >> 5, lane = tid & 31;
    int rowBase = blockIdx.x * 128, colBase = blockIdx.y * 128;
    int warpRow = (w >> 2) * 64, warpCol = (w & 3) * 32;

    float acc[4][4][4];
    #pragma unroll
    for (int i = 0; i < 4; i++)
        #pragma unroll
        for (int j = 0; j < 4; j++)
            #pragma unroll
            for (int d = 0; d < 4; d++) acc[i][j][d] = 0.f;

    int r  = tid >> 1;
    int hf = tid & 1;
    uint32_t stOff = (uint32_t)(r * 48 + hf * 16);

    int bl = lane & 15;
    uint32_t aFragBase = sb + (uint32_t)((warpRow + (lane & 15)) * 48 + (lane >> 4) * 16);
    uint32_t bFragBase = sb + 2*SEGB
                       + (uint32_t)((warpCol + (bl & 7)) * 48 + (bl >> 3) * 16);

    const int NC = K >> 4;
    for (int kb = 0; kb < NC; kb++) {
        {
            size_t goff = (size_t)(rowBase + r) * K + kb * 16 + hf * 8;
            *(uint4*)(smA        + stOff) = *(const uint4*)(Xhi + goff);
            *(uint4*)(smA + SEGB + stOff) = *(const uint4*)(Xlo + goff);
        }
        {
            size_t goff = (size_t)(colBase + r) * K + kb * 16 + hf * 8;
            *(uint4*)(smB        + stOff) = *(const uint4*)(Whi + goff);
            *(uint4*)(smB + SEGB + stOff) = *(const uint4*)(Wlo + goff);
        }
        __syncthreads();

        uint32_t bfr[2][4][2];
        #pragma unroll
        for (int s = 0; s < 2; s++)
            #pragma unroll
            for (int nt = 0; nt < 4; nt++)
                ldsm_x2(bfr[s][nt], bFragBase + s*SEGB + nt*(8*48));

        #pragma unroll
        for (int mt = 0; mt < 4; mt++) {
            uint32_t afr[2][4];
            #pragma unroll
            for (int s = 0; s < 2; s++)
                ldsm_x4(afr[s], aFragBase + s*SEGB + mt*(16*48));
            #pragma unroll
            for (int cb = 0; cb < 3; cb++) {        // hh, hl, lh
                int ai = (cb == 2) ? 1 : 0;
                int bi = (cb == 1) ? 1 : 0;
                #pragma unroll
                for (int nt = 0; nt < 4; nt++)
                    mma_f16(acc[mt][nt], afr[ai], bfr[bi][nt]);
            }
        }
        __syncthreads();
    }

    #pragma unroll
    for (int mt = 0; mt < 4; mt++) {
        int row = rowBase + warpRow + mt*16 + (lane >> 2);
        #pragma unroll
        for (int nt = 0; nt < 4; nt++) {
            int col = colBase + warpCol + nt*8 + (lane & 3)*2;
            *(float2*)&C[(size_t)row * 256 + col] =
                make_float2(acc[mt][nt][0], acc[mt][nt][1]);
            *(float2*)&C[(size_t)(row + 8) * 256 + col] =
                make_float2(acc[mt][nt][2], acc[mt][nt][3]);
        }
    }
}

// ---------------- per-graph CSR build (atomic scatter, 13.7us measured) --------
__global__ __launch_bounds__(256) void csr_build_kernel(
        const int* __restrict__ src, const int* __restrict__ dst,
        const float* __restrict__ ew, int npg,
        int* __restrict__ rs, int* __restrict__ rc,
        int2* __restrict__ cpack, float* __restrict__ dinv) {
    __shared__ float sdeg[256];
    __shared__ int   scnt[256];
    __shared__ int   sscan[256];
    __shared__ int   spos[256];
    int g = blockIdx.x, t = threadIdx.x;
    int nbase = g * npg, ebase = g * EPG;

    if (t < npg) { sdeg[t] = 1.0f; scnt[t] = 0; }
    __syncthreads();
    for (int e = t; e < EPG; e += 256) {
        float w = ew ? ew[ebase + e] : 1.0f;
        if (w != 0.f) {
            int d = dst[ebase + e] - nbase;
            atomicAdd(&sdeg[d], w);
            atomicAdd(&scnt[d], 1);
        }
    }
    __syncthreads();
    int v = (t < npg) ? scnt[t] : 0;
    sscan[t] = v;
    __syncthreads();
    #pragma unroll
    for (int off = 1; off < 256; off <<= 1) {
        int add = (t >= off) ? sscan[t - off] : 0;
        __syncthreads();
        sscan[t] += add;
        __syncthreads();
    }
    int start = sscan[t] - v;
    if (t < npg) {
        rs[nbase + t] = start;
        rc[nbase + t] = v;
        spos[t] = start;
        dinv[nbase + t] = 1.0f / sdeg[t];
    }
    __syncthreads();
    for (int e = t; e < EPG; e += 256) {
        float w = ew ? ew[ebase + e] : 1.0f;
        if (w != 0.f) {
            int s = src[ebase + e] - nbase;
            int d = dst[ebase + e] - nbase;
            float nm = rsqrtf(sdeg[s]) * rsqrtf(sdeg[d]) * w;
            int idx = atomicAdd(&spos[d], 1);
            cpack[ebase + idx] = make_int2(s, __float_as_int(nm));
        }
    }
}

// ---------------- fused aggregation + self-loop + bias + relu + score partial --
// block = (fc in [0,4), graph g); stages h tile [npg][64] in smem (R6 structure)
__global__ __launch_bounds__(256) void agg_fused_kernel(
        const float* __restrict__ h, const float* __restrict__ dinv,
        const int* __restrict__ rs, const int* __restrict__ rc,
        const int2* __restrict__ cpack, const float* __restrict__ bias,
        const float* __restrict__ pw, float* __restrict__ out,
        float* __restrict__ spart, int npg) {
    extern __shared__ float ht[];   // npg * 64 floats
    int fc = blockIdx.x, g = blockIdx.y;
    int t = threadIdx.x;
    int nbase = g * npg, ebase = g * EPG;

    const float4* h4 = (const float4*)h;
    float4* ht4 = (float4*)ht;
    for (int i = t; i < npg * 16; i += 256) {
        int node = i >> 4, q = i & 15;
        ht4[i] = h4[(size_t)(nbase + node) * 64 + fc * 16 + q];
    }
    __syncthreads();

    int w = t >> 5, lane = t & 31;
    float b0  = __ldg(bias + fc*64 + lane*2);
    float b1  = __ldg(bias + fc*64 + lane*2 + 1);
    float pw0 = __ldg(pw + fc*64 + lane*2);
    float pw1 = __ldg(pw + fc*64 + lane*2 + 1);
    for (int d = w; d < npg; d += 8) {
        float dv = dinv[nbase + d];
        float a0 = ht[d*64 + lane*2]     * dv + b0;
        float a1 = ht[d*64 + lane*2 + 1] * dv + b1;
        int cnt = rc[nbase + d];
        const int2* cp = cpack + ebase + rs[nbase + d];
        int e = 0;
        for (; e + 4 <= cnt; e += 4) {
            int2 p0 = __ldg(cp + e);
            int2 p1 = __ldg(cp + e + 1);
            int2 p2 = __ldg(cp + e + 2);
            int2 p3 = __ldg(cp + e + 3);
            a0 += __int_as_float(p0.y) * ht[p0.x*64 + lane*2];
            a1 += __int_as_float(p0.y) * ht[p0.x*64 + lane*2 + 1];
            a0 += __int_as_float(p1.y) * ht[p1.x*64 + lane*2];
            a1 += __int_as_float(p1.y) * ht[p1.x*64 + lane*2 + 1];
            a0 += __int_as_float(p2.y) * ht[p2.x*64 + lane*2];
            a1 += __int_as_float(p2.y) * ht[p2.x*64 + lane*2 + 1];
            a0 += __int_as_float(p3.y) * ht[p3.x*64 + lane*2];
            a1 += __int_as_float(p3.y) * ht[p3.x*64 + lane*2 + 1];
        }
        for (; e < cnt; e++) {
            int2 p = __ldg(cp + e);
            a0 += __int_as_float(p.y) * ht[p.x*64 + lane*2];
            a1 += __int_as_float(p.y) * ht[p.x*64 + lane*2 + 1];
        }
        float o0 = fmaxf(a0, 0.f);
        float o1 = fmaxf(a1, 0.f);
        *(float2*)(out + (size_t)(nbase + d) * 256 + fc*64 + lane*2) =
            make_float2(o0, o1);
        // score partial (deterministic shfl order)
        float sp = o0 * pw0 + o1 * pw1;
        #pragma unroll
        for (int off = 16; off > 0; off >>= 1)
            sp += __shfl_down_sync(0xFFFFFFFFu, sp, off);
        if (lane == 0) spart[fc * MAXN + nbase + d] = sp;
    }
}

// ---------------- pool: sum partials, tanh, ||w|| inline, rank-count top-k -----
__global__ void pool_kernel(const float* __restrict__ spart,
                            const float* __restrict__ pw,
                            float* __restrict__ score, int npg, int k,
                            int* __restrict__ newid, int* __restrict__ perm) {
    __shared__ float s[256];
    __shared__ float red[256];
    int g = blockIdx.x, t = threadIdx.x;
    float ss = 0.f;
    for (int i = t; i < 256; i += npg) { float v = pw[i]; ss += v * v; }
    red[t] = ss;
    __syncthreads();
    for (int st = npg >> 1; st > 0; st >>= 1) {
        if (t < st) red[t] += red[t + st];
        __syncthreads();
    }
    float winv = rsqrtf(red[0]);

    int node = g * npg + t;
    float acc = 0.f;
    #pragma unroll
    for (int c = 0; c < 4; c++) acc += spart[c * MAXN + node];
    float my = tanhf(acc * winv);
    score[node] = my;
    s[t] = my;
    __syncthreads();
    int rank = 0;
    for (int j = 0; j < npg; j++) {
        float v = s[j];
        rank += (v > my) || (v == my && j < t);
    }
    if (rank < k) {
        newid[node] = g * k + rank;
        perm[g * k + rank] = node;
    } else {
        newid[node] = -1;
    }
}

// ---------------- gather*score + fp16 split for next GEMM ----------------
__global__ void gather_split_kernel(const float* __restrict__ x,
                                    const float* __restrict__ score,
                                    const int* __restrict__ perm,
                                    float* __restrict__ nx,
                                    __half* __restrict__ xhi,
                                    __half* __restrict__ xlo, int nNew) {
    int i = blockIdx.x * blockDim.x + threadIdx.x;
    if (i >= nNew * HF) return;
    int nn = i >> 8, f = i & 255;
    int old = perm[nn];
    float v = x[(size_t)old * HF + f] * score[old];
    nx[i] = v;
    __half h = __float2half_rn(v);
    xhi[i] = h;
    xlo[i] = __float2half_rn(v - __half2float(h));
}

__global__ void gather_scale_kernel(const float* __restrict__ x,
                                    const float* __restrict__ score,
                                    const int* __restrict__ perm,
                                    float* __restrict__ nx, int nNew) {
    int i = blockIdx.x * blockDim.x + threadIdx.x;
    if (i >= nNew * HF) return;
    int nn = i >> 8, f = i & 255;
    int old = perm[nn];
    nx[i] = x[(size_t)old * HF + f] * score[old];
}

__global__ void remap_kernel(const int* __restrict__ src, const int* __restrict__ dst,
                             const float* __restrict__ ew, const int* __restrict__ newid,
                             int* __restrict__ nsrc, int* __restrict__ ndst,
                             float* __restrict__ new_ew, int E) {
    int e = blockIdx.x * blockDim.x + threadIdx.x;
    if (e >= E) return;
    int s = newid[src[e]], d = newid[dst[e]];
    float w = ew ? ew[e] : 1.0f;
    bool valid = (s >= 0) && (d >= 0);
    nsrc[e]   = valid ? s : 0;
    ndst[e]   = valid ? d : 0;
    new_ew[e] = valid ? w : 0.f;
}

// ---------------- readout: [max | mean] per graph ----------------
__global__ void readout_kernel(const float* __restrict__ x, int k,
                               float* __restrict__ ro, int accumulate) {
    int g = blockIdx.x, f = threadIdx.x;
    const float* base = x + (size_t)g * k * HF + f;
    float mx = -3.4e38f, sum = 0.f;
    for (int j = 0; j < k; j++) {
        float v = base[(size_t)j * HF];
        mx = fmaxf(mx, v);
        sum += v;
    }
    float mean = sum / (float)k;
    if (accumulate) {
        ro[g*512 + f]       += mx;
        ro[g*512 + 256 + f] += mean;
    } else {
        ro[g*512 + f]       = mx;
        ro[g*512 + 256 + f] = mean;
    }
}

// ---------------- MLP (multi-graph blocks to amortize weight reads) ------------
__global__ __launch_bounds__(256) void lin1_kernel(const float* __restrict__ in,
        const float* __restrict__ W, const float* __restrict__ b,
        float* __restrict__ out) {
    int gb = blockIdx.x * 8, c = threadIdx.x;
    __shared__ float rows[8 * 512];
    for (int i = c; i < 8 * 512; i += 256) rows[i] = in[gb * 512 + i];
    __syncthreads();
    float acc[8];
    float bc = b[c];
    #pragma unroll
    for (int gg = 0; gg < 8; gg++) acc[gg] = bc;
    for (int kk = 0; kk < 512; kk++) {
        float wv = W[kk * 256 + c];
        #pragma unroll
        for (int gg = 0; gg < 8; gg++) acc[gg] += rows[gg * 512 + kk] * wv;
    }
    #pragma unroll
    for (int gg = 0; gg < 8; gg++)
        out[(gb + gg) * 256 + c] = fmaxf(acc[gg], 0.f);
}
__global__ __launch_bounds__(128) void lin2_kernel(const float* __restrict__ in,
        const float* __restrict__ W, const float* __restrict__ b,
        float* __restrict__ out) {
    int gb = blockIdx.x * 16, c = threadIdx.x;
    __shared__ float rows[16 * 256];
    for (int i = c; i < 16 * 256; i += 128) rows[i] = in[gb * 256 + i];
    __syncthreads();
    float acc[16];
    float bc = b[c];
    #pragma unroll
    for (int gg = 0; gg < 16; gg++) acc[gg] = bc;
    for (int kk = 0; kk < 256; kk++) {
        float wv = W[kk * 128 + c];
        #pragma unroll
        for (int gg = 0; gg < 16; gg++) acc[gg] += rows[gg * 256 + kk] * wv;
    }
    #pragma unroll
    for (int gg = 0; gg < 16; gg++)
        out[(gb + gg) * 128 + c] = fmaxf(acc[gg], 0.f);
}
__global__ void lin3_lsm_kernel(const float* __restrict__ in, const float* __restrict__ W,
                                const float* __restrict__ b, float* __restrict__ out) {
    int g = blockIdx.x, lane = threadIdx.x;
    const float* row = in + g*128;
    float a0 = 0.f, a1 = 0.f;
    #pragma unroll
    for (int kk = lane; kk < 128; kk += 32) {
        float v = row[kk];
        a0 += v * W[kk*2 + 0];
        a1 += v * W[kk*2 + 1];
    }
    #pragma unroll
    for (int o = 16; o > 0; o >>= 1) {
        a0 += __shfl_down_sync(0xFFFFFFFFu, a0, o);
        a1 += __shfl_down_sync(0xFFFFFFFFu, a1, o);
    }
    if (lane == 0) {
        float l0 = a0 + b[0], l1 = a1 + b[1];
        float m = fmaxf(l0, l1);
        float lse = m + logf(expf(l0 - m) + expf(l1 - m));
        out[g*2 + 0] = l0 - lse;
        out[g*2 + 1] = l1 - lse;
    }
}

// ---------------- host driver ----------------
extern "C" void kernel_launch(void* const* d_in, const int* in_sizes, int n_in,
                              void* d_out, int out_size) {
    const float* d_x      = (const float*)d_in[0];
    const int*   d_ei     = (const int*)d_in[1];
    const float* gcn_w0   = (const float*)d_in[3];
    const float* gcn_b0   = (const float*)d_in[4];
    const float* gcn_w1   = (const float*)d_in[5];
    const float* gcn_b1   = (const float*)d_in[6];
    const float* gcn_w2   = (const float*)d_in[7];
    const float* gcn_b2   = (const float*)d_in[8];
    const float* pool_w0  = (const float*)d_in[9];
    const float* pool_w1  = (const float*)d_in[10];
    const float* pool_w2  = (const float*)d_in[11];
    const float* lin1_w   = (const float*)d_in[12];
    const float* lin1_b   = (const float*)d_in[13];
    const float* lin2_w   = (const float*)d_in[14];
    const float* lin2_b   = (const float*)d_in[15];
    const float* lin3_w   = (const float*)d_in[16];
    const float* lin3_b   = (const float*)d_in[17];
    float* out = (float*)d_out;

    const int E = in_sizes[1] / 2;
    const int* d_src = d_ei;
    const int* d_dst = d_ei + E;

    float *p_h, *p_agg, *p_x, *p_dinv, *p_score, *p_spart, *p_ro, *p_h1, *p_h2;
    int *p_newid, *p_perm, *p_es0, *p_ed0, *p_es1, *p_ed1, *p_rs, *p_rc;
    int2 *p_cpack;
    float *p_ew0, *p_ew1;
    __half *p_xhi, *p_xlo, *p_whi, *p_wlo;
    cudaGetSymbolAddress((void**)&p_h,    g_h);
    cudaGetSymbolAddress((void**)&p_agg,  g_agg);
    cudaGetSymbolAddress((void**)&p_x,    g_x);
    cudaGetSymbolAddress((void**)&p_dinv, g_dinv);
    cudaGetSymbolAddress((void**)&p_score,g_score);
    cudaGetSymbolAddress((void**)&p_spart,g_spart);
    cudaGetSymbolAddress((void**)&p_newid,g_newid);
    cudaGetSymbolAddress((void**)&p_perm, g_perm);
    cudaGetSymbolAddress((void**)&p_es0,  g_esrc0);
    cudaGetSymbolAddress((void**)&p_ed0,  g_edst0);
    cudaGetSymbolAddress((void**)&p_ew0,  g_eew0);
    cudaGetSymbolAddress((void**)&p_es1,  g_esrc1);
    cudaGetSymbolAddress((void**)&p_ed1,  g_edst1);
    cudaGetSymbolAddress((void**)&p_ew1,  g_eew1);
    cudaGetSymbolAddress((void**)&p_rs,   g_rs);
    cudaGetSymbolAddress((void**)&p_rc,   g_rc);
    cudaGetSymbolAddress((void**)&p_cpack,g_cpack);
    cudaGetSymbolAddress((void**)&p_ro,   g_ro);
    cudaGetSymbolAddress((void**)&p_h1,   g_h1);
    cudaGetSymbolAddress((void**)&p_h2,   g_h2);
    cudaGetSymbolAddress((void**)&p_xhi,  g_xhi);
    cudaGetSymbolAddress((void**)&p_xlo,  g_xlo);
    cudaGetSymbolAddress((void**)&p_whi,  g_whi);
    cudaGetSymbolAddress((void**)&p_wlo,  g_wlo);

    cudaFuncSetAttribute(agg_fused_kernel,
                         cudaFuncAttributeMaxDynamicSharedMemorySize, 65536);

    // ---------------- level 0 ----------------
    int n = MAXN;
    {
        int npg = 256;
        wsplit_kernel<<<128, 256>>>(gcn_w0, 128, p_whi, p_wlo);
        xsplit_kernel<<<(n * 128 + 255) / 256, 256>>>(d_x, n * 128, p_xhi, p_xlo);
        gemm_mma_kernel<<<dim3(n / 128, 2), 256, MMA_SMEM>>>(p_xhi, p_xlo, p_whi, p_wlo, p_h, 128);
        csr_build_kernel<<<G, 256>>>(d_src, d_dst, nullptr, npg, p_rs, p_rc, p_cpack, p_dinv);
        agg_fused_kernel<<<dim3(4, G), 256, npg*64*4>>>(p_h, p_dinv, p_rs, p_rc,
                                                        p_cpack, gcn_b0, pool_w0,
                                                        p_agg, p_spart, npg);
    }
    {
        int npg = 256, k = 128, nNew = G * k;
        pool_kernel<<<G, npg>>>(p_spart, pool_w0, p_score, npg, k, p_newid, p_perm);
        gather_split_kernel<<<(nNew * HF + 255) / 256, 256>>>(p_agg, p_score, p_perm,
                                                              p_x, p_xhi, p_xlo, nNew);
        remap_kernel<<<(E + 255) / 256, 256>>>(d_src, d_dst, nullptr, p_newid,
                                               p_es0, p_ed0, p_ew0, E);
        readout_kernel<<<G, 256>>>(p_x, k, p_ro, 0);
        n = nNew;                 // 32768
    }
    // ---------------- level 1 ----------------
    {
        int npg = 128;
        wsplit_kernel<<<256, 256>>>(gcn_w1, 256, p_whi, p_wlo);
        gemm_mma_kernel<<<dim3(n / 128, 2), 256, MMA_SMEM>>>(p_xhi, p_xlo, p_whi, p_wlo, p_h, 256);
        csr_build_kernel<<<G, 256>>>(p_es0, p_ed0, p_ew0, npg, p_rs, p_rc, p_cpack, p_dinv);
        agg_fused_kernel<<<dim3(4, G), 256, npg*64*4>>>(p_h, p_dinv, p_rs, p_rc,
                                                        p_cpack, gcn_b1, pool_w1,
                                                        p_agg, p_spart, npg);
    }
    {
        int npg = 128, k = 64, nNew = G * k;
        pool_kernel<<<G, npg>>>(p_spart, pool_w1, p_score, npg, k, p_newid, p_perm);
        gather_split_kernel<<<(nNew * HF + 255) / 256, 256>>>(p_agg, p_score, p_perm,
                                                              p_x, p_xhi, p_xlo, nNew);
        remap_kernel<<<(E + 255) / 256, 256>>>(p_es0, p_ed0, p_ew0, p_newid,
                                               p_es1, p_ed1, p_ew1, E);
        readout_kernel<<<G, 256>>>(p_x, k, p_ro, 1);
        n = nNew;                 // 16384
    }
    // ---------------- level 2 ----------------
    {
        int npg = 64;
        wsplit_kernel<<<256, 256>>>(gcn_w2, 256, p_whi, p_wlo);
        gemm_mma_kernel<<<dim3(n / 128, 2), 256, MMA_SMEM>>>(p_xhi, p_xlo, p_whi, p_wlo, p_h, 256);
        csr_build_kernel<<<G, 256>>>(p_es1, p_ed1, p_ew1, npg, p_rs, p_rc, p_cpack, p_dinv);
        agg_fused_kernel<<<dim3(4, G), 256, npg*64*4>>>(p_h, p_dinv, p_rs, p_rc,
                                                        p_cpack, gcn_b2, pool_w2,
                                                        p_agg, p_spart, npg);
    }
    {
        int npg = 64, k = 32;
        pool_kernel<<<G, npg>>>(p_spart, pool_w2, p_score, npg, k, p_newid, p_perm);
        gather_scale_kernel<<<(G * k * HF + 255) / 256, 256>>>(p_agg, p_score, p_perm, p_x, G * k);
        readout_kernel<<<G, 256>>>(p_x, k, p_ro, 1);
    }

    // ---------------- MLP head ----------------
    lin1_kernel<<<32, 256>>>(p_ro, lin1_w, lin1_b, p_h1);
    lin2_kernel<<<16, 128>>>(p_h1, lin2_w, lin2_b, p_h2);
    lin3_lsm_kernel<<<G, 32>>>(p_h2, lin3_w, lin3_b, out);
}

// round 10
// speedup vs baseline: 2.1874x; 1.3672x over previous
#include <cuda_runtime.h>
#include <cuda_fp16.h>
#include <math.h>
#include <stdint.h>

// Problem constants
#define G 256
#define N0 256
#define HF 256            // hidden feature dim
#define MAXN (G*N0)       // 65536
#define MAXE (G*2048)     // 524288
#define EPG 2048          // edges per graph (fixed slot count, masked edges have ew=0)

// -------- scratch (device globals; no allocation allowed) --------
__device__ float g_h[MAXN*HF];        // 64 MB : h = x @ W
__device__ float g_agg[MAXN*HF];      // 64 MB : conv output
__device__ float g_x[(MAXN/2)*HF];    // 32 MB : pooled features
__device__ float g_dinv[MAXN];
__device__ float g_score[MAXN];
__device__ int   g_newid[MAXN];
__device__ int   g_perm[MAXN/2];
__device__ int   g_esrc0[MAXE], g_edst0[MAXE];
__device__ float g_eew0[MAXE];
__device__ int   g_esrc1[MAXE], g_edst1[MAXE];
__device__ float g_eew1[MAXE];
__device__ int   g_rs[MAXN];
__device__ int   g_rc[MAXN];
__device__ int2  g_cpack[MAXE];       // CSR packed (src, norm-bits)
__device__ float g_ro[G*512];
__device__ float g_h1[G*256];
__device__ float g_h2[G*128];
__device__ float g_winv;
// X split buffers (fp16 hi/lo)
__device__ __half g_xhi[8388608];
__device__ __half g_xlo[8388608];
// W split buffers (fp16 hi/lo, [256 (N)] x [K] K-major), K<=256
__device__ __half g_whi[256*256];
__device__ __half g_wlo[256*256];

// ================= helpers =================
__device__ __forceinline__ uint32_t smem_u32(const void* p) {
    uint32_t a;
    asm("{ .reg .u64 t; cvta.to.shared.u64 t, %1; cvt.u32.u64 %0, t; }"
        : "=r"(a) : "l"(p));
    return a;
}
__device__ __forceinline__ void ldsm_x4(uint32_t* r, uint32_t addr) {
    asm volatile("ldmatrix.sync.aligned.m8n8.x4.shared.b16 {%0,%1,%2,%3}, [%4];"
        : "=r"(r[0]), "=r"(r[1]), "=r"(r[2]), "=r"(r[3]) : "r"(addr));
}
__device__ __forceinline__ void ldsm_x2(uint32_t* r, uint32_t addr) {
    asm volatile("ldmatrix.sync.aligned.m8n8.x2.shared.b16 {%0,%1}, [%2];"
        : "=r"(r[0]), "=r"(r[1]) : "r"(addr));
}
__device__ __forceinline__ void mma_f16(float* d, const uint32_t* a, const uint32_t* b) {
    asm volatile("mma.sync.aligned.m16n8k16.row.col.f32.f16.f16.f32 "
        "{%0,%1,%2,%3}, {%4,%5,%6,%7}, {%8,%9}, {%0,%1,%2,%3};"
        : "+f"(d[0]), "+f"(d[1]), "+f"(d[2]), "+f"(d[3])
        : "r"(a[0]), "r"(a[1]), "r"(a[2]), "r"(a[3]), "r"(b[0]), "r"(b[1]));
}

// ================= split pre-passes (fp16 2-way) =================
__global__ void xsplit_kernel(const float* __restrict__ X, int total,
                              __half* __restrict__ xhi, __half* __restrict__ xlo) {
    int i = blockIdx.x * 256 + threadIdx.x;
    if (i >= total) return;
    float v = X[i];
    __half h = __float2half_rn(v);
    __half l = __float2half_rn(v - __half2float(h));
    xhi[i] = h; xlo[i] = l;
}

__global__ void wsplit_kernel(const float* __restrict__ W, int K,
                              __half* __restrict__ whi, __half* __restrict__ wlo) {
    int idx = blockIdx.x * 256 + threadIdx.x;
    if (idx >= K * 256) return;
    int k = idx >> 8, n = idx & 255;
    float w = W[idx];
    __half h = __float2half_rn(w);
    __half l = __float2half_rn(w - __half2float(h));
    whi[n*K + k] = h; wlo[n*K + k] = l;
}

// ================= MMA GEMM: C[n,256] = X[n,K] @ W[K,256] =================
// near-fp32 via fp16 2-way split, 3 product segments (hh, hl, lh; ll ~2^-22 dropped).
#define SEGB 6144
#define MMA_SMEM (4*SEGB)

__global__ __launch_bounds__(256) void gemm_mma_kernel(
        const __half* __restrict__ Xhi, const __half* __restrict__ Xlo,
        const __half* __restrict__ Whi, const __half* __restrict__ Wlo,
        float* __restrict__ C, int K) {
    extern __shared__ __align__(16) char smem[];
    char* smA = smem;                  // 2 segs
    char* smB = smem + 2*SEGB;         // 2 segs
    uint32_t sb = smem_u32(smem);
    int tid = threadIdx.x, w = tid >> 5, lane = tid & 31;
    int rowBase = blockIdx.x * 128, colBase = blockIdx.y * 128;
    int warpRow = (w >> 2) * 64, warpCol = (w & 3) * 32;

    float acc[4][4][4];
    #pragma unroll
    for (int i = 0; i < 4; i++)
        #pragma unroll
        for (int j = 0; j < 4; j++)
            #pragma unroll
            for (int d = 0; d < 4; d++) acc[i][j][d] = 0.f;

    int r  = tid >> 1;
    int hf = tid & 1;
    uint32_t stOff = (uint32_t)(r * 48 + hf * 16);

    int bl = lane & 15;
    uint32_t aFragBase = sb + (uint32_t)((warpRow + (lane & 15)) * 48 + (lane >> 4) * 16);
    uint32_t bFragBase = sb + 2*SEGB
                       + (uint32_t)((warpCol + (bl & 7)) * 48 + (bl >> 3) * 16);

    const int NC = K >> 4;
    for (int kb = 0; kb < NC; kb++) {
        {
            size_t goff = (size_t)(rowBase + r) * K + kb * 16 + hf * 8;
            *(uint4*)(smA        + stOff) = *(const uint4*)(Xhi + goff);
            *(uint4*)(smA + SEGB + stOff) = *(const uint4*)(Xlo + goff);
        }
        {
            size_t goff = (size_t)(colBase + r) * K + kb * 16 + hf * 8;
            *(uint4*)(smB        + stOff) = *(const uint4*)(Whi + goff);
            *(uint4*)(smB + SEGB + stOff) = *(const uint4*)(Wlo + goff);
        }
        __syncthreads();

        uint32_t bfr[2][4][2];
        #pragma unroll
        for (int s = 0; s < 2; s++)
            #pragma unroll
            for (int nt = 0; nt < 4; nt++)
                ldsm_x2(bfr[s][nt], bFragBase + s*SEGB + nt*(8*48));

        #pragma unroll
        for (int mt = 0; mt < 4; mt++) {
            uint32_t afr[2][4];
            #pragma unroll
            for (int s = 0; s < 2; s++)
                ldsm_x4(afr[s], aFragBase + s*SEGB + mt*(16*48));
            #pragma unroll
            for (int cb = 0; cb < 3; cb++) {        // hh, hl, lh
                int ai = (cb == 2) ? 1 : 0;
                int bi = (cb == 1) ? 1 : 0;
                #pragma unroll
                for (int nt = 0; nt < 4; nt++)
                    mma_f16(acc[mt][nt], afr[ai], bfr[bi][nt]);
            }
        }
        __syncthreads();
    }

    #pragma unroll
    for (int mt = 0; mt < 4; mt++) {
        int row = rowBase + warpRow + mt*16 + (lane >> 2);
        #pragma unroll
        for (int nt = 0; nt < 4; nt++) {
            int col = colBase + warpCol + nt*8 + (lane & 3)*2;
            *(float2*)&C[(size_t)row * 256 + col] =
                make_float2(acc[mt][nt][0], acc[mt][nt][1]);
            *(float2*)&C[(size_t)(row + 8) * 256 + col] =
                make_float2(acc[mt][nt][2], acc[mt][nt][3]);
        }
    }
}

// ---------------- per-graph CSR build (block = graph, 256 threads) ----------------
__global__ __launch_bounds__(256) void csr_build_kernel(
        const int* __restrict__ src, const int* __restrict__ dst,
        const float* __restrict__ ew, int npg,
        int* __restrict__ rs, int* __restrict__ rc,
        int2* __restrict__ cpack, float* __restrict__ dinv) {
    __shared__ float sdeg[256];
    __shared__ int   scnt[256];
    __shared__ int   sscan[256];
    __shared__ int   spos[256];
    int g = blockIdx.x, t = threadIdx.x;
    int nbase = g * npg, ebase = g * EPG;

    if (t < npg) { sdeg[t] = 1.0f; scnt[t] = 0; }
    __syncthreads();
    for (int e = t; e < EPG; e += 256) {
        float w = ew ? ew[ebase + e] : 1.0f;
        if (w != 0.f) {
            int d = dst[ebase + e] - nbase;
            atomicAdd(&sdeg[d], w);
            atomicAdd(&scnt[d], 1);
        }
    }
    __syncthreads();
    int v = (t < npg) ? scnt[t] : 0;
    sscan[t] = v;
    __syncthreads();
    #pragma unroll
    for (int off = 1; off < 256; off <<= 1) {
        int add = (t >= off) ? sscan[t - off] : 0;
        __syncthreads();
        sscan[t] += add;
        __syncthreads();
    }
    int start = sscan[t] - v;
    if (t < npg) {
        rs[nbase + t] = start;
        rc[nbase + t] = v;
        spos[t] = start;
        dinv[nbase + t] = 1.0f / sdeg[t];
    }
    __syncthreads();
    for (int e = t; e < EPG; e += 256) {
        float w = ew ? ew[ebase + e] : 1.0f;
        if (w != 0.f) {
            int s = src[ebase + e] - nbase;
            int d = dst[ebase + e] - nbase;
            float nm = rsqrtf(sdeg[s]) * rsqrtf(sdeg[d]) * w;
            int idx = atomicAdd(&spos[d], 1);
            cpack[ebase + idx] = make_int2(s, __float_as_int(nm));
        }
    }
}

// ---------------- fused aggregation + self-loop + bias + relu ----------------
// block = (fc in [0,4), graph g); stages h tile [npg][64] in smem
__global__ __launch_bounds__(256) void agg_fused_kernel(
        const float* __restrict__ h, const float* __restrict__ dinv,
        const int* __restrict__ rs, const int* __restrict__ rc,
        const int2* __restrict__ cpack, const float* __restrict__ bias,
        float* __restrict__ out, int npg) {
    extern __shared__ float ht[];   // npg * 64 floats
    int fc = blockIdx.x, g = blockIdx.y;
    int t = threadIdx.x;
    int nbase = g * npg, ebase = g * EPG;

    const float4* h4 = (const float4*)h;
    float4* ht4 = (float4*)ht;
    for (int i = t; i < npg * 16; i += 256) {
        int node = i >> 4, q = i & 15;
        ht4[i] = h4[(size_t)(nbase + node) * 64 + fc * 16 + q];
    }
    __syncthreads();

    int w = t >> 5, lane = t & 31;
    float b0 = __ldg(bias + fc*64 + lane*2);
    float b1 = __ldg(bias + fc*64 + lane*2 + 1);
    for (int d = w; d < npg; d += 8) {
        float dv = dinv[nbase + d];
        float a0 = ht[d*64 + lane*2]     * dv + b0;
        float a1 = ht[d*64 + lane*2 + 1] * dv + b1;
        int cnt = rc[nbase + d];
        const int2* cp = cpack + ebase + rs[nbase + d];
        int e = 0;
        for (; e + 4 <= cnt; e += 4) {
            int2 p0 = __ldg(cp + e);
            int2 p1 = __ldg(cp + e + 1);
            int2 p2 = __ldg(cp + e + 2);
            int2 p3 = __ldg(cp + e + 3);
            a0 += __int_as_float(p0.y) * ht[p0.x*64 + lane*2];
            a1 += __int_as_float(p0.y) * ht[p0.x*64 + lane*2 + 1];
            a0 += __int_as_float(p1.y) * ht[p1.x*64 + lane*2];
            a1 += __int_as_float(p1.y) * ht[p1.x*64 + lane*2 + 1];
            a0 += __int_as_float(p2.y) * ht[p2.x*64 + lane*2];
            a1 += __int_as_float(p2.y) * ht[p2.x*64 + lane*2 + 1];
            a0 += __int_as_float(p3.y) * ht[p3.x*64 + lane*2];
            a1 += __int_as_float(p3.y) * ht[p3.x*64 + lane*2 + 1];
        }
        for (; e < cnt; e++) {
            int2 p = __ldg(cp + e);
            a0 += __int_as_float(p.y) * ht[p.x*64 + lane*2];
            a1 += __int_as_float(p.y) * ht[p.x*64 + lane*2 + 1];
        }
        float2 o;
        o.x = fmaxf(a0, 0.f);
        o.y = fmaxf(a1, 0.f);
        *(float2*)(out + (size_t)(nbase + d) * 256 + fc*64 + lane*2) = o;
    }
}

// ---------------- pooling ----------------
__global__ void wnorm_kernel(const float* __restrict__ w) {
    __shared__ float red[256];
    int t = threadIdx.x;
    float v = w[t];
    red[t] = v * v;
    __syncthreads();
    for (int s = 128; s > 0; s >>= 1) {
        if (t < s) red[t] += red[t + s];
        __syncthreads();
    }
    if (t == 0) g_winv = rsqrtf(red[0]);
}

__global__ void score_kernel(const float* __restrict__ x, const float* __restrict__ w,
                             float* __restrict__ score, int n) {
    int gt = blockIdx.x * blockDim.x + threadIdx.x;
    int node = gt >> 5, lane = gt & 31;
    if (node >= n) return;
    const float* row = x + (size_t)node * HF;
    float s = 0.f;
    #pragma unroll
    for (int f = lane; f < HF; f += 32) s += row[f] * w[f];
    #pragma unroll
    for (int o = 16; o > 0; o >>= 1) s += __shfl_down_sync(0xFFFFFFFFu, s, o);
    if (lane == 0) score[node] = tanhf(s * g_winv);
}

__global__ void pool_kernel(const float* __restrict__ score, int npg, int k,
                            int* __restrict__ newid, int* __restrict__ perm) {
    __shared__ float s[256];
    int g = blockIdx.x, t = threadIdx.x;
    int node = g * npg + t;
    float my = score[node];
    s[t] = my;
    __syncthreads();
    int rank = 0;
    for (int j = 0; j < npg; j++) {
        float v = s[j];
        rank += (v > my) || (v == my && j < t);
    }
    if (rank < k) {
        newid[node] = g * k + rank;
        perm[g * k + rank] = node;
    } else {
        newid[node] = -1;
    }
}

// ---------------- gather*score + fp16 split for next GEMM ----------------
__global__ void gather_split_kernel(const float* __restrict__ x,
                                    const float* __restrict__ score,
                                    const int* __restrict__ perm,
                                    float* __restrict__ nx,
                                    __half* __restrict__ xhi,
                                    __half* __restrict__ xlo, int nNew) {
    int i = blockIdx.x * blockDim.x + threadIdx.x;
    if (i >= nNew * HF) return;
    int nn = i >> 8, f = i & 255;
    int old = perm[nn];
    float v = x[(size_t)old * HF + f] * score[old];
    nx[i] = v;
    __half h = __float2half_rn(v);
    xhi[i] = h;
    xlo[i] = __float2half_rn(v - __half2float(h));
}

__global__ void gather_scale_kernel(const float* __restrict__ x,
                                    const float* __restrict__ score,
                                    const int* __restrict__ perm,
                                    float* __restrict__ nx, int nNew) {
    int i = blockIdx.x * blockDim.x + threadIdx.x;
    if (i >= nNew * HF) return;
    int nn = i >> 8, f = i & 255;
    int old = perm[nn];
    nx[i] = x[(size_t)old * HF + f] * score[old];
}

__global__ void remap_kernel(const int* __restrict__ src, const int* __restrict__ dst,
                             const float* __restrict__ ew, const int* __restrict__ newid,
                             int* __restrict__ nsrc, int* __restrict__ ndst,
                             float* __restrict__ new_ew, int E) {
    int e = blockIdx.x * blockDim.x + threadIdx.x;
    if (e >= E) return;
    int s = newid[src[e]], d = newid[dst[e]];
    float w = ew ? ew[e] : 1.0f;
    bool valid = (s >= 0) && (d >= 0);
    nsrc[e]   = valid ? s : 0;
    ndst[e]   = valid ? d : 0;
    new_ew[e] = valid ? w : 0.f;
}

// ---------------- readout: [max | mean] per graph ----------------
__global__ void readout_kernel(const float* __restrict__ x, int k,
                               float* __restrict__ ro, int accumulate) {
    int g = blockIdx.x, f = threadIdx.x;
    const float* base = x + (size_t)g * k * HF + f;
    float mx = -3.4e38f, sum = 0.f;
    for (int j = 0; j < k; j++) {
        float v = base[(size_t)j * HF];
        mx = fmaxf(mx, v);
        sum += v;
    }
    float mean = sum / (float)k;
    if (accumulate) {
        ro[g*512 + f]       += mx;
        ro[g*512 + 256 + f] += mean;
    } else {
        ro[g*512 + f]       = mx;
        ro[g*512 + 256 + f] = mean;
    }
}

// ---------------- MLP (multi-graph blocks to amortize weight reads) ------------
__global__ __launch_bounds__(256) void lin1_kernel(const float* __restrict__ in,
        const float* __restrict__ W, const float* __restrict__ b,
        float* __restrict__ out) {
    int gb = blockIdx.x * 8, c = threadIdx.x;
    __shared__ float rows[8 * 512];
    for (int i = c; i < 8 * 512; i += 256) rows[i] = in[gb * 512 + i];
    __syncthreads();
    float acc[8];
    float bc = b[c];
    #pragma unroll
    for (int gg = 0; gg < 8; gg++) acc[gg] = bc;
    for (int kk = 0; kk < 512; kk++) {
        float wv = W[kk * 256 + c];
        #pragma unroll
        for (int gg = 0; gg < 8; gg++) acc[gg] += rows[gg * 512 + kk] * wv;
    }
    #pragma unroll
    for (int gg = 0; gg < 8; gg++)
        out[(gb + gg) * 256 + c] = fmaxf(acc[gg], 0.f);
}
__global__ __launch_bounds__(128) void lin2_kernel(const float* __restrict__ in,
        const float* __restrict__ W, const float* __restrict__ b,
        float* __restrict__ out) {
    int gb = blockIdx.x * 16, c = threadIdx.x;
    __shared__ float rows[16 * 256];
    for (int i = c; i < 16 * 256; i += 128) rows[i] = in[gb * 256 + i];
    __syncthreads();
    float acc[16];
    float bc = b[c];
    #pragma unroll
    for (int gg = 0; gg < 16; gg++) acc[gg] = bc;
    for (int kk = 0; kk < 256; kk++) {
        float wv = W[kk * 128 + c];
        #pragma unroll
        for (int gg = 0; gg < 16; gg++) acc[gg] += rows[gg * 256 + kk] * wv;
    }
    #pragma unroll
    for (int gg = 0; gg < 16; gg++)
        out[(gb + gg) * 128 + c] = fmaxf(acc[gg], 0.f);
}
__global__ void lin3_lsm_kernel(const float* __restrict__ in, const float* __restrict__ W,
                                const float* __restrict__ b, float* __restrict__ out) {
    int g = blockIdx.x, lane = threadIdx.x;
    const float* row = in + g*128;
    float a0 = 0.f, a1 = 0.f;
    #pragma unroll
    for (int kk = lane; kk < 128; kk += 32) {
        float v = row[kk];
        a0 += v * W[kk*2 + 0];
        a1 += v * W[kk*2 + 1];
    }
    #pragma unroll
    for (int o = 16; o > 0; o >>= 1) {
        a0 += __shfl_down_sync(0xFFFFFFFFu, a0, o);
        a1 += __shfl_down_sync(0xFFFFFFFFu, a1, o);
    }
    if (lane == 0) {
        float l0 = a0 + b[0], l1 = a1 + b[1];
        float m = fmaxf(l0, l1);
        float lse = m + logf(expf(l0 - m) + expf(l1 - m));
        out[g*2 + 0] = l0 - lse;
        out[g*2 + 1] = l1 - lse;
    }
}

// ---------------- host driver ----------------
extern "C" void kernel_launch(void* const* d_in, const int* in_sizes, int n_in,
                              void* d_out, int out_size) {
    const float* d_x      = (const float*)d_in[0];
    const int*   d_ei     = (const int*)d_in[1];
    const float* gcn_w0   = (const float*)d_in[3];
    const float* gcn_b0   = (const float*)d_in[4];
    const float* gcn_w1   = (const float*)d_in[5];
    const float* gcn_b1   = (const float*)d_in[6];
    const float* gcn_w2   = (const float*)d_in[7];
    const float* gcn_b2   = (const float*)d_in[8];
    const float* pool_w0  = (const float*)d_in[9];
    const float* pool_w1  = (const float*)d_in[10];
    const float* pool_w2  = (const float*)d_in[11];
    const float* lin1_w   = (const float*)d_in[12];
    const float* lin1_b   = (const float*)d_in[13];
    const float* lin2_w   = (const float*)d_in[14];
    const float* lin2_b   = (const float*)d_in[15];
    const float* lin3_w   = (const float*)d_in[16];
    const float* lin3_b   = (const float*)d_in[17];
    float* out = (float*)d_out;

    const int E = in_sizes[1] / 2;
    const int* d_src = d_ei;
    const int* d_dst = d_ei + E;

    float *p_h, *p_agg, *p_x, *p_dinv, *p_score, *p_ro, *p_h1, *p_h2;
    int *p_newid, *p_perm, *p_es0, *p_ed0, *p_es1, *p_ed1, *p_rs, *p_rc;
    int2 *p_cpack;
    float *p_ew0, *p_ew1;
    __half *p_xhi, *p_xlo, *p_whi, *p_wlo;
    cudaGetSymbolAddress((void**)&p_h,    g_h);
    cudaGetSymbolAddress((void**)&p_agg,  g_agg);
    cudaGetSymbolAddress((void**)&p_x,    g_x);
    cudaGetSymbolAddress((void**)&p_dinv, g_dinv);
    cudaGetSymbolAddress((void**)&p_score,g_score);
    cudaGetSymbolAddress((void**)&p_newid,g_newid);
    cudaGetSymbolAddress((void**)&p_perm, g_perm);
    cudaGetSymbolAddress((void**)&p_es0,  g_esrc0);
    cudaGetSymbolAddress((void**)&p_ed0,  g_edst0);
    cudaGetSymbolAddress((void**)&p_ew0,  g_eew0);
    cudaGetSymbolAddress((void**)&p_es1,  g_esrc1);
    cudaGetSymbolAddress((void**)&p_ed1,  g_edst1);
    cudaGetSymbolAddress((void**)&p_ew1,  g_eew1);
    cudaGetSymbolAddress((void**)&p_rs,   g_rs);
    cudaGetSymbolAddress((void**)&p_rc,   g_rc);
    cudaGetSymbolAddress((void**)&p_cpack,g_cpack);
    cudaGetSymbolAddress((void**)&p_ro,   g_ro);
    cudaGetSymbolAddress((void**)&p_h1,   g_h1);
    cudaGetSymbolAddress((void**)&p_h2,   g_h2);
    cudaGetSymbolAddress((void**)&p_xhi,  g_xhi);
    cudaGetSymbolAddress((void**)&p_xlo,  g_xlo);
    cudaGetSymbolAddress((void**)&p_whi,  g_whi);
    cudaGetSymbolAddress((void**)&p_wlo,  g_wlo);

    cudaFuncSetAttribute(agg_fused_kernel,
                         cudaFuncAttributeMaxDynamicSharedMemorySize, 65536);

    // ---------------- level 0 ----------------
    int n = MAXN;
    {
        int npg = 256;
        wsplit_kernel<<<128, 256>>>(gcn_w0, 128, p_whi, p_wlo);
        xsplit_kernel<<<(n * 128 + 255) / 256, 256>>>(d_x, n * 128, p_xhi, p_xlo);
        gemm_mma_kernel<<<dim3(n / 128, 2), 256, MMA_SMEM>>>(p_xhi, p_xlo, p_whi, p_wlo, p_h, 128);
        csr_build_kernel<<<G, 256>>>(d_src, d_dst, nullptr, npg, p_rs, p_rc, p_cpack, p_dinv);
        agg_fused_kernel<<<dim3(4, G), 256, npg*64*4>>>(p_h, p_dinv, p_rs, p_rc,
                                                        p_cpack, gcn_b0, p_agg, npg);
    }
    {
        int npg = 256, k = 128, nNew = G * k;
        wnorm_kernel<<<1, 256>>>(pool_w0);
        score_kernel<<<(n * 32 + 255) / 256, 256>>>(p_agg, pool_w0, p_score, n);
        pool_kernel<<<G, npg>>>(p_score, npg, k, p_newid, p_perm);
        gather_split_kernel<<<(nNew * HF + 255) / 256, 256>>>(p_agg, p_score, p_perm,
                                                              p_x, p_xhi, p_xlo, nNew);
        remap_kernel<<<(E + 255) / 256, 256>>>(d_src, d_dst, nullptr, p_newid,
                                               p_es0, p_ed0, p_ew0, E);
        readout_kernel<<<G, 256>>>(p_x, k, p_ro, 0);
        n = nNew;                 // 32768
    }
    // ---------------- level 1 ----------------
    {
        int npg = 128;
        wsplit_kernel<<<256, 256>>>(gcn_w1, 256, p_whi, p_wlo);
        gemm_mma_kernel<<<dim3(n / 128, 2), 256, MMA_SMEM>>>(p_xhi, p_xlo, p_whi, p_wlo, p_h, 256);
        csr_build_kernel<<<G, 256>>>(p_es0, p_ed0, p_ew0, npg, p_rs, p_rc, p_cpack, p_dinv);
        agg_fused_kernel<<<dim3(4, G), 256, npg*64*4>>>(p_h, p_dinv, p_rs, p_rc,
                                                        p_cpack, gcn_b1, p_agg, npg);
    }
    {
        int npg = 128, k = 64, nNew = G * k;
        wnorm_kernel<<<1, 256>>>(pool_w1);
        score_kernel<<<(n * 32 + 255) / 256, 256>>>(p_agg, pool_w1, p_score, n);
        pool_kernel<<<G, npg>>>(p_score, npg, k, p_newid, p_perm);
        gather_split_kernel<<<(nNew * HF + 255) / 256, 256>>>(p_agg, p_score, p_perm,
                                                              p_x, p_xhi, p_xlo, nNew);
        remap_kernel<<<(E + 255) / 256, 256>>>(p_es0, p_ed0, p_ew0, p_newid,
                                               p_es1, p_ed1, p_ew1, E);
        readout_kernel<<<G, 256>>>(p_x, k, p_ro, 1);
        n = nNew;                 // 16384
    }
    // ---------------- level 2 ----------------
    {
        int npg = 64;
        wsplit_kernel<<<256, 256>>>(gcn_w2, 256, p_whi, p_wlo);
        gemm_mma_kernel<<<dim3(n / 128, 2), 256, MMA_SMEM>>>(p_xhi, p_xlo, p_whi, p_wlo, p_h, 256);
        csr_build_kernel<<<G, 256>>>(p_es1, p_ed1, p_ew1, npg, p_rs, p_rc, p_cpack, p_dinv);
        agg_fused_kernel<<<dim3(4, G), 256, npg*64*4>>>(p_h, p_dinv, p_rs, p_rc,
                                                        p_cpack, gcn_b2, p_agg, npg);
    }
    {
        int npg = 64, k = 32;
        wnorm_kernel<<<1, 256>>>(pool_w2);
        score_kernel<<<(n * 32 + 255) / 256, 256>>>(p_agg, pool_w2, p_score, n);
        pool_kernel<<<G, npg>>>(p_score, npg, k, p_newid, p_perm);
        gather_scale_kernel<<<(G * k * HF + 255) / 256, 256>>>(p_agg, p_score, p_perm, p_x, G * k);
        readout_kernel<<<G, 256>>>(p_x, k, p_ro, 1);
    }

    // ---------------- MLP head ----------------
    lin1_kernel<<<32, 256>>>(p_ro, lin1_w, lin1_b, p_h1);
    lin2_kernel<<<16, 128>>>(p_h1, lin2_w, lin2_b, p_h2);
    lin3_lsm_kernel<<<G, 32>>>(p_h2, lin3_w, lin3_b, out);
}

// round 12
// speedup vs baseline: 2.2190x; 1.0145x over previous
#include <cuda_runtime.h>
#include <cuda_fp16.h>
#include <math.h>
#include <stdint.h>

// Problem constants
#define G 256
#define N0 256
#define HF 256            // hidden feature dim
#define MAXN (G*N0)       // 65536
#define MAXE (G*2048)     // 524288
#define EPG 2048          // edges per graph (fixed slot count, masked edges have ew=0)

// -------- scratch (device globals; no allocation allowed) --------
__device__ float g_h[MAXN*HF];        // 64 MB : h = x @ W
__device__ float g_agg[MAXN*HF];      // 64 MB : conv output
__device__ float g_x[(MAXN/2)*HF];    // 32 MB : pooled features
__device__ float g_dinv[MAXN];
__device__ float g_score[MAXN];
__device__ int   g_newid[MAXN];
__device__ int   g_perm[MAXN/2];
__device__ int   g_esrc0[MAXE], g_edst0[MAXE];
__device__ float g_eew0[MAXE];
__device__ int   g_esrc1[MAXE], g_edst1[MAXE];
__device__ float g_eew1[MAXE];
__device__ int   g_rs[MAXN];
__device__ int   g_rc[MAXN];
__device__ int2  g_cpack[MAXE];       // CSR packed (src, norm-bits)
__device__ float g_ro[G*512];
__device__ float g_h1[G*256];
__device__ float g_h2[G*128];
__device__ float g_winv;
// X split buffers (fp16 hi/lo)
__device__ __half g_xhi[8388608];
__device__ __half g_xlo[8388608];
// W split buffers (fp16 hi/lo, [256 (N)] x [K] K-major), K<=256
__device__ __half g_whi[256*256];
__device__ __half g_wlo[256*256];

// ================= helpers =================
__device__ __forceinline__ uint32_t smem_u32(const void* p) {
    uint32_t a;
    asm("{ .reg .u64 t; cvta.to.shared.u64 t, %1; cvt.u32.u64 %0, t; }"
        : "=r"(a) : "l"(p));
    return a;
}
__device__ __forceinline__ void ldsm_x4(uint32_t* r, uint32_t addr) {
    asm volatile("ldmatrix.sync.aligned.m8n8.x4.shared.b16 {%0,%1,%2,%3}, [%4];"
        : "=r"(r[0]), "=r"(r[1]), "=r"(r[2]), "=r"(r[3]) : "r"(addr));
}
__device__ __forceinline__ void ldsm_x2(uint32_t* r, uint32_t addr) {
    asm volatile("ldmatrix.sync.aligned.m8n8.x2.shared.b16 {%0,%1}, [%2];"
        : "=r"(r[0]), "=r"(r[1]) : "r"(addr));
}
__device__ __forceinline__ void mma_f16(float* d, const uint32_t* a, const uint32_t* b) {
    asm volatile("mma.sync.aligned.m16n8k16.row.col.f32.f16.f16.f32 "
        "{%0,%1,%2,%3}, {%4,%5,%6,%7}, {%8,%9}, {%0,%1,%2,%3};"
        : "+f"(d[0]), "+f"(d[1]), "+f"(d[2]), "+f"(d[3])
        : "r"(a[0]), "r"(a[1]), "r"(a[2]), "r"(a[3]), "r"(b[0]), "r"(b[1]));
}
__device__ __forceinline__ void cp16(uint32_t saddr, const void* g) {
    asm volatile("cp.async.cg.shared.global [%0], [%1], 16;" :: "r"(saddr), "l"(g));
}
#define CP_COMMIT() asm volatile("cp.async.commit_group;" ::: "memory")
#define CP_WAIT0()  asm volatile("cp.async.wait_group 0;" ::: "memory")
#define CP_WAIT1()  asm volatile("cp.async.wait_group 1;" ::: "memory")

// ================= split pre-passes (fp16 2-way) =================
__global__ void xsplit_kernel(const float* __restrict__ X, int total,
                              __half* __restrict__ xhi, __half* __restrict__ xlo) {
    int i = blockIdx.x * 256 + threadIdx.x;
    if (i >= total) return;
    float v = X[i];
    __half h = __float2half_rn(v);
    __half l = __float2half_rn(v - __half2float(h));
    xhi[i] = h; xlo[i] = l;
}

__global__ void wsplit_kernel(const float* __restrict__ W, int K,
                              __half* __restrict__ whi, __half* __restrict__ wlo) {
    int idx = blockIdx.x * 256 + threadIdx.x;
    if (idx >= K * 256) return;
    int k = idx >> 8, n = idx & 255;
    float w = W[idx];
    __half h = __float2half_rn(w);
    __half l = __float2half_rn(w - __half2float(h));
    whi[n*K + k] = h; wlo[n*K + k] = l;
}

// ================= MMA GEMM: C[n,256] = X[n,K] @ W[K,256] =================
// near-fp32 via fp16 2-way split, 3 product segments (hh, hl, lh; ll ~2^-22 dropped).
// Double-buffered cp.async pipeline over K=16 chunks.
#define SEGB 6144                  // 128 rows * 48B stride (16 halves + pad)
#define CHUNKB (4*SEGB)            // one chunk: A hi, A lo, B hi, B lo
#define MMA_SMEM (2*CHUNKB)        // 49152

__global__ __launch_bounds__(256) void gemm_mma_kernel(
        const __half* __restrict__ Xhi, const __half* __restrict__ Xlo,
        const __half* __restrict__ Whi, const __half* __restrict__ Wlo,
        float* __restrict__ C, int K) {
    extern __shared__ __align__(16) char smem[];
    uint32_t sb = smem_u32(smem);
    int tid = threadIdx.x, w = tid >> 5, lane = tid & 31;
    int rowBase = blockIdx.x * 128, colBase = blockIdx.y * 128;
    int warpRow = (w >> 2) * 64, warpCol = (w & 3) * 32;

    float acc[4][4][4];
    #pragma unroll
    for (int i = 0; i < 4; i++)
        #pragma unroll
        for (int j = 0; j < 4; j++)
            #pragma unroll
            for (int d = 0; d < 4; d++) acc[i][j][d] = 0.f;

    int r  = tid >> 1;                 // 0..127
    int hf = tid & 1;                  // 16B half-row
    uint32_t stOff = (uint32_t)(r * 48 + hf * 16);

    int bl = lane & 15;
    uint32_t aFragOff = (uint32_t)((warpRow + (lane & 15)) * 48 + (lane >> 4) * 16);
    uint32_t bFragOff = (uint32_t)(2*SEGB + (warpCol + (bl & 7)) * 48 + (bl >> 3) * 16);

    const __half* arow = Xhi + (size_t)(rowBase + r) * K + hf * 8;
    const __half* alow = Xlo + (size_t)(rowBase + r) * K + hf * 8;
    const __half* brow = Whi + (size_t)(colBase + r) * K + hf * 8;
    const __half* blow = Wlo + (size_t)(colBase + r) * K + hf * 8;

    const int NC = K >> 4;
    // prefetch chunk 0
    {
        uint32_t base = sb + stOff;
        cp16(base,          arow);
        cp16(base + SEGB,   alow);
        cp16(base + 2*SEGB, brow);
        cp16(base + 3*SEGB, blow);
        CP_COMMIT();
    }

    for (int kb = 0; kb < NC; kb++) {
        if (kb + 1 < NC) {
            uint32_t base = sb + ((kb + 1) & 1) * CHUNKB + stOff;
            int ko = (kb + 1) * 16;
            cp16(base,          arow + ko);
            cp16(base + SEGB,   alow + ko);
            cp16(base + 2*SEGB, brow + ko);
            cp16(base + 3*SEGB, blow + ko);
            CP_COMMIT();
            CP_WAIT1();                 // chunk kb complete
        } else {
            CP_WAIT0();
        }
        __syncthreads();

        uint32_t bufbase = sb + (kb & 1) * CHUNKB;
        uint32_t bfr[2][4][2];
        #pragma unroll
        for (int s = 0; s < 2; s++)
            #pragma unroll
            for (int nt = 0; nt < 4; nt++)
                ldsm_x2(bfr[s][nt], bufbase + bFragOff + s*SEGB + nt*(8*48));

        #pragma unroll
        for (int mt = 0; mt < 4; mt++) {
            uint32_t afr[2][4];
            #pragma unroll
            for (int s = 0; s < 2; s++)
                ldsm_x4(afr[s], bufbase + aFragOff + s*SEGB + mt*(16*48));
            #pragma unroll
            for (int cb = 0; cb < 3; cb++) {        // hh, hl, lh
                int ai = (cb == 2) ? 1 : 0;
                int bi = (cb == 1) ? 1 : 0;
                #pragma unroll
                for (int nt = 0; nt < 4; nt++)
                    mma_f16(acc[mt][nt], afr[ai], bfr[bi][nt]);
            }
        }
        __syncthreads();
    }

    #pragma unroll
    for (int mt = 0; mt < 4; mt++) {
        int row = rowBase + warpRow + mt*16 + (lane >> 2);
        #pragma unroll
        for (int nt = 0; nt < 4; nt++) {
            int col = colBase + warpCol + nt*8 + (lane & 3)*2;
            *(float2*)&C[(size_t)row * 256 + col] =
                make_float2(acc[mt][nt][0], acc[mt][nt][1]);
            *(float2*)&C[(size_t)(row + 8) * 256 + col] =
                make_float2(acc[mt][nt][2], acc[mt][nt][3]);
        }
    }
}

// ---------------- per-graph CSR build (block = graph, 256 threads) ----------------
__global__ __launch_bounds__(256) void csr_build_kernel(
        const int* __restrict__ src, const int* __restrict__ dst,
        const float* __restrict__ ew, int npg,
        int* __restrict__ rs, int* __restrict__ rc,
        int2* __restrict__ cpack, float* __restrict__ dinv) {
    __shared__ float sdeg[256];
    __shared__ int   scnt[256];
    __shared__ int   sscan[256];
    __shared__ int   spos[256];
    int g = blockIdx.x, t = threadIdx.x;
    int nbase = g * npg, ebase = g * EPG;

    if (t < npg) { sdeg[t] = 1.0f; scnt[t] = 0; }
    __syncthreads();
    for (int e = t; e < EPG; e += 256) {
        float w = ew ? ew[ebase + e] : 1.0f;
        if (w != 0.f) {
            int d = dst[ebase + e] - nbase;
            atomicAdd(&sdeg[d], w);
            atomicAdd(&scnt[d], 1);
        }
    }
    __syncthreads();
    int v = (t < npg) ? scnt[t] : 0;
    sscan[t] = v;
    __syncthreads();
    #pragma unroll
    for (int off = 1; off < 256; off <<= 1) {
        int add = (t >= off) ? sscan[t - off] : 0;
        __syncthreads();
        sscan[t] += add;
        __syncthreads();
    }
    int start = sscan[t] - v;
    if (t < npg) {
        rs[nbase + t] = start;
        rc[nbase + t] = v;
        spos[t] = start;
        dinv[nbase + t] = 1.0f / sdeg[t];
    }
    __syncthreads();
    for (int e = t; e < EPG; e += 256) {
        float w = ew ? ew[ebase + e] : 1.0f;
        if (w != 0.f) {
            int s = src[ebase + e] - nbase;
            int d = dst[ebase + e] - nbase;
            float nm = rsqrtf(sdeg[s]) * rsqrtf(sdeg[d]) * w;
            int idx = atomicAdd(&spos[d], 1);
            cpack[ebase + idx] = make_int2(s, __float_as_int(nm));
        }
    }
}

// ---------------- fused aggregation + self-loop + bias + relu ----------------
// block = (fc in [0,4), graph g); stages h tile [npg][64] in smem
__global__ __launch_bounds__(256) void agg_fused_kernel(
        const float* __restrict__ h, const float* __restrict__ dinv,
        const int* __restrict__ rs, const int* __restrict__ rc,
        const int2* __restrict__ cpack, const float* __restrict__ bias,
        float* __restrict__ out, int npg) {
    extern __shared__ float ht[];   // npg * 64 floats
    int fc = blockIdx.x, g = blockIdx.y;
    int t = threadIdx.x;
    int nbase = g * npg, ebase = g * EPG;

    const float4* h4 = (const float4*)h;
    float4* ht4 = (float4*)ht;
    for (int i = t; i < npg * 16; i += 256) {
        int node = i >> 4, q = i & 15;
        ht4[i] = h4[(size_t)(nbase + node) * 64 + fc * 16 + q];
    }
    __syncthreads();

    int w = t >> 5, lane = t & 31;
    float b0 = __ldg(bias + fc*64 + lane*2);
    float b1 = __ldg(bias + fc*64 + lane*2 + 1);
    for (int d = w; d < npg; d += 8) {
        float dv = dinv[nbase + d];
        float a0 = ht[d*64 + lane*2]     * dv + b0;
        float a1 = ht[d*64 + lane*2 + 1] * dv + b1;
        int cnt = rc[nbase + d];
        const int2* cp = cpack + ebase + rs[nbase + d];
        int e = 0;
        for (; e + 4 <= cnt; e += 4) {
            int2 p0 = __ldg(cp + e);
            int2 p1 = __ldg(cp + e + 1);
            int2 p2 = __ldg(cp + e + 2);
            int2 p3 = __ldg(cp + e + 3);
            a0 += __int_as_float(p0.y) * ht[p0.x*64 + lane*2];
            a1 += __int_as_float(p0.y) * ht[p0.x*64 + lane*2 + 1];
            a0 += __int_as_float(p1.y) * ht[p1.x*64 + lane*2];
            a1 += __int_as_float(p1.y) * ht[p1.x*64 + lane*2 + 1];
            a0 += __int_as_float(p2.y) * ht[p2.x*64 + lane*2];
            a1 += __int_as_float(p2.y) * ht[p2.x*64 + lane*2 + 1];
            a0 += __int_as_float(p3.y) * ht[p3.x*64 + lane*2];
            a1 += __int_as_float(p3.y) * ht[p3.x*64 + lane*2 + 1];
        }
        for (; e < cnt; e++) {
            int2 p = __ldg(cp + e);
            a0 += __int_as_float(p.y) * ht[p.x*64 + lane*2];
            a1 += __int_as_float(p.y) * ht[p.x*64 + lane*2 + 1];
        }
        float2 o;
        o.x = fmaxf(a0, 0.f);
        o.y = fmaxf(a1, 0.f);
        *(float2*)(out + (size_t)(nbase + d) * 256 + fc*64 + lane*2) = o;
    }
}

// ---------------- pooling ----------------
__global__ void wnorm_kernel(const float* __restrict__ w) {
    __shared__ float red[256];
    int t = threadIdx.x;
    float v = w[t];
    red[t] = v * v;
    __syncthreads();
    for (int s = 128; s > 0; s >>= 1) {
        if (t < s) red[t] += red[t + s];
        __syncthreads();
    }
    if (t == 0) g_winv = rsqrtf(red[0]);
}

__global__ void score_kernel(const float* __restrict__ x, const float* __restrict__ w,
                             float* __restrict__ score, int n) {
    int gt = blockIdx.x * blockDim.x + threadIdx.x;
    int node = gt >> 5, lane = gt & 31;
    if (node >= n) return;
    const float* row = x + (size_t)node * HF;
    float s = 0.f;
    #pragma unroll
    for (int f = lane; f < HF; f += 32) s += row[f] * w[f];
    #pragma unroll
    for (int o = 16; o > 0; o >>= 1) s += __shfl_down_sync(0xFFFFFFFFu, s, o);
    if (lane == 0) score[node] = tanhf(s * g_winv);
}

__global__ void pool_kernel(const float* __restrict__ score, int npg, int k,
                            int* __restrict__ newid, int* __restrict__ perm) {
    __shared__ float s[256];
    int g = blockIdx.x, t = threadIdx.x;
    int node = g * npg + t;
    float my = score[node];
    s[t] = my;
    __syncthreads();
    int rank = 0;
    for (int j = 0; j < npg; j++) {
        float v = s[j];
        rank += (v > my) || (v == my && j < t);
    }
    if (rank < k) {
        newid[node] = g * k + rank;
        perm[g * k + rank] = node;
    } else {
        newid[node] = -1;
    }
}

// ---------------- gather*score + fp16 split for next GEMM ----------------
__global__ void gather_split_kernel(const float* __restrict__ x,
                                    const float* __restrict__ score,
                                    const int* __restrict__ perm,
                                    float* __restrict__ nx,
                                    __half* __restrict__ xhi,
                                    __half* __restrict__ xlo, int nNew) {
    int i = blockIdx.x * blockDim.x + threadIdx.x;
    if (i >= nNew * HF) return;
    int nn = i >> 8, f = i & 255;
    int old = perm[nn];
    float v = x[(size_t)old * HF + f] * score[old];
    nx[i] = v;
    __half h = __float2half_rn(v);
    xhi[i] = h;
    xlo[i] = __float2half_rn(v - __half2float(h));
}

__global__ void gather_scale_kernel(const float* __restrict__ x,
                                    const float* __restrict__ score,
                                    const int* __restrict__ perm,
                                    float* __restrict__ nx, int nNew) {
    int i = blockIdx.x * blockDim.x + threadIdx.x;
    if (i >= nNew * HF) return;
    int nn = i >> 8, f = i & 255;
    int old = perm[nn];
    nx[i] = x[(size_t)old * HF + f] * score[old];
}

__global__ void remap_kernel(const int* __restrict__ src, const int* __restrict__ dst,
                             const float* __restrict__ ew, const int* __restrict__ newid,
                             int* __restrict__ nsrc, int* __restrict__ ndst,
                             float* __restrict__ new_ew, int E) {
    int e = blockIdx.x * blockDim.x + threadIdx.x;
    if (e >= E) return;
    int s = newid[src[e]], d = newid[dst[e]];
    float w = ew ? ew[e] : 1.0f;
    bool valid = (s >= 0) && (d >= 0);
    nsrc[e]   = valid ? s : 0;
    ndst[e]   = valid ? d : 0;
    new_ew[e] = valid ? w : 0.f;
}

// ---------------- readout: [max | mean] per graph ----------------
__global__ void readout_kernel(const float* __restrict__ x, int k,
                               float* __restrict__ ro, int accumulate) {
    int g = blockIdx.x, f = threadIdx.x;
    const float* base = x + (size_t)g * k * HF + f;
    float mx = -3.4e38f, sum = 0.f;
    for (int j = 0; j < k; j++) {
        float v = base[(size_t)j * HF];
        mx = fmaxf(mx, v);
        sum += v;
    }
    float mean = sum / (float)k;
    if (accumulate) {
        ro[g*512 + f]       += mx;
        ro[g*512 + 256 + f] += mean;
    } else {
        ro[g*512 + f]       = mx;
        ro[g*512 + 256 + f] = mean;
    }
}

// ---------------- MLP (multi-graph blocks to amortize weight reads) ------------
__global__ __launch_bounds__(256) void lin1_kernel(const float* __restrict__ in,
        const float* __restrict__ W, const float* __restrict__ b,
        float* __restrict__ out) {
    int gb = blockIdx.x * 8, c = threadIdx.x;
    __shared__ float rows[8 * 512];
    for (int i = c; i < 8 * 512; i += 256) rows[i] = in[gb * 512 + i];
    __syncthreads();
    float acc[8];
    float bc = b[c];
    #pragma unroll
    for (int gg = 0; gg < 8; gg++) acc[gg] = bc;
    for (int kk = 0; kk < 512; kk++) {
        float wv = W[kk * 256 + c];
        #pragma unroll
        for (int gg = 0; gg < 8; gg++) acc[gg] += rows[gg * 512 + kk] * wv;
    }
    #pragma unroll
    for (int gg = 0; gg < 8; gg++)
        out[(gb + gg) * 256 + c] = fmaxf(acc[gg], 0.f);
}
__global__ __launch_bounds__(128) void lin2_kernel(const float* __restrict__ in,
        const float* __restrict__ W, const float* __restrict__ b,
        float* __restrict__ out) {
    int gb = blockIdx.x * 16, c = threadIdx.x;
    __shared__ float rows[16 * 256];
    for (int i = c; i < 16 * 256; i += 128) rows[i] = in[gb * 256 + i];
    __syncthreads();
    float acc[16];
    float bc = b[c];
    #pragma unroll
    for (int gg = 0; gg < 16; gg++) acc[gg] = bc;
    for (int kk = 0; kk < 256; kk++) {
        float wv = W[kk * 128 + c];
        #pragma unroll
        for (int gg = 0; gg < 16; gg++) acc[gg] += rows[gg * 256 + kk] * wv;
    }
    #pragma unroll
    for (int gg = 0; gg < 16; gg++)
        out[(gb + gg) * 128 + c] = fmaxf(acc[gg], 0.f);
}
__global__ void lin3_lsm_kernel(const float* __restrict__ in, const float* __restrict__ W,
                                const float* __restrict__ b, float* __restrict__ out) {
    int g = blockIdx.x, lane = threadIdx.x;
    const float* row = in + g*128;
    float a0 = 0.f, a1 = 0.f;
    #pragma unroll
    for (int kk = lane; kk < 128; kk += 32) {
        float v = row[kk];
        a0 += v * W[kk*2 + 0];
        a1 += v * W[kk*2 + 1];
    }
    #pragma unroll
    for (int o = 16; o > 0; o >>= 1) {
        a0 += __shfl_down_sync(0xFFFFFFFFu, a0, o);
        a1 += __shfl_down_sync(0xFFFFFFFFu, a1, o);
    }
    if (lane == 0) {
        float l0 = a0 + b[0], l1 = a1 + b[1];
        float m = fmaxf(l0, l1);
        float lse = m + logf(expf(l0 - m) + expf(l1 - m));
        out[g*2 + 0] = l0 - lse;
        out[g*2 + 1] = l1 - lse;
    }
}

// ---------------- host driver ----------------
extern "C" void kernel_launch(void* const* d_in, const int* in_sizes, int n_in,
                              void* d_out, int out_size) {
    const float* d_x      = (const float*)d_in[0];
    const int*   d_ei     = (const int*)d_in[1];
    const float* gcn_w0   = (const float*)d_in[3];
    const float* gcn_b0   = (const float*)d_in[4];
    const float* gcn_w1   = (const float*)d_in[5];
    const float* gcn_b1   = (const float*)d_in[6];
    const float* gcn_w2   = (const float*)d_in[7];
    const float* gcn_b2   = (const float*)d_in[8];
    const float* pool_w0  = (const float*)d_in[9];
    const float* pool_w1  = (const float*)d_in[10];
    const float* pool_w2  = (const float*)d_in[11];
    const float* lin1_w   = (const float*)d_in[12];
    const float* lin1_b   = (const float*)d_in[13];
    const float* lin2_w   = (const float*)d_in[14];
    const float* lin2_b   = (const float*)d_in[15];
    const float* lin3_w   = (const float*)d_in[16];
    const float* lin3_b   = (const float*)d_in[17];
    float* out = (float*)d_out;

    const int E = in_sizes[1] / 2;
    const int* d_src = d_ei;
    const int* d_dst = d_ei + E;

    float *p_h, *p_agg, *p_x, *p_dinv, *p_score, *p_ro, *p_h1, *p_h2;
    int *p_newid, *p_perm, *p_es0, *p_ed0, *p_es1, *p_ed1, *p_rs, *p_rc;
    int2 *p_cpack;
    float *p_ew0, *p_ew1;
    __half *p_xhi, *p_xlo, *p_whi, *p_wlo;
    cudaGetSymbolAddress((void**)&p_h,    g_h);
    cudaGetSymbolAddress((void**)&p_agg,  g_agg);
    cudaGetSymbolAddress((void**)&p_x,    g_x);
    cudaGetSymbolAddress((void**)&p_dinv, g_dinv);
    cudaGetSymbolAddress((void**)&p_score,g_score);
    cudaGetSymbolAddress((void**)&p_newid,g_newid);
    cudaGetSymbolAddress((void**)&p_perm, g_perm);
    cudaGetSymbolAddress((void**)&p_es0,  g_esrc0);
    cudaGetSymbolAddress((void**)&p_ed0,  g_edst0);
    cudaGetSymbolAddress((void**)&p_ew0,  g_eew0);
    cudaGetSymbolAddress((void**)&p_es1,  g_esrc1);
    cudaGetSymbolAddress((void**)&p_ed1,  g_edst1);
    cudaGetSymbolAddress((void**)&p_ew1,  g_eew1);
    cudaGetSymbolAddress((void**)&p_rs,   g_rs);
    cudaGetSymbolAddress((void**)&p_rc,   g_rc);
    cudaGetSymbolAddress((void**)&p_cpack,g_cpack);
    cudaGetSymbolAddress((void**)&p_ro,   g_ro);
    cudaGetSymbolAddress((void**)&p_h1,   g_h1);
    cudaGetSymbolAddress((void**)&p_h2,   g_h2);
    cudaGetSymbolAddress((void**)&p_xhi,  g_xhi);
    cudaGetSymbolAddress((void**)&p_xlo,  g_xlo);
    cudaGetSymbolAddress((void**)&p_whi,  g_whi);
    cudaGetSymbolAddress((void**)&p_wlo,  g_wlo);

    cudaFuncSetAttribute(agg_fused_kernel,
                         cudaFuncAttributeMaxDynamicSharedMemorySize, 65536);
    cudaFuncSetAttribute(gemm_mma_kernel,
                         cudaFuncAttributeMaxDynamicSharedMemorySize, MMA_SMEM);

    // ---------------- level 0 ----------------
    int n = MAXN;
    {
        int npg = 256;
        wsplit_kernel<<<128, 256>>>(gcn_w0, 128, p_whi, p_wlo);
        xsplit_kernel<<<(n * 128 + 255) / 256, 256>>>(d_x, n * 128, p_xhi, p_xlo);
        gemm_mma_kernel<<<dim3(n / 128, 2), 256, MMA_SMEM>>>(p_xhi, p_xlo, p_whi, p_wlo, p_h, 128);
        csr_build_kernel<<<G, 256>>>(d_src, d_dst, nullptr, npg, p_rs, p_rc, p_cpack, p_dinv);
        agg_fused_kernel<<<dim3(4, G), 256, npg*64*4>>>(p_h, p_dinv, p_rs, p_rc,
                                                        p_cpack, gcn_b0, p_agg, npg);
    }
    {
        int npg = 256, k = 128, nNew = G * k;
        wnorm_kernel<<<1, 256>>>(pool_w0);
        score_kernel<<<(n * 32 + 255) / 256, 256>>>(p_agg, pool_w0, p_score, n);
        pool_kernel<<<G, npg>>>(p_score, npg, k, p_newid, p_perm);
        gather_split_kernel<<<(nNew * HF + 255) / 256, 256>>>(p_agg, p_score, p_perm,
                                                              p_x, p_xhi, p_xlo, nNew);
        remap_kernel<<<(E + 255) / 256, 256>>>(d_src, d_dst, nullptr, p_newid,
                                               p_es0, p_ed0, p_ew0, E);
        readout_kernel<<<G, 256>>>(p_x, k, p_ro, 0);
        n = nNew;                 // 32768
    }
    // ---------------- level 1 ----------------
    {
        int npg = 128;
        wsplit_kernel<<<256, 256>>>(gcn_w1, 256, p_whi, p_wlo);
        gemm_mma_kernel<<<dim3(n / 128, 2), 256, MMA_SMEM>>>(p_xhi, p_xlo, p_whi, p_wlo, p_h, 256);
        csr_build_kernel<<<G, 256>>>(p_es0, p_ed0, p_ew0, npg, p_rs, p_rc, p_cpack, p_dinv);
        agg_fused_kernel<<<dim3(4, G), 256, npg*64*4>>>(p_h, p_dinv, p_rs, p_rc,
                                                        p_cpack, gcn_b1, p_agg, npg);
    }
    {
        int npg = 128, k = 64, nNew = G * k;
        wnorm_kernel<<<1, 256>>>(pool_w1);
        score_kernel<<<(n * 32 + 255) / 256, 256>>>(p_agg, pool_w1, p_score, n);
        pool_kernel<<<G, npg>>>(p_score, npg, k, p_newid, p_perm);
        gather_split_kernel<<<(nNew * HF + 255) / 256, 256>>>(p_agg, p_score, p_perm,
                                                              p_x, p_xhi, p_xlo, nNew);
        remap_kernel<<<(E + 255) / 256, 256>>>(p_es0, p_ed0, p_ew0, p_newid,
                                               p_es1, p_ed1, p_ew1, E);
        readout_kernel<<<G, 256>>>(p_x, k, p_ro, 1);
        n = nNew;                 // 16384
    }
    // ---------------- level 2 ----------------
    {
        int npg = 64;
        wsplit_kernel<<<256, 256>>>(gcn_w2, 256, p_whi, p_wlo);
        gemm_mma_kernel<<<dim3(n / 128, 2), 256, MMA_SMEM>>>(p_xhi, p_xlo, p_whi, p_wlo, p_h, 256);
        csr_build_kernel<<<G, 256>>>(p_es1, p_ed1, p_ew1, npg, p_rs, p_rc, p_cpack, p_dinv);
        agg_fused_kernel<<<dim3(4, G), 256, npg*64*4>>>(p_h, p_dinv, p_rs, p_rc,
                                                        p_cpack, gcn_b2, p_agg, npg);
    }
    {
        int npg = 64, k = 32;
        wnorm_kernel<<<1, 256>>>(pool_w2);
        score_kernel<<<(n * 32 + 255) / 256, 256>>>(p_agg, pool_w2, p_score, n);
        pool_kernel<<<G, npg>>>(p_score, npg, k, p_newid, p_perm);
        gather_scale_kernel<<<(G * k * HF + 255) / 256, 256>>>(p_agg, p_score, p_perm, p_x, G * k);
        readout_kernel<<<G, 256>>>(p_x, k, p_ro, 1);
    }

    // ---------------- MLP head ----------------
    lin1_kernel<<<32, 256>>>(p_ro, lin1_w, lin1_b, p_h1);
    lin2_kernel<<<16, 128>>>(p_h1, lin2_w, lin2_b, p_h2);
    lin3_lsm_kernel<<<G, 32>>>(p_h2, lin3_w, lin3_b, out);
}

// round 14
// speedup vs baseline: 2.3185x; 1.0448x over previous
#include <cuda_runtime.h>
#include <cuda_fp16.h>
#include <math.h>
#include <stdint.h>

// Problem constants
#define G 256
#define N0 256
#define HF 256            // hidden feature dim
#define MAXN (G*N0)       // 65536
#define MAXE (G*2048)     // 524288
#define EPG 2048          // edges per graph (fixed slot count, masked edges have ew=0)

// -------- scratch (device globals; no allocation allowed) --------
__device__ float g_h[MAXN*HF];        // 64 MB : h = x @ W
__device__ float g_agg[MAXN*HF];      // 64 MB : conv output
__device__ float g_x[(MAXN/2)*HF];    // 32 MB : pooled features
__device__ float g_dinv[MAXN];
__device__ float g_score[MAXN];
__device__ int   g_newid[MAXN];
__device__ int   g_perm[MAXN/2];
__device__ int   g_esrc0[MAXE], g_edst0[MAXE];
__device__ float g_eew0[MAXE];
__device__ int   g_esrc1[MAXE], g_edst1[MAXE];
__device__ float g_eew1[MAXE];
__device__ int   g_rs[MAXN];
__device__ int   g_rc[MAXN];
__device__ int2  g_cpack[MAXE];       // CSR packed (src, norm-bits)
__device__ float g_ro[G*512];
__device__ float g_h1[G*256];
__device__ float g_h2[G*128];
// X split buffers (fp16 hi/lo)
__device__ __half g_xhi[8388608];
__device__ __half g_xlo[8388608];
// W split buffers (fp16 hi/lo, [256 (N)] x [K] K-major), K<=256
__device__ __half g_whi[256*256];
__device__ __half g_wlo[256*256];

// ================= helpers =================
__device__ __forceinline__ uint32_t smem_u32(const void* p) {
    uint32_t a;
    asm("{ .reg .u64 t; cvta.to.shared.u64 t, %1; cvt.u32.u64 %0, t; }"
        : "=r"(a) : "l"(p));
    return a;
}
__device__ __forceinline__ void ldsm_x4(uint32_t* r, uint32_t addr) {
    asm volatile("ldmatrix.sync.aligned.m8n8.x4.shared.b16 {%0,%1,%2,%3}, [%4];"
        : "=r"(r[0]), "=r"(r[1]), "=r"(r[2]), "=r"(r[3]) : "r"(addr));
}
__device__ __forceinline__ void ldsm_x2(uint32_t* r, uint32_t addr) {
    asm volatile("ldmatrix.sync.aligned.m8n8.x2.shared.b16 {%0,%1}, [%2];"
        : "=r"(r[0]), "=r"(r[1]) : "r"(addr));
}
__device__ __forceinline__ void mma_f16(float* d, const uint32_t* a, const uint32_t* b) {
    asm volatile("mma.sync.aligned.m16n8k16.row.col.f32.f16.f16.f32 "
        "{%0,%1,%2,%3}, {%4,%5,%6,%7}, {%8,%9}, {%0,%1,%2,%3};"
        : "+f"(d[0]), "+f"(d[1]), "+f"(d[2]), "+f"(d[3])
        : "r"(a[0]), "r"(a[1]), "r"(a[2]), "r"(a[3]), "r"(b[0]), "r"(b[1]));
}
__device__ __forceinline__ void cp16(uint32_t saddr, const void* g) {
    asm volatile("cp.async.cg.shared.global [%0], [%1], 16;" :: "r"(saddr), "l"(g));
}
#define CP_COMMIT() asm volatile("cp.async.commit_group;" ::: "memory")
#define CP_WAIT0()  asm volatile("cp.async.wait_group 0;" ::: "memory")
#define CP_WAIT1()  asm volatile("cp.async.wait_group 1;" ::: "memory")

// ================= split pre-passes (fp16 2-way) =================
__global__ void xsplit_kernel(const float* __restrict__ X, int total,
                              __half* __restrict__ xhi, __half* __restrict__ xlo) {
    int i = blockIdx.x * 256 + threadIdx.x;
    if (i >= total) return;
    float v = X[i];
    __half h = __float2half_rn(v);
    __half l = __float2half_rn(v - __half2float(h));
    xhi[i] = h; xlo[i] = l;
}

__global__ void wsplit_kernel(const float* __restrict__ W, int K,
                              __half* __restrict__ whi, __half* __restrict__ wlo) {
    int idx = blockIdx.x * 256 + threadIdx.x;
    if (idx >= K * 256) return;
    int k = idx >> 8, n = idx & 255;
    float w = W[idx];
    __half h = __float2half_rn(w);
    __half l = __float2half_rn(w - __half2float(h));
    whi[n*K + k] = h; wlo[n*K + k] = l;
}

// ================= MMA GEMM: C[n,256] = X[n,K] @ W[K,256] =================
// near-fp32 via fp16 2-way split, 3 product segments (hh, hl, lh; ll ~2^-22 dropped).
// Double-buffered cp.async pipeline over K=16 chunks.
#define SEGB 6144                  // 128 rows * 48B stride (16 halves + pad)
#define CHUNKB (4*SEGB)            // one chunk: A hi, A lo, B hi, B lo
#define MMA_SMEM (2*CHUNKB)        // 49152

__global__ __launch_bounds__(256) void gemm_mma_kernel(
        const __half* __restrict__ Xhi, const __half* __restrict__ Xlo,
        const __half* __restrict__ Whi, const __half* __restrict__ Wlo,
        float* __restrict__ C, int K) {
    extern __shared__ __align__(16) char smem[];
    uint32_t sb = smem_u32(smem);
    int tid = threadIdx.x, w = tid >> 5, lane = tid & 31;
    int rowBase = blockIdx.x * 128, colBase = blockIdx.y * 128;
    int warpRow = (w >> 2) * 64, warpCol = (w & 3) * 32;

    float acc[4][4][4];
    #pragma unroll
    for (int i = 0; i < 4; i++)
        #pragma unroll
        for (int j = 0; j < 4; j++)
            #pragma unroll
            for (int d = 0; d < 4; d++) acc[i][j][d] = 0.f;

    int r  = tid >> 1;                 // 0..127
    int hf = tid & 1;                  // 16B half-row
    uint32_t stOff = (uint32_t)(r * 48 + hf * 16);

    int bl = lane & 15;
    uint32_t aFragOff = (uint32_t)((warpRow + (lane & 15)) * 48 + (lane >> 4) * 16);
    uint32_t bFragOff = (uint32_t)(2*SEGB + (warpCol + (bl & 7)) * 48 + (bl >> 3) * 16);

    const __half* arow = Xhi + (size_t)(rowBase + r) * K + hf * 8;
    const __half* alow = Xlo + (size_t)(rowBase + r) * K + hf * 8;
    const __half* brow = Whi + (size_t)(colBase + r) * K + hf * 8;
    const __half* blow = Wlo + (size_t)(colBase + r) * K + hf * 8;

    const int NC = K >> 4;
    // prefetch chunk 0
    {
        uint32_t base = sb + stOff;
        cp16(base,          arow);
        cp16(base + SEGB,   alow);
        cp16(base + 2*SEGB, brow);
        cp16(base + 3*SEGB, blow);
        CP_COMMIT();
    }

    for (int kb = 0; kb < NC; kb++) {
        if (kb + 1 < NC) {
            uint32_t base = sb + ((kb + 1) & 1) * CHUNKB + stOff;
            int ko = (kb + 1) * 16;
            cp16(base,          arow + ko);
            cp16(base + SEGB,   alow + ko);
            cp16(base + 2*SEGB, brow + ko);
            cp16(base + 3*SEGB, blow + ko);
            CP_COMMIT();
            CP_WAIT1();                 // chunk kb complete
        } else {
            CP_WAIT0();
        }
        __syncthreads();

        uint32_t bufbase = sb + (kb & 1) * CHUNKB;
        uint32_t bfr[2][4][2];
        #pragma unroll
        for (int s = 0; s < 2; s++)
            #pragma unroll
            for (int nt = 0; nt < 4; nt++)
                ldsm_x2(bfr[s][nt], bufbase + bFragOff + s*SEGB + nt*(8*48));

        #pragma unroll
        for (int mt = 0; mt < 4; mt++) {
            uint32_t afr[2][4];
            #pragma unroll
            for (int s = 0; s < 2; s++)
                ldsm_x4(afr[s], bufbase + aFragOff + s*SEGB + mt*(16*48));
            #pragma unroll
            for (int cb = 0; cb < 3; cb++) {        // hh, hl, lh
                int ai = (cb == 2) ? 1 : 0;
                int bi = (cb == 1) ? 1 : 0;
                #pragma unroll
                for (int nt = 0; nt < 4; nt++)
                    mma_f16(acc[mt][nt], afr[ai], bfr[bi][nt]);
            }
        }
        __syncthreads();
    }

    #pragma unroll
    for (int mt = 0; mt < 4; mt++) {
        int row = rowBase + warpRow + mt*16 + (lane >> 2);
        #pragma unroll
        for (int nt = 0; nt < 4; nt++) {
            int col = colBase + warpCol + nt*8 + (lane & 3)*2;
            *(float2*)&C[(size_t)row * 256 + col] =
                make_float2(acc[mt][nt][0], acc[mt][nt][1]);
            *(float2*)&C[(size_t)(row + 8) * 256 + col] =
                make_float2(acc[mt][nt][2], acc[mt][nt][3]);
        }
    }
}

// ---------------- per-graph CSR build (block = graph, 256 threads) ----------------
__global__ __launch_bounds__(256) void csr_build_kernel(
        const int* __restrict__ src, const int* __restrict__ dst,
        const float* __restrict__ ew, int npg,
        int* __restrict__ rs, int* __restrict__ rc,
        int2* __restrict__ cpack, float* __restrict__ dinv) {
    __shared__ float sdeg[256];
    __shared__ int   scnt[256];
    __shared__ int   sscan[256];
    __shared__ int   spos[256];
    int g = blockIdx.x, t = threadIdx.x;
    int nbase = g * npg, ebase = g * EPG;

    if (t < npg) { sdeg[t] = 1.0f; scnt[t] = 0; }
    __syncthreads();
    for (int e = t; e < EPG; e += 256) {
        float w = ew ? ew[ebase + e] : 1.0f;
        if (w != 0.f) {
            int d = dst[ebase + e] - nbase;
            atomicAdd(&sdeg[d], w);
            atomicAdd(&scnt[d], 1);
        }
    }
    __syncthreads();
    int v = (t < npg) ? scnt[t] : 0;
    sscan[t] = v;
    __syncthreads();
    #pragma unroll
    for (int off = 1; off < 256; off <<= 1) {
        int add = (t >= off) ? sscan[t - off] : 0;
        __syncthreads();
        sscan[t] += add;
        __syncthreads();
    }
    int start = sscan[t] - v;
    if (t < npg) {
        rs[nbase + t] = start;
        rc[nbase + t] = v;
        spos[t] = start;
        dinv[nbase + t] = 1.0f / sdeg[t];
    }
    __syncthreads();
    for (int e = t; e < EPG; e += 256) {
        float w = ew ? ew[ebase + e] : 1.0f;
        if (w != 0.f) {
            int s = src[ebase + e] - nbase;
            int d = dst[ebase + e] - nbase;
            float nm = rsqrtf(sdeg[s]) * rsqrtf(sdeg[d]) * w;
            int idx = atomicAdd(&spos[d], 1);
            cpack[ebase + idx] = make_int2(s, __float_as_int(nm));
        }
    }
}

// ---------------- fused aggregation + self-loop + bias + relu ----------------
// block = (fc in [0,4), graph g); stages h tile [npg][64] floats; 2 dsts per warp
__global__ __launch_bounds__(256) void agg_fused_kernel(
        const float* __restrict__ h, const float* __restrict__ dinv,
        const int* __restrict__ rs, const int* __restrict__ rc,
        const int2* __restrict__ cpack, const float* __restrict__ bias,
        float* __restrict__ out, int npg) {
    extern __shared__ float ht[];   // npg * 64 floats
    int fc = blockIdx.x, g = blockIdx.y;
    int t = threadIdx.x;
    int nbase = g * npg, ebase = g * EPG;

    const float4* h4 = (const float4*)h;
    float4* ht4 = (float4*)ht;
    for (int i = t; i < npg * 16; i += 256) {
        int node = i >> 4, q = i & 15;
        ht4[i] = h4[(size_t)(nbase + node) * 64 + fc * 16 + q];
    }
    __syncthreads();

    int w = t >> 5, lane = t & 31;
    float b0 = __ldg(bias + fc*64 + lane*2);
    float b1 = __ldg(bias + fc*64 + lane*2 + 1);
    const float2* ht2 = (const float2*)ht;

    for (int d0 = w * 2; d0 < npg; d0 += 16) {
        int d1 = d0 + 1;
        float2 v0 = ht2[d0*32 + lane];
        float2 v1 = ht2[d1*32 + lane];
        float dv0 = dinv[nbase + d0], dv1 = dinv[nbase + d1];
        float a00 = v0.x * dv0 + b0, a01 = v0.y * dv0 + b1;
        float a10 = v1.x * dv1 + b0, a11 = v1.y * dv1 + b1;
        int c0 = rc[nbase + d0], c1 = rc[nbase + d1];
        const int2* cp0 = cpack + ebase + rs[nbase + d0];
        const int2* cp1 = cpack + ebase + rs[nbase + d1];
        int e0 = 0, e1 = 0;
        while (e0 + 2 <= c0 && e1 + 2 <= c1) {
            int2 pa = __ldg(cp0 + e0), pb = __ldg(cp0 + e0 + 1);
            int2 pc = __ldg(cp1 + e1), pd = __ldg(cp1 + e1 + 1);
            float2 xa = ht2[pa.x*32 + lane]; float na = __int_as_float(pa.y);
            float2 xb = ht2[pb.x*32 + lane]; float nb = __int_as_float(pb.y);
            float2 xc = ht2[pc.x*32 + lane]; float nc = __int_as_float(pc.y);
            float2 xd = ht2[pd.x*32 + lane]; float nd = __int_as_float(pd.y);
            a00 += na * xa.x; a01 += na * xa.y;
            a00 += nb * xb.x; a01 += nb * xb.y;
            a10 += nc * xc.x; a11 += nc * xc.y;
            a10 += nd * xd.x; a11 += nd * xd.y;
            e0 += 2; e1 += 2;
        }
        for (; e0 < c0; e0++) {
            int2 p = __ldg(cp0 + e0);
            float2 x = ht2[p.x*32 + lane]; float nm = __int_as_float(p.y);
            a00 += nm * x.x; a01 += nm * x.y;
        }
        for (; e1 < c1; e1++) {
            int2 p = __ldg(cp1 + e1);
            float2 x = ht2[p.x*32 + lane]; float nm = __int_as_float(p.y);
            a10 += nm * x.x; a11 += nm * x.y;
        }
        *(float2*)(out + (size_t)(nbase + d0) * 256 + fc*64 + lane*2) =
            make_float2(fmaxf(a00, 0.f), fmaxf(a01, 0.f));
        *(float2*)(out + (size_t)(nbase + d1) * 256 + fc*64 + lane*2) =
            make_float2(fmaxf(a10, 0.f), fmaxf(a11, 0.f));
    }
}

// ---------------- pooling ----------------
__global__ void score_kernel(const float* __restrict__ x, const float* __restrict__ w,
                             float* __restrict__ score, int n) {
    int gt = blockIdx.x * blockDim.x + threadIdx.x;
    int node = gt >> 5, lane = gt & 31;
    if (node >= n) return;
    // inline ||w||: each lane sums 8 strided elements, then the same shfl tree
    float ss = 0.f;
    #pragma unroll
    for (int f = lane; f < HF; f += 32) { float v = __ldg(w + f); ss += v * v; }
    const float* row = x + (size_t)node * HF;
    float s = 0.f;
    #pragma unroll
    for (int f = lane; f < HF; f += 32) s += row[f] * __ldg(w + f);
    #pragma unroll
    for (int o = 16; o > 0; o >>= 1) {
        s  += __shfl_down_sync(0xFFFFFFFFu, s, o);
        ss += __shfl_down_sync(0xFFFFFFFFu, ss, o);
    }
    if (lane == 0) score[node] = tanhf(s * rsqrtf(ss));
}

__global__ void pool_kernel(const float* __restrict__ score, int npg, int k,
                            int* __restrict__ newid, int* __restrict__ perm) {
    __shared__ float s[256];
    int g = blockIdx.x, t = threadIdx.x;
    int node = g * npg + t;
    float my = score[node];
    s[t] = my;
    __syncthreads();
    int rank = 0;
    for (int j = 0; j < npg; j++) {
        float v = s[j];
        rank += (v > my) || (v == my && j < t);
    }
    if (rank < k) {
        newid[node] = g * k + rank;
        perm[g * k + rank] = node;
    } else {
        newid[node] = -1;
    }
}

// ---------------- gather*score + fp16 split for next GEMM ----------------
__global__ void gather_split_kernel(const float* __restrict__ x,
                                    const float* __restrict__ score,
                                    const int* __restrict__ perm,
                                    float* __restrict__ nx,
                                    __half* __restrict__ xhi,
                                    __half* __restrict__ xlo, int nNew) {
    int i = blockIdx.x * blockDim.x + threadIdx.x;
    if (i >= nNew * HF) return;
    int nn = i >> 8, f = i & 255;
    int old = perm[nn];
    float v = x[(size_t)old * HF + f] * score[old];
    nx[i] = v;
    __half h = __float2half_rn(v);
    xhi[i] = h;
    xlo[i] = __float2half_rn(v - __half2float(h));
}

__global__ void gather_scale_kernel(const float* __restrict__ x,
                                    const float* __restrict__ score,
                                    const int* __restrict__ perm,
                                    float* __restrict__ nx, int nNew) {
    int i = blockIdx.x * blockDim.x + threadIdx.x;
    if (i >= nNew * HF) return;
    int nn = i >> 8, f = i & 255;
    int old = perm[nn];
    nx[i] = x[(size_t)old * HF + f] * score[old];
}

__global__ void remap_kernel(const int* __restrict__ src, const int* __restrict__ dst,
                             const float* __restrict__ ew, const int* __restrict__ newid,
                             int* __restrict__ nsrc, int* __restrict__ ndst,
                             float* __restrict__ new_ew, int E) {
    int e = blockIdx.x * blockDim.x + threadIdx.x;
    if (e >= E) return;
    int s = newid[src[e]], d = newid[dst[e]];
    float w = ew ? ew[e] : 1.0f;
    bool valid = (s >= 0) && (d >= 0);
    nsrc[e]   = valid ? s : 0;
    ndst[e]   = valid ? d : 0;
    new_ew[e] = valid ? w : 0.f;
}

// ---------------- readout: [max | mean] per graph ----------------
__global__ void readout_kernel(const float* __restrict__ x, int k,
                               float* __restrict__ ro, int accumulate) {
    int g = blockIdx.x, f = threadIdx.x;
    const float* base = x + (size_t)g * k * HF + f;
    float mx = -3.4e38f, sum = 0.f;
    for (int j = 0; j < k; j++) {
        float v = base[(size_t)j * HF];
        mx = fmaxf(mx, v);
        sum += v;
    }
    float mean = sum / (float)k;
    if (accumulate) {
        ro[g*512 + f]       += mx;
        ro[g*512 + 256 + f] += mean;
    } else {
        ro[g*512 + f]       = mx;
        ro[g*512 + 256 + f] = mean;
    }
}

// ---------------- MLP (multi-graph blocks to amortize weight reads) ------------
__global__ __launch_bounds__(256) void lin1_kernel(const float* __restrict__ in,
        const float* __restrict__ W, const float* __restrict__ b,
        float* __restrict__ out) {
    int gb = blockIdx.x * 8, c = threadIdx.x;
    __shared__ float rows[8 * 512];
    for (int i = c; i < 8 * 512; i += 256) rows[i] = in[gb * 512 + i];
    __syncthreads();
    float acc[8];
    float bc = b[c];
    #pragma unroll
    for (int gg = 0; gg < 8; gg++) acc[gg] = bc;
    for (int kk = 0; kk < 512; kk++) {
        float wv = W[kk * 256 + c];
        #pragma unroll
        for (int gg = 0; gg < 8; gg++) acc[gg] += rows[gg * 512 + kk] * wv;
    }
    #pragma unroll
    for (int gg = 0; gg < 8; gg++)
        out[(gb + gg) * 256 + c] = fmaxf(acc[gg], 0.f);
}
__global__ __launch_bounds__(128) void lin2_kernel(const float* __restrict__ in,
        const float* __restrict__ W, const float* __restrict__ b,
        float* __restrict__ out) {
    int gb = blockIdx.x * 16, c = threadIdx.x;
    __shared__ float rows[16 * 256];
    for (int i = c; i < 16 * 256; i += 128) rows[i] = in[gb * 256 + i];
    __syncthreads();
    float acc[16];
    float bc = b[c];
    #pragma unroll
    for (int gg = 0; gg < 16; gg++) acc[gg] = bc;
    for (int kk = 0; kk < 256; kk++) {
        float wv = W[kk * 128 + c];
        #pragma unroll
        for (int gg = 0; gg < 16; gg++) acc[gg] += rows[gg * 256 + kk] * wv;
    }
    #pragma unroll
    for (int gg = 0; gg < 16; gg++)
        out[(gb + gg) * 128 + c] = fmaxf(acc[gg], 0.f);
}
__global__ void lin3_lsm_kernel(const float* __restrict__ in, const float* __restrict__ W,
                                const float* __restrict__ b, float* __restrict__ out) {
    int g = blockIdx.x, lane = threadIdx.x;
    const float* row = in + g*128;
    float a0 = 0.f, a1 = 0.f;
    #pragma unroll
    for (int kk = lane; kk < 128; kk += 32) {
        float v = row[kk];
        a0 += v * W[kk*2 + 0];
        a1 += v * W[kk*2 + 1];
    }
    #pragma unroll
    for (int o = 16; o > 0; o >>= 1) {
        a0 += __shfl_down_sync(0xFFFFFFFFu, a0, o);
        a1 += __shfl_down_sync(0xFFFFFFFFu, a1, o);
    }
    if (lane == 0) {
        float l0 = a0 + b[0], l1 = a1 + b[1];
        float m = fmaxf(l0, l1);
        float lse = m + logf(expf(l0 - m) + expf(l1 - m));
        out[g*2 + 0] = l0 - lse;
        out[g*2 + 1] = l1 - lse;
    }
}

// ---------------- host driver ----------------
extern "C" void kernel_launch(void* const* d_in, const int* in_sizes, int n_in,
                              void* d_out, int out_size) {
    const float* d_x      = (const float*)d_in[0];
    const int*   d_ei     = (const int*)d_in[1];
    const float* gcn_w0   = (const float*)d_in[3];
    const float* gcn_b0   = (const float*)d_in[4];
    const float* gcn_w1   = (const float*)d_in[5];
    const float* gcn_b1   = (const float*)d_in[6];
    const float* gcn_w2   = (const float*)d_in[7];
    const float* gcn_b2   = (const float*)d_in[8];
    const float* pool_w0  = (const float*)d_in[9];
    const float* pool_w1  = (const float*)d_in[10];
    const float* pool_w2  = (const float*)d_in[11];
    const float* lin1_w   = (const float*)d_in[12];
    const float* lin1_b   = (const float*)d_in[13];
    const float* lin2_w   = (const float*)d_in[14];
    const float* lin2_b   = (const float*)d_in[15];
    const float* lin3_w   = (const float*)d_in[16];
    const float* lin3_b   = (const float*)d_in[17];
    float* out = (float*)d_out;

    const int E = in_sizes[1] / 2;
    const int* d_src = d_ei;
    const int* d_dst = d_ei + E;

    float *p_h, *p_agg, *p_x, *p_dinv, *p_score, *p_ro, *p_h1, *p_h2;
    int *p_newid, *p_perm, *p_es0, *p_ed0, *p_es1, *p_ed1, *p_rs, *p_rc;
    int2 *p_cpack;
    float *p_ew0, *p_ew1;
    __half *p_xhi, *p_xlo, *p_whi, *p_wlo;
    cudaGetSymbolAddress((void**)&p_h,    g_h);
    cudaGetSymbolAddress((void**)&p_agg,  g_agg);
    cudaGetSymbolAddress((void**)&p_x,    g_x);
    cudaGetSymbolAddress((void**)&p_dinv, g_dinv);
    cudaGetSymbolAddress((void**)&p_score,g_score);
    cudaGetSymbolAddress((void**)&p_newid,g_newid);
    cudaGetSymbolAddress((void**)&p_perm, g_perm);
    cudaGetSymbolAddress((void**)&p_es0,  g_esrc0);
    cudaGetSymbolAddress((void**)&p_ed0,  g_edst0);
    cudaGetSymbolAddress((void**)&p_ew0,  g_eew0);
    cudaGetSymbolAddress((void**)&p_es1,  g_esrc1);
    cudaGetSymbolAddress((void**)&p_ed1,  g_edst1);
    cudaGetSymbolAddress((void**)&p_ew1,  g_eew1);
    cudaGetSymbolAddress((void**)&p_rs,   g_rs);
    cudaGetSymbolAddress((void**)&p_rc,   g_rc);
    cudaGetSymbolAddress((void**)&p_cpack,g_cpack);
    cudaGetSymbolAddress((void**)&p_ro,   g_ro);
    cudaGetSymbolAddress((void**)&p_h1,   g_h1);
    cudaGetSymbolAddress((void**)&p_h2,   g_h2);
    cudaGetSymbolAddress((void**)&p_xhi,  g_xhi);
    cudaGetSymbolAddress((void**)&p_xlo,  g_xlo);
    cudaGetSymbolAddress((void**)&p_whi,  g_whi);
    cudaGetSymbolAddress((void**)&p_wlo,  g_wlo);

    cudaFuncSetAttribute(agg_fused_kernel,
                         cudaFuncAttributeMaxDynamicSharedMemorySize, 65536);
    cudaFuncSetAttribute(gemm_mma_kernel,
                         cudaFuncAttributeMaxDynamicSharedMemorySize, MMA_SMEM);

    // ---------------- level 0 ----------------
    int n = MAXN;
    {
        int npg = 256;
        wsplit_kernel<<<128, 256>>>(gcn_w0, 128, p_whi, p_wlo);
        xsplit_kernel<<<(n * 128 + 255) / 256, 256>>>(d_x, n * 128, p_xhi, p_xlo);
        gemm_mma_kernel<<<dim3(n / 128, 2), 256, MMA_SMEM>>>(p_xhi, p_xlo, p_whi, p_wlo, p_h, 128);
        csr_build_kernel<<<G, 256>>>(d_src, d_dst, nullptr, npg, p_rs, p_rc, p_cpack, p_dinv);
        agg_fused_kernel<<<dim3(4, G), 256, npg*64*4>>>(p_h, p_dinv, p_rs, p_rc,
                                                        p_cpack, gcn_b0, p_agg, npg);
    }
    {
        int npg = 256, k = 128, nNew = G * k;
        score_kernel<<<(n * 32 + 255) / 256, 256>>>(p_agg, pool_w0, p_score, n);
        pool_kernel<<<G, npg>>>(p_score, npg, k, p_newid, p_perm);
        gather_split_kernel<<<(nNew * HF + 255) / 256, 256>>>(p_agg, p_score, p_perm,
                                                              p_x, p_xhi, p_xlo, nNew);
        remap_kernel<<<(E + 255) / 256, 256>>>(d_src, d_dst, nullptr, p_newid,
                                               p_es0, p_ed0, p_ew0, E);
        readout_kernel<<<G, 256>>>(p_x, k, p_ro, 0);
        n = nNew;                 // 32768
    }
    // ---------------- level 1 ----------------
    {
        int npg = 128;
        wsplit_kernel<<<256, 256>>>(gcn_w1, 256, p_whi, p_wlo);
        gemm_mma_kernel<<<dim3(n / 128, 2), 256, MMA_SMEM>>>(p_xhi, p_xlo, p_whi, p_wlo, p_h, 256);
        csr_build_kernel<<<G, 256>>>(p_es0, p_ed0, p_ew0, npg, p_rs, p_rc, p_cpack, p_dinv);
        agg_fused_kernel<<<dim3(4, G), 256, npg*64*4>>>(p_h, p_dinv, p_rs, p_rc,
                                                        p_cpack, gcn_b1, p_agg, npg);
    }
    {
        int npg = 128, k = 64, nNew = G * k;
        score_kernel<<<(n * 32 + 255) / 256, 256>>>(p_agg, pool_w1, p_score, n);
        pool_kernel<<<G, npg>>>(p_score, npg, k, p_newid, p_perm);
        gather_split_kernel<<<(nNew * HF + 255) / 256, 256>>>(p_agg, p_score, p_perm,
                                                              p_x, p_xhi, p_xlo, nNew);
        remap_kernel<<<(E + 255) / 256, 256>>>(p_es0, p_ed0, p_ew0, p_newid,
                                               p_es1, p_ed1, p_ew1, E);
        readout_kernel<<<G, 256>>>(p_x, k, p_ro, 1);
        n = nNew;                 // 16384
    }
    // ---------------- level 2 ----------------
    {
        int npg = 64;
        wsplit_kernel<<<256, 256>>>(gcn_w2, 256, p_whi, p_wlo);
        gemm_mma_kernel<<<dim3(n / 128, 2), 256, MMA_SMEM>>>(p_xhi, p_xlo, p_whi, p_wlo, p_h, 256);
        csr_build_kernel<<<G, 256>>>(p_es1, p_ed1, p_ew1, npg, p_rs, p_rc, p_cpack, p_dinv);
        agg_fused_kernel<<<dim3(4, G), 256, npg*64*4>>>(p_h, p_dinv, p_rs, p_rc,
                                                        p_cpack, gcn_b2, p_agg, npg);
    }
    {
        int npg = 64, k = 32;
        score_kernel<<<(n * 32 + 255) / 256, 256>>>(p_agg, pool_w2, p_score, n);
        pool_kernel<<<G, npg>>>(p_score, npg, k, p_newid, p_perm);
        gather_scale_kernel<<<(G * k * HF + 255) / 256, 256>>>(p_agg, p_score, p_perm, p_x, G * k);
        readout_kernel<<<G, 256>>>(p_x, k, p_ro, 1);
    }

    // ---------------- MLP head ----------------
    lin1_kernel<<<32, 256>>>(p_ro, lin1_w, lin1_b, p_h1);
    lin2_kernel<<<16, 128>>>(p_h1, lin2_w, lin2_b, p_h2);
    lin3_lsm_kernel<<<G, 32>>>(p_h2, lin3_w, lin3_b, out);
}

// round 15
// speedup vs baseline: 2.3311x; 1.0055x over previous
#include <cuda_runtime.h>
#include <cuda_fp16.h>
#include <math.h>
#include <stdint.h>

// Problem constants
#define G 256
#define N0 256
#define HF 256            // hidden feature dim
#define MAXN (G*N0)       // 65536
#define MAXE (G*2048)     // 524288
#define EPG 2048          // edges per graph (fixed slot count, masked edges have ew=0)

// -------- scratch (device globals; no allocation allowed) --------
__device__ float g_h[MAXN*HF];        // 64 MB : h = x @ W
__device__ float g_agg[MAXN*HF];      // 64 MB : conv output
__device__ float g_x[(MAXN/2)*HF];    // 32 MB : pooled features
__device__ float g_dinv[MAXN];
__device__ float g_score[MAXN];
__device__ float g_spart[4*MAXN];     // per-fc-chunk score partials
__device__ int   g_newid[MAXN];
__device__ int   g_perm[MAXN/2];
__device__ int   g_esrc0[MAXE], g_edst0[MAXE];
__device__ float g_eew0[MAXE];
__device__ int   g_esrc1[MAXE], g_edst1[MAXE];
__device__ float g_eew1[MAXE];
__device__ int   g_rs[MAXN];
__device__ int   g_rc[MAXN];
__device__ int2  g_cpack[MAXE];       // CSR packed (src, norm-bits)
__device__ float g_ro[G*512];
__device__ float g_h1[G*256];
__device__ float g_h2[G*128];
// X split buffers (fp16 hi/lo)
__device__ __half g_xhi[8388608];
__device__ __half g_xlo[8388608];
// W split buffers (fp16 hi/lo, [256 (N)] x [K] K-major), K<=256
__device__ __half g_whi[256*256];
__device__ __half g_wlo[256*256];

// ================= helpers =================
__device__ __forceinline__ uint32_t smem_u32(const void* p) {
    uint32_t a;
    asm("{ .reg .u64 t; cvta.to.shared.u64 t, %1; cvt.u32.u64 %0, t; }"
        : "=r"(a) : "l"(p));
    return a;
}
__device__ __forceinline__ void ldsm_x4(uint32_t* r, uint32_t addr) {
    asm volatile("ldmatrix.sync.aligned.m8n8.x4.shared.b16 {%0,%1,%2,%3}, [%4];"
        : "=r"(r[0]), "=r"(r[1]), "=r"(r[2]), "=r"(r[3]) : "r"(addr));
}
__device__ __forceinline__ void ldsm_x2(uint32_t* r, uint32_t addr) {
    asm volatile("ldmatrix.sync.aligned.m8n8.x2.shared.b16 {%0,%1}, [%2];"
        : "=r"(r[0]), "=r"(r[1]) : "r"(addr));
}
__device__ __forceinline__ void mma_f16(float* d, const uint32_t* a, const uint32_t* b) {
    asm volatile("mma.sync.aligned.m16n8k16.row.col.f32.f16.f16.f32 "
        "{%0,%1,%2,%3}, {%4,%5,%6,%7}, {%8,%9}, {%0,%1,%2,%3};"
        : "+f"(d[0]), "+f"(d[1]), "+f"(d[2]), "+f"(d[3])
        : "r"(a[0]), "r"(a[1]), "r"(a[2]), "r"(a[3]), "r"(b[0]), "r"(b[1]));
}
__device__ __forceinline__ void cp16(uint32_t saddr, const void* g) {
    asm volatile("cp.async.cg.shared.global [%0], [%1], 16;" :: "r"(saddr), "l"(g));
}
#define CP_COMMIT() asm volatile("cp.async.commit_group;" ::: "memory")
#define CP_WAIT0()  asm volatile("cp.async.wait_group 0;" ::: "memory")
#define CP_WAIT1()  asm volatile("cp.async.wait_group 1;" ::: "memory")

// ================= split pre-passes (fp16 2-way) =================
__global__ void xsplit_kernel(const float* __restrict__ X, int total,
                              __half* __restrict__ xhi, __half* __restrict__ xlo) {
    int i = blockIdx.x * 256 + threadIdx.x;
    if (i >= total) return;
    float v = X[i];
    __half h = __float2half_rn(v);
    __half l = __float2half_rn(v - __half2float(h));
    xhi[i] = h; xlo[i] = l;
}

__global__ void wsplit_kernel(const float* __restrict__ W, int K,
                              __half* __restrict__ whi, __half* __restrict__ wlo) {
    int idx = blockIdx.x * 256 + threadIdx.x;
    if (idx >= K * 256) return;
    int k = idx >> 8, n = idx & 255;
    float w = W[idx];
    __half h = __float2half_rn(w);
    __half l = __float2half_rn(w - __half2float(h));
    whi[n*K + k] = h; wlo[n*K + k] = l;
}

// ================= MMA GEMM: C[n,256] = X[n,K] @ W[K,256] =================
// near-fp32 via fp16 2-way split, 3 product segments (hh, hl, lh; ll ~2^-22 dropped).
// Double-buffered cp.async pipeline over K=16 chunks.
#define SEGB 6144                  // 128 rows * 48B stride (16 halves + pad)
#define CHUNKB (4*SEGB)            // one chunk: A hi, A lo, B hi, B lo
#define MMA_SMEM (2*CHUNKB)        // 49152

__global__ __launch_bounds__(256) void gemm_mma_kernel(
        const __half* __restrict__ Xhi, const __half* __restrict__ Xlo,
        const __half* __restrict__ Whi, const __half* __restrict__ Wlo,
        float* __restrict__ C, int K) {
    extern __shared__ __align__(16) char smem[];
    uint32_t sb = smem_u32(smem);
    int tid = threadIdx.x, w = tid >> 5, lane = tid & 31;
    int rowBase = blockIdx.x * 128, colBase = blockIdx.y * 128;
    int warpRow = (w >> 2) * 64, warpCol = (w & 3) * 32;

    float acc[4][4][4];
    #pragma unroll
    for (int i = 0; i < 4; i++)
        #pragma unroll
        for (int j = 0; j < 4; j++)
            #pragma unroll
            for (int d = 0; d < 4; d++) acc[i][j][d] = 0.f;

    int r  = tid >> 1;                 // 0..127
    int hf = tid & 1;                  // 16B half-row
    uint32_t stOff = (uint32_t)(r * 48 + hf * 16);

    int bl = lane & 15;
    uint32_t aFragOff = (uint32_t)((warpRow + (lane & 15)) * 48 + (lane >> 4) * 16);
    uint32_t bFragOff = (uint32_t)(2*SEGB + (warpCol + (bl & 7)) * 48 + (bl >> 3) * 16);

    const __half* arow = Xhi + (size_t)(rowBase + r) * K + hf * 8;
    const __half* alow = Xlo + (size_t)(rowBase + r) * K + hf * 8;
    const __half* brow = Whi + (size_t)(colBase + r) * K + hf * 8;
    const __half* blow = Wlo + (size_t)(colBase + r) * K + hf * 8;

    const int NC = K >> 4;
    // prefetch chunk 0
    {
        uint32_t base = sb + stOff;
        cp16(base,          arow);
        cp16(base + SEGB,   alow);
        cp16(base + 2*SEGB, brow);
        cp16(base + 3*SEGB, blow);
        CP_COMMIT();
    }

    for (int kb = 0; kb < NC; kb++) {
        if (kb + 1 < NC) {
            uint32_t base = sb + ((kb + 1) & 1) * CHUNKB + stOff;
            int ko = (kb + 1) * 16;
            cp16(base,          arow + ko);
            cp16(base + SEGB,   alow + ko);
            cp16(base + 2*SEGB, brow + ko);
            cp16(base + 3*SEGB, blow + ko);
            CP_COMMIT();
            CP_WAIT1();                 // chunk kb complete
        } else {
            CP_WAIT0();
        }
        __syncthreads();

        uint32_t bufbase = sb + (kb & 1) * CHUNKB;
        uint32_t bfr[2][4][2];
        #pragma unroll
        for (int s = 0; s < 2; s++)
            #pragma unroll
            for (int nt = 0; nt < 4; nt++)
                ldsm_x2(bfr[s][nt], bufbase + bFragOff + s*SEGB + nt*(8*48));

        #pragma unroll
        for (int mt = 0; mt < 4; mt++) {
            uint32_t afr[2][4];
            #pragma unroll
            for (int s = 0; s < 2; s++)
                ldsm_x4(afr[s], bufbase + aFragOff + s*SEGB + mt*(16*48));
            #pragma unroll
            for (int cb = 0; cb < 3; cb++) {        // hh, hl, lh
                int ai = (cb == 2) ? 1 : 0;
                int bi = (cb == 1) ? 1 : 0;
                #pragma unroll
                for (int nt = 0; nt < 4; nt++)
                    mma_f16(acc[mt][nt], afr[ai], bfr[bi][nt]);
            }
        }
        __syncthreads();
    }

    #pragma unroll
    for (int mt = 0; mt < 4; mt++) {
        int row = rowBase + warpRow + mt*16 + (lane >> 2);
        #pragma unroll
        for (int nt = 0; nt < 4; nt++) {
            int col = colBase + warpCol + nt*8 + (lane & 3)*2;
            *(float2*)&C[(size_t)row * 256 + col] =
                make_float2(acc[mt][nt][0], acc[mt][nt][1]);
            *(float2*)&C[(size_t)(row + 8) * 256 + col] =
                make_float2(acc[mt][nt][2], acc[mt][nt][3]);
        }
    }
}

// ---------------- per-graph CSR build, single edge sweep ----------------
// Valid edges always have w == 1.0 (remap passes 1.0 or masks to 0),
// so staging (src, dst|-1) in smem preserves exact norms.
__global__ __launch_bounds__(256) void csr_build_kernel(
        const int* __restrict__ src, const int* __restrict__ dst,
        const float* __restrict__ ew, int npg,
        int* __restrict__ rs, int* __restrict__ rc,
        int2* __restrict__ cpack, float* __restrict__ dinv) {
    __shared__ float sdeg[256];
    __shared__ int   scnt[256];
    __shared__ int   sscan[256];
    __shared__ int   spos[256];
    __shared__ int   ssrc[EPG];
    __shared__ int   sdst[EPG];
    int g = blockIdx.x, t = threadIdx.x;
    int nbase = g * npg, ebase = g * EPG;

    if (t < npg) { sdeg[t] = 1.0f; scnt[t] = 0; }
    __syncthreads();
    for (int e = t; e < EPG; e += 256) {
        float w = ew ? ew[ebase + e] : 1.0f;
        int s = src[ebase + e] - nbase;
        int d = dst[ebase + e] - nbase;
        ssrc[e] = s;
        sdst[e] = (w != 0.f) ? d : -1;
        if (w != 0.f) {
            atomicAdd(&sdeg[d], w);
            atomicAdd(&scnt[d], 1);
        }
    }
    __syncthreads();
    int v = (t < npg) ? scnt[t] : 0;
    sscan[t] = v;
    __syncthreads();
    #pragma unroll
    for (int off = 1; off < 256; off <<= 1) {
        int add = (t >= off) ? sscan[t - off] : 0;
        __syncthreads();
        sscan[t] += add;
        __syncthreads();
    }
    int start = sscan[t] - v;
    if (t < npg) {
        rs[nbase + t] = start;
        rc[nbase + t] = v;
        spos[t] = start;
        dinv[nbase + t] = 1.0f / sdeg[t];
    }
    __syncthreads();
    for (int e = t; e < EPG; e += 256) {
        int d = sdst[e];
        if (d >= 0) {
            int s = ssrc[e];
            float nm = rsqrtf(sdeg[s]) * rsqrtf(sdeg[d]);   // w == 1 for valid edges
            int idx = atomicAdd(&spos[d], 1);
            cpack[ebase + idx] = make_int2(s, __float_as_int(nm));
        }
    }
}

// ---------------- fused aggregation + self-loop + bias + relu + score partial --
// block = (fc in [0,4), graph g); stages h tile [npg][64] floats; 2 dsts per warp
__global__ __launch_bounds__(256) void agg_fused_kernel(
        const float* __restrict__ h, const float* __restrict__ dinv,
        const int* __restrict__ rs, const int* __restrict__ rc,
        const int2* __restrict__ cpack, const float* __restrict__ bias,
        const float* __restrict__ pw, float* __restrict__ out,
        float* __restrict__ spart, int npg) {
    extern __shared__ float ht[];   // npg * 64 floats
    int fc = blockIdx.x, g = blockIdx.y;
    int t = threadIdx.x;
    int nbase = g * npg, ebase = g * EPG;

    const float4* h4 = (const float4*)h;
    float4* ht4 = (float4*)ht;
    for (int i = t; i < npg * 16; i += 256) {
        int node = i >> 4, q = i & 15;
        ht4[i] = h4[(size_t)(nbase + node) * 64 + fc * 16 + q];
    }
    __syncthreads();

    int w = t >> 5, lane = t & 31;
    float b0  = __ldg(bias + fc*64 + lane*2);
    float b1  = __ldg(bias + fc*64 + lane*2 + 1);
    float pw0 = __ldg(pw + fc*64 + lane*2);
    float pw1 = __ldg(pw + fc*64 + lane*2 + 1);
    const float2* ht2 = (const float2*)ht;

    for (int d0 = w * 2; d0 < npg; d0 += 16) {
        int d1 = d0 + 1;
        float2 v0 = ht2[d0*32 + lane];
        float2 v1 = ht2[d1*32 + lane];
        float dv0 = dinv[nbase + d0], dv1 = dinv[nbase + d1];
        float a00 = v0.x * dv0 + b0, a01 = v0.y * dv0 + b1;
        float a10 = v1.x * dv1 + b0, a11 = v1.y * dv1 + b1;
        int c0 = rc[nbase + d0], c1 = rc[nbase + d1];
        const int2* cp0 = cpack + ebase + rs[nbase + d0];
        const int2* cp1 = cpack + ebase + rs[nbase + d1];
        int e0 = 0, e1 = 0;
        while (e0 + 2 <= c0 && e1 + 2 <= c1) {
            int2 pa = __ldg(cp0 + e0), pb = __ldg(cp0 + e0 + 1);
            int2 pc = __ldg(cp1 + e1), pd = __ldg(cp1 + e1 + 1);
            float2 xa = ht2[pa.x*32 + lane]; float na = __int_as_float(pa.y);
            float2 xb = ht2[pb.x*32 + lane]; float nb = __int_as_float(pb.y);
            float2 xc = ht2[pc.x*32 + lane]; float nc = __int_as_float(pc.y);
            float2 xd = ht2[pd.x*32 + lane]; float nd = __int_as_float(pd.y);
            a00 += na * xa.x; a01 += na * xa.y;
            a00 += nb * xb.x; a01 += nb * xb.y;
            a10 += nc * xc.x; a11 += nc * xc.y;
            a10 += nd * xd.x; a11 += nd * xd.y;
            e0 += 2; e1 += 2;
        }
        for (; e0 < c0; e0++) {
            int2 p = __ldg(cp0 + e0);
            float2 x = ht2[p.x*32 + lane]; float nm = __int_as_float(p.y);
            a00 += nm * x.x; a01 += nm * x.y;
        }
        for (; e1 < c1; e1++) {
            int2 p = __ldg(cp1 + e1);
            float2 x = ht2[p.x*32 + lane]; float nm = __int_as_float(p.y);
            a10 += nm * x.x; a11 += nm * x.y;
        }
        float o00 = fmaxf(a00, 0.f), o01 = fmaxf(a01, 0.f);
        float o10 = fmaxf(a10, 0.f), o11 = fmaxf(a11, 0.f);
        *(float2*)(out + (size_t)(nbase + d0) * 256 + fc*64 + lane*2) =
            make_float2(o00, o01);
        *(float2*)(out + (size_t)(nbase + d1) * 256 + fc*64 + lane*2) =
            make_float2(o10, o11);
        // score partials (deterministic shfl order)
        float sp0 = o00 * pw0 + o01 * pw1;
        float sp1 = o10 * pw0 + o11 * pw1;
        #pragma unroll
        for (int off = 16; off > 0; off >>= 1) {
            sp0 += __shfl_down_sync(0xFFFFFFFFu, sp0, off);
            sp1 += __shfl_down_sync(0xFFFFFFFFu, sp1, off);
        }
        if (lane == 0) {
            spart[fc * MAXN + nbase + d0] = sp0;
            spart[fc * MAXN + nbase + d1] = sp1;
        }
    }
}

// ---------------- pool: sum partials, tanh, ||w|| inline, rank-count top-k -----
__global__ void pool_kernel(const float* __restrict__ spart,
                            const float* __restrict__ pw,
                            float* __restrict__ score, int npg, int k,
                            int* __restrict__ newid, int* __restrict__ perm) {
    __shared__ float s[256];
    __shared__ float red[256];
    int g = blockIdx.x, t = threadIdx.x;
    float ss = 0.f;
    for (int i = t; i < 256; i += npg) { float v = __ldg(pw + i); ss += v * v; }
    red[t] = ss;
    __syncthreads();
    for (int st = npg >> 1; st > 0; st >>= 1) {
        if (t < st) red[t] += red[t + st];
        __syncthreads();
    }
    float winv = rsqrtf(red[0]);

    int node = g * npg + t;
    float acc = 0.f;
    #pragma unroll
    for (int c = 0; c < 4; c++) acc += spart[c * MAXN + node];
    float my = tanhf(acc * winv);
    score[node] = my;
    s[t] = my;
    __syncthreads();
    int rank = 0;
    for (int j = 0; j < npg; j++) {
        float v = s[j];
        rank += (v > my) || (v == my && j < t);
    }
    if (rank < k) {
        newid[node] = g * k + rank;
        perm[g * k + rank] = node;
    } else {
        newid[node] = -1;
    }
}

// ---------------- gather*score + fp16 split for next GEMM ----------------
__global__ void gather_split_kernel(const float* __restrict__ x,
                                    const float* __restrict__ score,
                                    const int* __restrict__ perm,
                                    float* __restrict__ nx,
                                    __half* __restrict__ xhi,
                                    __half* __restrict__ xlo, int nNew) {
    int i = blockIdx.x * blockDim.x + threadIdx.x;
    if (i >= nNew * HF) return;
    int nn = i >> 8, f = i & 255;
    int old = perm[nn];
    float v = x[(size_t)old * HF + f] * score[old];
    nx[i] = v;
    __half h = __float2half_rn(v);
    xhi[i] = h;
    xlo[i] = __float2half_rn(v - __half2float(h));
}

__global__ void gather_scale_kernel(const float* __restrict__ x,
                                    const float* __restrict__ score,
                                    const int* __restrict__ perm,
                                    float* __restrict__ nx, int nNew) {
    int i = blockIdx.x * blockDim.x + threadIdx.x;
    if (i >= nNew * HF) return;
    int nn = i >> 8, f = i & 255;
    int old = perm[nn];
    nx[i] = x[(size_t)old * HF + f] * score[old];
}

__global__ void remap_kernel(const int* __restrict__ src, const int* __restrict__ dst,
                             const float* __restrict__ ew, const int* __restrict__ newid,
                             int* __restrict__ nsrc, int* __restrict__ ndst,
                             float* __restrict__ new_ew, int E) {
    int e = blockIdx.x * blockDim.x + threadIdx.x;
    if (e >= E) return;
    int s = newid[src[e]], d = newid[dst[e]];
    float w = ew ? ew[e] : 1.0f;
    bool valid = (s >= 0) && (d >= 0);
    nsrc[e]   = valid ? s : 0;
    ndst[e]   = valid ? d : 0;
    new_ew[e] = valid ? w : 0.f;
}

// ---------------- readout: [max | mean] per graph ----------------
__global__ void readout_kernel(const float* __restrict__ x, int k,
                               float* __restrict__ ro, int accumulate) {
    int g = blockIdx.x, f = threadIdx.x;
    const float* base = x + (size_t)g * k * HF + f;
    float mx = -3.4e38f, sum = 0.f;
    for (int j = 0; j < k; j++) {
        float v = base[(size_t)j * HF];
        mx = fmaxf(mx, v);
        sum += v;
    }
    float mean = sum / (float)k;
    if (accumulate) {
        ro[g*512 + f]       += mx;
        ro[g*512 + 256 + f] += mean;
    } else {
        ro[g*512 + f]       = mx;
        ro[g*512 + 256 + f] = mean;
    }
}

// ---------------- MLP (multi-graph blocks to amortize weight reads) ------------
__global__ __launch_bounds__(256) void lin1_kernel(const float* __restrict__ in,
        const float* __restrict__ W, const float* __restrict__ b,
        float* __restrict__ out) {
    int gb = blockIdx.x * 8, c = threadIdx.x;
    __shared__ float rows[8 * 512];
    for (int i = c; i < 8 * 512; i += 256) rows[i] = in[gb * 512 + i];
    __syncthreads();
    float acc[8];
    float bc = b[c];
    #pragma unroll
    for (int gg = 0; gg < 8; gg++) acc[gg] = bc;
    for (int kk = 0; kk < 512; kk++) {
        float wv = W[kk * 256 + c];
        #pragma unroll
        for (int gg = 0; gg < 8; gg++) acc[gg] += rows[gg * 512 + kk] * wv;
    }
    #pragma unroll
    for (int gg = 0; gg < 8; gg++)
        out[(gb + gg) * 256 + c] = fmaxf(acc[gg], 0.f);
}
__global__ __launch_bounds__(128) void lin2_kernel(const float* __restrict__ in,
        const float* __restrict__ W, const float* __restrict__ b,
        float* __restrict__ out) {
    int gb = blockIdx.x * 16, c = threadIdx.x;
    __shared__ float rows[16 * 256];
    for (int i = c; i < 16 * 256; i += 128) rows[i] = in[gb * 256 + i];
    __syncthreads();
    float acc[16];
    float bc = b[c];
    #pragma unroll
    for (int gg = 0; gg < 16; gg++) acc[gg] = bc;
    for (int kk = 0; kk < 256; kk++) {
        float wv = W[kk * 128 + c];
        #pragma unroll
        for (int gg = 0; gg < 16; gg++) acc[gg] += rows[gg * 256 + kk] * wv;
    }
    #pragma unroll
    for (int gg = 0; gg < 16; gg++)
        out[(gb + gg) * 128 + c] = fmaxf(acc[gg], 0.f);
}
__global__ void lin3_lsm_kernel(const float* __restrict__ in, const float* __restrict__ W,
                                const float* __restrict__ b, float* __restrict__ out) {
    int g = blockIdx.x, lane = threadIdx.x;
    const float* row = in + g*128;
    float a0 = 0.f, a1 = 0.f;
    #pragma unroll
    for (int kk = lane; kk < 128; kk += 32) {
        float v = row[kk];
        a0 += v * W[kk*2 + 0];
        a1 += v * W[kk*2 + 1];
    }
    #pragma unroll
    for (int o = 16; o > 0; o >>= 1) {
        a0 += __shfl_down_sync(0xFFFFFFFFu, a0, o);
        a1 += __shfl_down_sync(0xFFFFFFFFu, a1, o);
    }
    if (lane == 0) {
        float l0 = a0 + b[0], l1 = a1 + b[1];
        float m = fmaxf(l0, l1);
        float lse = m + logf(expf(l0 - m) + expf(l1 - m));
        out[g*2 + 0] = l0 - lse;
        out[g*2 + 1] = l1 - lse;
    }
}

// ---------------- host driver ----------------
extern "C" void kernel_launch(void* const* d_in, const int* in_sizes, int n_in,
                              void* d_out, int out_size) {
    const float* d_x      = (const float*)d_in[0];
    const int*   d_ei     = (const int*)d_in[1];
    const float* gcn_w0   = (const float*)d_in[3];
    const float* gcn_b0   = (const float*)d_in[4];
    const float* gcn_w1   = (const float*)d_in[5];
    const float* gcn_b1   = (const float*)d_in[6];
    const float* gcn_w2   = (const float*)d_in[7];
    const float* gcn_b2   = (const float*)d_in[8];
    const float* pool_w0  = (const float*)d_in[9];
    const float* pool_w1  = (const float*)d_in[10];
    const float* pool_w2  = (const float*)d_in[11];
    const float* lin1_w   = (const float*)d_in[12];
    const float* lin1_b   = (const float*)d_in[13];
    const float* lin2_w   = (const float*)d_in[14];
    const float* lin2_b   = (const float*)d_in[15];
    const float* lin3_w   = (const float*)d_in[16];
    const float* lin3_b   = (const float*)d_in[17];
    float* out = (float*)d_out;

    const int E = in_sizes[1] / 2;
    const int* d_src = d_ei;
    const int* d_dst = d_ei + E;

    float *p_h, *p_agg, *p_x, *p_dinv, *p_score, *p_spart, *p_ro, *p_h1, *p_h2;
    int *p_newid, *p_perm, *p_es0, *p_ed0, *p_es1, *p_ed1, *p_rs, *p_rc;
    int2 *p_cpack;
    float *p_ew0, *p_ew1;
    __half *p_xhi, *p_xlo, *p_whi, *p_wlo;
    cudaGetSymbolAddress((void**)&p_h,    g_h);
    cudaGetSymbolAddress((void**)&p_agg,  g_agg);
    cudaGetSymbolAddress((void**)&p_x,    g_x);
    cudaGetSymbolAddress((void**)&p_dinv, g_dinv);
    cudaGetSymbolAddress((void**)&p_score,g_score);
    cudaGetSymbolAddress((void**)&p_spart,g_spart);
    cudaGetSymbolAddress((void**)&p_newid,g_newid);
    cudaGetSymbolAddress((void**)&p_perm, g_perm);
    cudaGetSymbolAddress((void**)&p_es0,  g_esrc0);
    cudaGetSymbolAddress((void**)&p_ed0,  g_edst0);
    cudaGetSymbolAddress((void**)&p_ew0,  g_eew0);
    cudaGetSymbolAddress((void**)&p_es1,  g_esrc1);
    cudaGetSymbolAddress((void**)&p_ed1,  g_edst1);
    cudaGetSymbolAddress((void**)&p_ew1,  g_eew1);
    cudaGetSymbolAddress((void**)&p_rs,   g_rs);
    cudaGetSymbolAddress((void**)&p_rc,   g_rc);
    cudaGetSymbolAddress((void**)&p_cpack,g_cpack);
    cudaGetSymbolAddress((void**)&p_ro,   g_ro);
    cudaGetSymbolAddress((void**)&p_h1,   g_h1);
    cudaGetSymbolAddress((void**)&p_h2,   g_h2);
    cudaGetSymbolAddress((void**)&p_xhi,  g_xhi);
    cudaGetSymbolAddress((void**)&p_xlo,  g_xlo);
    cudaGetSymbolAddress((void**)&p_whi,  g_whi);
    cudaGetSymbolAddress((void**)&p_wlo,  g_wlo);

    cudaFuncSetAttribute(agg_fused_kernel,
                         cudaFuncAttributeMaxDynamicSharedMemorySize, 65536);
    cudaFuncSetAttribute(gemm_mma_kernel,
                         cudaFuncAttributeMaxDynamicSharedMemorySize, MMA_SMEM);

    // ---------------- level 0 ----------------
    int n = MAXN;
    {
        int npg = 256;
        wsplit_kernel<<<128, 256>>>(gcn_w0, 128, p_whi, p_wlo);
        xsplit_kernel<<<(n * 128 + 255) / 256, 256>>>(d_x, n * 128, p_xhi, p_xlo);
        gemm_mma_kernel<<<dim3(n / 128, 2), 256, MMA_SMEM>>>(p_xhi, p_xlo, p_whi, p_wlo, p_h, 128);
        csr_build_kernel<<<G, 256>>>(d_src, d_dst, nullptr, npg, p_rs, p_rc, p_cpack, p_dinv);
        agg_fused_kernel<<<dim3(4, G), 256, npg*64*4>>>(p_h, p_dinv, p_rs, p_rc,
                                                        p_cpack, gcn_b0, pool_w0,
                                                        p_agg, p_spart, npg);
    }
    {
        int npg = 256, k = 128, nNew = G * k;
        pool_kernel<<<G, npg>>>(p_spart, pool_w0, p_score, npg, k, p_newid, p_perm);
        gather_split_kernel<<<(nNew * HF + 255) / 256, 256>>>(p_agg, p_score, p_perm,
                                                              p_x, p_xhi, p_xlo, nNew);
        remap_kernel<<<(E + 255) / 256, 256>>>(d_src, d_dst, nullptr, p_newid,
                                               p_es0, p_ed0, p_ew0, E);
        readout_kernel<<<G, 256>>>(p_x, k, p_ro, 0);
        n = nNew;                 // 32768
    }
    // ---------------- level 1 ----------------
    {
        int npg = 128;
        wsplit_kernel<<<256, 256>>>(gcn_w1, 256, p_whi, p_wlo);
        gemm_mma_kernel<<<dim3(n / 128, 2), 256, MMA_SMEM>>>(p_xhi, p_xlo, p_whi, p_wlo, p_h, 256);
        csr_build_kernel<<<G, 256>>>(p_es0, p_ed0, p_ew0, npg, p_rs, p_rc, p_cpack, p_dinv);
        agg_fused_kernel<<<dim3(4, G), 256, npg*64*4>>>(p_h, p_dinv, p_rs, p_rc,
                                                        p_cpack, gcn_b1, pool_w1,
                                                        p_agg, p_spart, npg);
    }
    {
        int npg = 128, k = 64, nNew = G * k;
        pool_kernel<<<G, npg>>>(p_spart, pool_w1, p_score, npg, k, p_newid, p_perm);
        gather_split_kernel<<<(nNew * HF + 255) / 256, 256>>>(p_agg, p_score, p_perm,
                                                              p_x, p_xhi, p_xlo, nNew);
        remap_kernel<<<(E + 255) / 256, 256>>>(p_es0, p_ed0, p_ew0, p_newid,
                                               p_es1, p_ed1, p_ew1, E);
        readout_kernel<<<G, 256>>>(p_x, k, p_ro, 1);
        n = nNew;                 // 16384
    }
    // ---------------- level 2 ----------------
    {
        int npg = 64;
        wsplit_kernel<<<256, 256>>>(gcn_w2, 256, p_whi, p_wlo);
        gemm_mma_kernel<<<dim3(n / 128, 2), 256, MMA_SMEM>>>(p_xhi, p_xlo, p_whi, p_wlo, p_h, 256);
        csr_build_kernel<<<G, 256>>>(p_es1, p_ed1, p_ew1, npg, p_rs, p_rc, p_cpack, p_dinv);
        agg_fused_kernel<<<dim3(4, G), 256, npg*64*4>>>(p_h, p_dinv, p_rs, p_rc,
                                                        p_cpack, gcn_b2, pool_w2,
                                                        p_agg, p_spart, npg);
    }
    {
        int npg = 64, k = 32;
        pool_kernel<<<G, npg>>>(p_spart, pool_w2, p_score, npg, k, p_newid, p_perm);
        gather_scale_kernel<<<(G * k * HF + 255) / 256, 256>>>(p_agg, p_score, p_perm, p_x, G * k);
        readout_kernel<<<G, 256>>>(p_x, k, p_ro, 1);
    }

    // ---------------- MLP head ----------------
    lin1_kernel<<<32, 256>>>(p_ro, lin1_w, lin1_b, p_h1);
    lin2_kernel<<<16, 128>>>(p_h1, lin2_w, lin2_b, p_h2);
    lin3_lsm_kernel<<<G, 32>>>(p_h2, lin3_w, lin3_b, out);
}

// round 16
// speedup vs baseline: 2.3534x; 1.0095x over previous
#include <cuda_runtime.h>
#include <cuda_fp16.h>
#include <math.h>
#include <stdint.h>

// Problem constants
#define G 256
#define N0 256
#define HF 256            // hidden feature dim
#define MAXN (G*N0)       // 65536
#define MAXE (G*2048)     // 524288
#define EPG 2048          // edges per graph (fixed slot count)

// -------- scratch (device globals; no allocation allowed) --------
__device__ float g_h[MAXN*HF];        // 64 MB : h = x @ W
__device__ float g_agg[MAXN*HF];      // 64 MB : conv output
__device__ float g_x[(MAXN/2)*HF];    // 32 MB : pooled features
__device__ float g_dinv[MAXN];
__device__ float g_score[MAXN];
__device__ float g_spart[4*MAXN];     // per-fc-chunk score partials
__device__ int   g_newid0[MAXN];      // pool0 map (orig node -> L1 id or -1)
__device__ int   g_newid1[MAXN/2];    // pool1 map (L1 node -> L2 id or -1)
__device__ int   g_cmap[MAXN];        // composed map for L2
__device__ int   g_perm[MAXN/2];
__device__ int   g_rs[MAXN];
__device__ int   g_rc[MAXN];
__device__ int2  g_cpack[MAXE];       // CSR packed (src, norm-bits)
__device__ float g_ro[G*512];
__device__ float g_h1[G*256];
__device__ float g_h2[G*128];
// X split buffers (fp16 hi/lo)
__device__ __half g_xhi[8388608];
__device__ __half g_xlo[8388608];
// W split buffers (fp16 hi/lo, [256 (N)] x [K] K-major), K<=256
__device__ __half g_whi[256*256];
__device__ __half g_wlo[256*256];

// ================= helpers =================
__device__ __forceinline__ uint32_t smem_u32(const void* p) {
    uint32_t a;
    asm("{ .reg .u64 t; cvta.to.shared.u64 t, %1; cvt.u32.u64 %0, t; }"
        : "=r"(a) : "l"(p));
    return a;
}
__device__ __forceinline__ void ldsm_x4(uint32_t* r, uint32_t addr) {
    asm volatile("ldmatrix.sync.aligned.m8n8.x4.shared.b16 {%0,%1,%2,%3}, [%4];"
        : "=r"(r[0]), "=r"(r[1]), "=r"(r[2]), "=r"(r[3]) : "r"(addr));
}
__device__ __forceinline__ void ldsm_x2(uint32_t* r, uint32_t addr) {
    asm volatile("ldmatrix.sync.aligned.m8n8.x2.shared.b16 {%0,%1}, [%2];"
        : "=r"(r[0]), "=r"(r[1]) : "r"(addr));
}
__device__ __forceinline__ void mma_f16(float* d, const uint32_t* a, const uint32_t* b) {
    asm volatile("mma.sync.aligned.m16n8k16.row.col.f32.f16.f16.f32 "
        "{%0,%1,%2,%3}, {%4,%5,%6,%7}, {%8,%9}, {%0,%1,%2,%3};"
        : "+f"(d[0]), "+f"(d[1]), "+f"(d[2]), "+f"(d[3])
        : "r"(a[0]), "r"(a[1]), "r"(a[2]), "r"(a[3]), "r"(b[0]), "r"(b[1]));
}
__device__ __forceinline__ void cp16(uint32_t saddr, const void* g) {
    asm volatile("cp.async.cg.shared.global [%0], [%1], 16;" :: "r"(saddr), "l"(g));
}
#define CP_COMMIT() asm volatile("cp.async.commit_group;" ::: "memory")
#define CP_WAIT0()  asm volatile("cp.async.wait_group 0;" ::: "memory")
#define CP_WAIT1()  asm volatile("cp.async.wait_group 1;" ::: "memory")

// ================= split pre-passes (fp16 2-way) =================
__global__ void xsplit_kernel(const float* __restrict__ X, int total,
                              __half* __restrict__ xhi, __half* __restrict__ xlo) {
    int i = blockIdx.x * 256 + threadIdx.x;
    if (i >= total) return;
    float v = X[i];
    __half h = __float2half_rn(v);
    __half l = __float2half_rn(v - __half2float(h));
    xhi[i] = h; xlo[i] = l;
}

__global__ void wsplit_kernel(const float* __restrict__ W, int K,
                              __half* __restrict__ whi, __half* __restrict__ wlo) {
    int idx = blockIdx.x * 256 + threadIdx.x;
    if (idx >= K * 256) return;
    int k = idx >> 8, n = idx & 255;
    float w = W[idx];
    __half h = __float2half_rn(w);
    __half l = __float2half_rn(w - __half2float(h));
    whi[n*K + k] = h; wlo[n*K + k] = l;
}

// ================= MMA GEMM: C[n,256] = X[n,K] @ W[K,256] =================
// near-fp32 via fp16 2-way split, 3 product segments (hh, hl, lh; ll ~2^-22 dropped).
// Double-buffered cp.async pipeline over K=16 chunks.
#define SEGB 6144                  // 128 rows * 48B stride (16 halves + pad)
#define CHUNKB (4*SEGB)            // one chunk: A hi, A lo, B hi, B lo
#define MMA_SMEM (2*CHUNKB)        // 49152

__global__ __launch_bounds__(256) void gemm_mma_kernel(
        const __half* __restrict__ Xhi, const __half* __restrict__ Xlo,
        const __half* __restrict__ Whi, const __half* __restrict__ Wlo,
        float* __restrict__ C, int K) {
    extern __shared__ __align__(16) char smem[];
    uint32_t sb = smem_u32(smem);
    int tid = threadIdx.x, w = tid >> 5, lane = tid & 31;
    int rowBase = blockIdx.x * 128, colBase = blockIdx.y * 128;
    int warpRow = (w >> 2) * 64, warpCol = (w & 3) * 32;

    float acc[4][4][4];
    #pragma unroll
    for (int i = 0; i < 4; i++)
        #pragma unroll
        for (int j = 0; j < 4; j++)
            #pragma unroll
            for (int d = 0; d < 4; d++) acc[i][j][d] = 0.f;

    int r  = tid >> 1;                 // 0..127
    int hf = tid & 1;                  // 16B half-row
    uint32_t stOff = (uint32_t)(r * 48 + hf * 16);

    int bl = lane & 15;
    uint32_t aFragOff = (uint32_t)((warpRow + (lane & 15)) * 48 + (lane >> 4) * 16);
    uint32_t bFragOff = (uint32_t)(2*SEGB + (warpCol + (bl & 7)) * 48 + (bl >> 3) * 16);

    const __half* arow = Xhi + (size_t)(rowBase + r) * K + hf * 8;
    const __half* alow = Xlo + (size_t)(rowBase + r) * K + hf * 8;
    const __half* brow = Whi + (size_t)(colBase + r) * K + hf * 8;
    const __half* blow = Wlo + (size_t)(colBase + r) * K + hf * 8;

    const int NC = K >> 4;
    // prefetch chunk 0
    {
        uint32_t base = sb + stOff;
        cp16(base,          arow);
        cp16(base + SEGB,   alow);
        cp16(base + 2*SEGB, brow);
        cp16(base + 3*SEGB, blow);
        CP_COMMIT();
    }

    for (int kb = 0; kb < NC; kb++) {
        if (kb + 1 < NC) {
            uint32_t base = sb + ((kb + 1) & 1) * CHUNKB + stOff;
            int ko = (kb + 1) * 16;
            cp16(base,          arow + ko);
            cp16(base + SEGB,   alow + ko);
            cp16(base + 2*SEGB, brow + ko);
            cp16(base + 3*SEGB, blow + ko);
            CP_COMMIT();
            CP_WAIT1();                 // chunk kb complete
        } else {
            CP_WAIT0();
        }
        __syncthreads();

        uint32_t bufbase = sb + (kb & 1) * CHUNKB;
        uint32_t bfr[2][4][2];
        #pragma unroll
        for (int s = 0; s < 2; s++)
            #pragma unroll
            for (int nt = 0; nt < 4; nt++)
                ldsm_x2(bfr[s][nt], bufbase + bFragOff + s*SEGB + nt*(8*48));

        #pragma unroll
        for (int mt = 0; mt < 4; mt++) {
            uint32_t afr[2][4];
            #pragma unroll
            for (int s = 0; s < 2; s++)
                ldsm_x4(afr[s], bufbase + aFragOff + s*SEGB + mt*(16*48));
            #pragma unroll
            for (int cb = 0; cb < 3; cb++) {        // hh, hl, lh
                int ai = (cb == 2) ? 1 : 0;
                int bi = (cb == 1) ? 1 : 0;
                #pragma unroll
                for (int nt = 0; nt < 4; nt++)
                    mma_f16(acc[mt][nt], afr[ai], bfr[bi][nt]);
            }
        }
        __syncthreads();
    }

    #pragma unroll
    for (int mt = 0; mt < 4; mt++) {
        int row = rowBase + warpRow + mt*16 + (lane >> 2);
        #pragma unroll
        for (int nt = 0; nt < 4; nt++) {
            int col = colBase + warpCol + nt*8 + (lane & 3)*2;
            *(float2*)&C[(size_t)row * 256 + col] =
                make_float2(acc[mt][nt][0], acc[mt][nt][1]);
            *(float2*)&C[(size_t)(row + 8) * 256 + col] =
                make_float2(acc[mt][nt][2], acc[mt][nt][3]);
        }
    }
}

// ---------------- per-graph CSR build from ORIGINAL edges + node map ----------
// All valid edges have weight exactly 1 (ew in {0,1} throughout the network),
// and validity == both mapped endpoints >= 0. map == nullptr means identity (L0).
__global__ __launch_bounds__(256) void csr_build_kernel(
        const int* __restrict__ src, const int* __restrict__ dst,
        const int* __restrict__ map, int npg,
        int* __restrict__ rs, int* __restrict__ rc,
        int2* __restrict__ cpack, float* __restrict__ dinv) {
    __shared__ float sdeg[256];
    __shared__ int   scnt[256];
    __shared__ int   sscan[256];
    __shared__ int   spos[256];
    __shared__ int   ssrc[EPG];
    __shared__ int   sdst[EPG];
    int g = blockIdx.x, t = threadIdx.x;
    int nbase = g * npg, ebase = g * EPG;

    if (t < npg) { sdeg[t] = 1.0f; scnt[t] = 0; }
    __syncthreads();
    for (int e = t; e < EPG; e += 256) {
        int gs = src[ebase + e], gd = dst[ebase + e];
        int s  = map ? __ldg(map + gs) : gs;
        int d  = map ? __ldg(map + gd) : gd;
        bool valid = (s >= 0) && (d >= 0);
        ssrc[e] = s - nbase;
        sdst[e] = valid ? (d - nbase) : -1;
        if (valid) {
            atomicAdd(&sdeg[d - nbase], 1.0f);
            atomicAdd(&scnt[d - nbase], 1);
        }
    }
    __syncthreads();
    int v = (t < npg) ? scnt[t] : 0;
    sscan[t] = v;
    __syncthreads();
    #pragma unroll
    for (int off = 1; off < 256; off <<= 1) {
        int add = (t >= off) ? sscan[t - off] : 0;
        __syncthreads();
        sscan[t] += add;
        __syncthreads();
    }
    int start = sscan[t] - v;
    if (t < npg) {
        rs[nbase + t] = start;
        rc[nbase + t] = v;
        spos[t] = start;
        dinv[nbase + t] = 1.0f / sdeg[t];
    }
    __syncthreads();
    for (int e = t; e < EPG; e += 256) {
        int d = sdst[e];
        if (d >= 0) {
            int s = ssrc[e];
            float nm = rsqrtf(sdeg[s]) * rsqrtf(sdeg[d]);   // w == 1 for valid edges
            int idx = atomicAdd(&spos[d], 1);
            cpack[ebase + idx] = make_int2(s, __float_as_int(nm));
        }
    }
}

// ---------------- compose node maps: c[i] = a[i] >= 0 ? b[a[i]] : -1 ----------
__global__ void compose_kernel(const int* __restrict__ a, const int* __restrict__ b,
                               int* __restrict__ c, int n) {
    int i = blockIdx.x * 256 + threadIdx.x;
    if (i >= n) return;
    int m = a[i];
    c[i] = (m >= 0) ? b[m] : -1;
}

// ---------------- fused aggregation + self-loop + bias + relu + score partial --
// block = (fc in [0,4), graph g); stages h tile [npg][64] floats; 2 dsts per warp
__global__ __launch_bounds__(256) void agg_fused_kernel(
        const float* __restrict__ h, const float* __restrict__ dinv,
        const int* __restrict__ rs, const int* __restrict__ rc,
        const int2* __restrict__ cpack, const float* __restrict__ bias,
        const float* __restrict__ pw, float* __restrict__ out,
        float* __restrict__ spart, int npg) {
    extern __shared__ float ht[];   // npg * 64 floats
    int fc = blockIdx.x, g = blockIdx.y;
    int t = threadIdx.x;
    int nbase = g * npg, ebase = g * EPG;

    const float4* h4 = (const float4*)h;
    float4* ht4 = (float4*)ht;
    for (int i = t; i < npg * 16; i += 256) {
        int node = i >> 4, q = i & 15;
        ht4[i] = h4[(size_t)(nbase + node) * 64 + fc * 16 + q];
    }
    __syncthreads();

    int w = t >> 5, lane = t & 31;
    float b0  = __ldg(bias + fc*64 + lane*2);
    float b1  = __ldg(bias + fc*64 + lane*2 + 1);
    float pw0 = __ldg(pw + fc*64 + lane*2);
    float pw1 = __ldg(pw + fc*64 + lane*2 + 1);
    const float2* ht2 = (const float2*)ht;

    for (int d0 = w * 2; d0 < npg; d0 += 16) {
        int d1 = d0 + 1;
        float2 v0 = ht2[d0*32 + lane];
        float2 v1 = ht2[d1*32 + lane];
        float dv0 = dinv[nbase + d0], dv1 = dinv[nbase + d1];
        float a00 = v0.x * dv0 + b0, a01 = v0.y * dv0 + b1;
        float a10 = v1.x * dv1 + b0, a11 = v1.y * dv1 + b1;
        int c0 = rc[nbase + d0], c1 = rc[nbase + d1];
        const int2* cp0 = cpack + ebase + rs[nbase + d0];
        const int2* cp1 = cpack + ebase + rs[nbase + d1];
        int e0 = 0, e1 = 0;
        while (e0 + 2 <= c0 && e1 + 2 <= c1) {
            int2 pa = __ldg(cp0 + e0), pb = __ldg(cp0 + e0 + 1);
            int2 pc = __ldg(cp1 + e1), pd = __ldg(cp1 + e1 + 1);
            float2 xa = ht2[pa.x*32 + lane]; float na = __int_as_float(pa.y);
            float2 xb = ht2[pb.x*32 + lane]; float nb = __int_as_float(pb.y);
            float2 xc = ht2[pc.x*32 + lane]; float nc = __int_as_float(pc.y);
            float2 xd = ht2[pd.x*32 + lane]; float nd = __int_as_float(pd.y);
            a00 += na * xa.x; a01 += na * xa.y;
            a00 += nb * xb.x; a01 += nb * xb.y;
            a10 += nc * xc.x; a11 += nc * xc.y;
            a10 += nd * xd.x; a11 += nd * xd.y;
            e0 += 2; e1 += 2;
        }
        for (; e0 < c0; e0++) {
            int2 p = __ldg(cp0 + e0);
            float2 x = ht2[p.x*32 + lane]; float nm = __int_as_float(p.y);
            a00 += nm * x.x; a01 += nm * x.y;
        }
        for (; e1 < c1; e1++) {
            int2 p = __ldg(cp1 + e1);
            float2 x = ht2[p.x*32 + lane]; float nm = __int_as_float(p.y);
            a10 += nm * x.x; a11 += nm * x.y;
        }
        float o00 = fmaxf(a00, 0.f), o01 = fmaxf(a01, 0.f);
        float o10 = fmaxf(a10, 0.f), o11 = fmaxf(a11, 0.f);
        *(float2*)(out + (size_t)(nbase + d0) * 256 + fc*64 + lane*2) =
            make_float2(o00, o01);
        *(float2*)(out + (size_t)(nbase + d1) * 256 + fc*64 + lane*2) =
            make_float2(o10, o11);
        // score partials (deterministic shfl order)
        float sp0 = o00 * pw0 + o01 * pw1;
        float sp1 = o10 * pw0 + o11 * pw1;
        #pragma unroll
        for (int off = 16; off > 0; off >>= 1) {
            sp0 += __shfl_down_sync(0xFFFFFFFFu, sp0, off);
            sp1 += __shfl_down_sync(0xFFFFFFFFu, sp1, off);
        }
        if (lane == 0) {
            spart[fc * MAXN + nbase + d0] = sp0;
            spart[fc * MAXN + nbase + d1] = sp1;
        }
    }
}

// ---------------- pool: sum partials, tanh, ||w|| inline, rank-count top-k -----
__global__ void pool_kernel(const float* __restrict__ spart,
                            const float* __restrict__ pw,
                            float* __restrict__ score, int npg, int k,
                            int* __restrict__ newid, int* __restrict__ perm) {
    __shared__ float s[256];
    __shared__ float red[256];
    int g = blockIdx.x, t = threadIdx.x;
    float ss = 0.f;
    for (int i = t; i < 256; i += npg) { float v = __ldg(pw + i); ss += v * v; }
    red[t] = ss;
    __syncthreads();
    for (int st = npg >> 1; st > 0; st >>= 1) {
        if (t < st) red[t] += red[t + st];
        __syncthreads();
    }
    float winv = rsqrtf(red[0]);

    int node = g * npg + t;
    float acc = 0.f;
    #pragma unroll
    for (int c = 0; c < 4; c++) acc += spart[c * MAXN + node];
    float my = tanhf(acc * winv);
    score[node] = my;
    s[t] = my;
    __syncthreads();
    int rank = 0;
    for (int j = 0; j < npg; j++) {
        float v = s[j];
        rank += (v > my) || (v == my && j < t);
    }
    if (rank < k) {
        newid[node] = g * k + rank;
        perm[g * k + rank] = node;
    } else {
        newid[node] = -1;
    }
}

// ---------------- gather*score + fp16 split for next GEMM ----------------
__global__ void gather_split_kernel(const float* __restrict__ x,
                                    const float* __restrict__ score,
                                    const int* __restrict__ perm,
                                    float* __restrict__ nx,
                                    __half* __restrict__ xhi,
                                    __half* __restrict__ xlo, int nNew) {
    int i = blockIdx.x * blockDim.x + threadIdx.x;
    if (i >= nNew * HF) return;
    int nn = i >> 8, f = i & 255;
    int old = perm[nn];
    float v = x[(size_t)old * HF + f] * score[old];
    nx[i] = v;
    __half h = __float2half_rn(v);
    xhi[i] = h;
    xlo[i] = __float2half_rn(v - __half2float(h));
}

__global__ void gather_scale_kernel(const float* __restrict__ x,
                                    const float* __restrict__ score,
                                    const int* __restrict__ perm,
                                    float* __restrict__ nx, int nNew) {
    int i = blockIdx.x * blockDim.x + threadIdx.x;
    if (i >= nNew * HF) return;
    int nn = i >> 8, f = i & 255;
    int old = perm[nn];
    nx[i] = x[(size_t)old * HF + f] * score[old];
}

// ---------------- readout: [max | mean] per graph ----------------
__global__ void readout_kernel(const float* __restrict__ x, int k,
                               float* __restrict__ ro, int accumulate) {
    int g = blockIdx.x, f = threadIdx.x;
    const float* base = x + (size_t)g * k * HF + f;
    float mx = -3.4e38f, sum = 0.f;
    for (int j = 0; j < k; j++) {
        float v = base[(size_t)j * HF];
        mx = fmaxf(mx, v);
        sum += v;
    }
    float mean = sum / (float)k;
    if (accumulate) {
        ro[g*512 + f]       += mx;
        ro[g*512 + 256 + f] += mean;
    } else {
        ro[g*512 + f]       = mx;
        ro[g*512 + 256 + f] = mean;
    }
}

// ---------------- MLP (multi-graph blocks to amortize weight reads) ------------
__global__ __launch_bounds__(256) void lin1_kernel(const float* __restrict__ in,
        const float* __restrict__ W, const float* __restrict__ b,
        float* __restrict__ out) {
    int gb = blockIdx.x * 8, c = threadIdx.x;
    __shared__ float rows[8 * 512];
    for (int i = c; i < 8 * 512; i += 256) rows[i] = in[gb * 512 + i];
    __syncthreads();
    float acc[8];
    float bc = b[c];
    #pragma unroll
    for (int gg = 0; gg < 8; gg++) acc[gg] = bc;
    for (int kk = 0; kk < 512; kk++) {
        float wv = W[kk * 256 + c];
        #pragma unroll
        for (int gg = 0; gg < 8; gg++) acc[gg] += rows[gg * 512 + kk] * wv;
    }
    #pragma unroll
    for (int gg = 0; gg < 8; gg++)
        out[(gb + gg) * 256 + c] = fmaxf(acc[gg], 0.f);
}
__global__ __launch_bounds__(128) void lin2_kernel(const float* __restrict__ in,
        const float* __restrict__ W, const float* __restrict__ b,
        float* __restrict__ out) {
    int gb = blockIdx.x * 16, c = threadIdx.x;
    __shared__ float rows[16 * 256];
    for (int i = c; i < 16 * 256; i += 128) rows[i] = in[gb * 256 + i];
    __syncthreads();
    float acc[16];
    float bc = b[c];
    #pragma unroll
    for (int gg = 0; gg < 16; gg++) acc[gg] = bc;
    for (int kk = 0; kk < 256; kk++) {
        float wv = W[kk * 128 + c];
        #pragma unroll
        for (int gg = 0; gg < 16; gg++) acc[gg] += rows[gg * 256 + kk] * wv;
    }
    #pragma unroll
    for (int gg = 0; gg < 16; gg++)
        out[(gb + gg) * 128 + c] = fmaxf(acc[gg], 0.f);
}
__global__ void lin3_lsm_kernel(const float* __restrict__ in, const float* __restrict__ W,
                                const float* __restrict__ b, float* __restrict__ out) {
    int g = blockIdx.x, lane = threadIdx.x;
    const float* row = in + g*128;
    float a0 = 0.f, a1 = 0.f;
    #pragma unroll
    for (int kk = lane; kk < 128; kk += 32) {
        float v = row[kk];
        a0 += v * W[kk*2 + 0];
        a1 += v * W[kk*2 + 1];
    }
    #pragma unroll
    for (int o = 16; o > 0; o >>= 1) {
        a0 += __shfl_down_sync(0xFFFFFFFFu, a0, o);
        a1 += __shfl_down_sync(0xFFFFFFFFu, a1, o);
    }
    if (lane == 0) {
        float l0 = a0 + b[0], l1 = a1 + b[1];
        float m = fmaxf(l0, l1);
        float lse = m + logf(expf(l0 - m) + expf(l1 - m));
        out[g*2 + 0] = l0 - lse;
        out[g*2 + 1] = l1 - lse;
    }
}

// ---------------- host driver ----------------
extern "C" void kernel_launch(void* const* d_in, const int* in_sizes, int n_in,
                              void* d_out, int out_size) {
    const float* d_x      = (const float*)d_in[0];
    const int*   d_ei     = (const int*)d_in[1];
    const float* gcn_w0   = (const float*)d_in[3];
    const float* gcn_b0   = (const float*)d_in[4];
    const float* gcn_w1   = (const float*)d_in[5];
    const float* gcn_b1   = (const float*)d_in[6];
    const float* gcn_w2   = (const float*)d_in[7];
    const float* gcn_b2   = (const float*)d_in[8];
    const float* pool_w0  = (const float*)d_in[9];
    const float* pool_w1  = (const float*)d_in[10];
    const float* pool_w2  = (const float*)d_in[11];
    const float* lin1_w   = (const float*)d_in[12];
    const float* lin1_b   = (const float*)d_in[13];
    const float* lin2_w   = (const float*)d_in[14];
    const float* lin2_b   = (const float*)d_in[15];
    const float* lin3_w   = (const float*)d_in[16];
    const float* lin3_b   = (const float*)d_in[17];
    float* out = (float*)d_out;

    const int E = in_sizes[1] / 2;
    const int* d_src = d_ei;
    const int* d_dst = d_ei + E;

    float *p_h, *p_agg, *p_x, *p_dinv, *p_score, *p_spart, *p_ro, *p_h1, *p_h2;
    int *p_newid0, *p_newid1, *p_cmap, *p_perm, *p_rs, *p_rc;
    int2 *p_cpack;
    __half *p_xhi, *p_xlo, *p_whi, *p_wlo;
    cudaGetSymbolAddress((void**)&p_h,     g_h);
    cudaGetSymbolAddress((void**)&p_agg,   g_agg);
    cudaGetSymbolAddress((void**)&p_x,     g_x);
    cudaGetSymbolAddress((void**)&p_dinv,  g_dinv);
    cudaGetSymbolAddress((void**)&p_score, g_score);
    cudaGetSymbolAddress((void**)&p_spart, g_spart);
    cudaGetSymbolAddress((void**)&p_newid0,g_newid0);
    cudaGetSymbolAddress((void**)&p_newid1,g_newid1);
    cudaGetSymbolAddress((void**)&p_cmap,  g_cmap);
    cudaGetSymbolAddress((void**)&p_perm,  g_perm);
    cudaGetSymbolAddress((void**)&p_rs,    g_rs);
    cudaGetSymbolAddress((void**)&p_rc,    g_rc);
    cudaGetSymbolAddress((void**)&p_cpack, g_cpack);
    cudaGetSymbolAddress((void**)&p_ro,    g_ro);
    cudaGetSymbolAddress((void**)&p_h1,    g_h1);
    cudaGetSymbolAddress((void**)&p_h2,    g_h2);
    cudaGetSymbolAddress((void**)&p_xhi,   g_xhi);
    cudaGetSymbolAddress((void**)&p_xlo,   g_xlo);
    cudaGetSymbolAddress((void**)&p_whi,   g_whi);
    cudaGetSymbolAddress((void**)&p_wlo,   g_wlo);

    cudaFuncSetAttribute(agg_fused_kernel,
                         cudaFuncAttributeMaxDynamicSharedMemorySize, 65536);
    cudaFuncSetAttribute(gemm_mma_kernel,
                         cudaFuncAttributeMaxDynamicSharedMemorySize, MMA_SMEM);

    // ---------------- level 0 ----------------
    int n = MAXN;
    {
        int npg = 256;
        wsplit_kernel<<<128, 256>>>(gcn_w0, 128, p_whi, p_wlo);
        xsplit_kernel<<<(n * 128 + 255) / 256, 256>>>(d_x, n * 128, p_xhi, p_xlo);
        gemm_mma_kernel<<<dim3(n / 128, 2), 256, MMA_SMEM>>>(p_xhi, p_xlo, p_whi, p_wlo, p_h, 128);
        csr_build_kernel<<<G, 256>>>(d_src, d_dst, nullptr, npg, p_rs, p_rc, p_cpack, p_dinv);
        agg_fused_kernel<<<dim3(4, G), 256, npg*64*4>>>(p_h, p_dinv, p_rs, p_rc,
                                                        p_cpack, gcn_b0, pool_w0,
                                                        p_agg, p_spart, npg);
    }
    {
        int npg = 256, k = 128, nNew = G * k;
        pool_kernel<<<G, npg>>>(p_spart, pool_w0, p_score, npg, k, p_newid0, p_perm);
        gather_split_kernel<<<(nNew * HF + 255) / 256, 256>>>(p_agg, p_score, p_perm,
                                                              p_x, p_xhi, p_xlo, nNew);
        readout_kernel<<<G, 256>>>(p_x, k, p_ro, 0);
        n = nNew;                 // 32768
    }
    // ---------------- level 1 (edges = orig + newid0 map) ----------------
    {
        int npg = 128;
        wsplit_kernel<<<256, 256>>>(gcn_w1, 256, p_whi, p_wlo);
        gemm_mma_kernel<<<dim3(n / 128, 2), 256, MMA_SMEM>>>(p_xhi, p_xlo, p_whi, p_wlo, p_h, 256);
        csr_build_kernel<<<G, 256>>>(d_src, d_dst, p_newid0, npg, p_rs, p_rc, p_cpack, p_dinv);
        agg_fused_kernel<<<dim3(4, G), 256, npg*64*4>>>(p_h, p_dinv, p_rs, p_rc,
                                                        p_cpack, gcn_b1, pool_w1,
                                                        p_agg, p_spart, npg);
    }
    {
        int npg = 128, k = 64, nNew = G * k;
        pool_kernel<<<G, npg>>>(p_spart, pool_w1, p_score, npg, k, p_newid1, p_perm);
        gather_split_kernel<<<(nNew * HF + 255) / 256, 256>>>(p_agg, p_score, p_perm,
                                                              p_x, p_xhi, p_xlo, nNew);
        compose_kernel<<<(MAXN + 255) / 256, 256>>>(p_newid0, p_newid1, p_cmap, MAXN);
        readout_kernel<<<G, 256>>>(p_x, k, p_ro, 1);
        n = nNew;                 // 16384
    }
    // ---------------- level 2 (edges = orig + composed map) ----------------
    {
        int npg = 64;
        wsplit_kernel<<<256, 256>>>(gcn_w2, 256, p_whi, p_wlo);
        gemm_mma_kernel<<<dim3(n / 128, 2), 256, MMA_SMEM>>>(p_xhi, p_xlo, p_whi, p_wlo, p_h, 256);
        csr_build_kernel<<<G, 256>>>(d_src, d_dst, p_cmap, npg, p_rs, p_rc, p_cpack, p_dinv);
        agg_fused_kernel<<<dim3(4, G), 256, npg*64*4>>>(p_h, p_dinv, p_rs, p_rc,
                                                        p_cpack, gcn_b2, pool_w2,
                                                        p_agg, p_spart, npg);
    }
    {
        int npg = 64, k = 32;
        pool_kernel<<<G, npg>>>(p_spart, pool_w2, p_score, npg, k, p_newid0, p_perm);
        gather_scale_kernel<<<(G * k * HF + 255) / 256, 256>>>(p_agg, p_score, p_perm, p_x, G * k);
        readout_kernel<<<G, 256>>>(p_x, k, p_ro, 1);
    }

    // ---------------- MLP head ----------------
    lin1_kernel<<<32, 256>>>(p_ro, lin1_w, lin1_b, p_h1);
    lin2_kernel<<<16, 128>>>(p_h1, lin2_w, lin2_b, p_h2);
    lin3_lsm_kernel<<<G, 32>>>(p_h2, lin3_w, lin3_b, out);
}